// round 11
// baseline (speedup 1.0000x reference)
#include <cuda_runtime.h>
#include <cuda_bf16.h>
#include <cuda_fp16.h>
#include <math.h>
#include <float.h>
#include <stdint.h>

// ---------------------------------------------------------------------------
// Problem constants
// ---------------------------------------------------------------------------
#define NB      4
#define NTOK    1024
#define DIM     768
#define NHEAD   12
#define DHEAD   64
#define MLPD    3072
#define IMGS    4
#define NCLS    1000
#define TOKS    (NB*NTOK)
#define BH      (NB*NHEAD)

#define FBIAS 1
#define FGELU 2
#define FRES  4

#define WOFF_EMB 0ULL
#define WPERL    7077888ULL
#define WOFF_L(l)   (589824ULL + (unsigned long long)(l)*WPERL)
#define WOFF_Q(l)   (WOFF_L(l) + 0ULL)
#define WOFF_KV(l)  (WOFF_L(l) + 589824ULL)
#define WOFF_O(l)   (WOFF_L(l) + 1769472ULL)
#define WOFF_W1(l)  (WOFF_L(l) + 2359296ULL)
#define WOFF_W2(l)  (WOFF_L(l) + 4718592ULL)
#define WOFF_PKV    (589824ULL + 4ULL*WPERL)
#define WTOTAL      30081024ULL

// ---------------------------------------------------------------------------
// Device scratch
// ---------------------------------------------------------------------------
__device__ float g_x   [TOKS*DIM];
__device__ float g_qkv [TOKS*2304];
__device__ __half g_xn  [TOKS*DIM];
__device__ __half g_tmp [TOKS*MLPD];
__device__ __half g_ao  [TOKS*DIM];
__device__ __nv_bfloat16 g_qTh[BH*NTOK*DHEAD], g_qTl[BH*NTOK*DHEAD];
__device__ __nv_bfloat16 g_kTh[BH*NTOK*DHEAD], g_kTl[BH*NTOK*DHEAD];
__device__ __nv_bfloat16 g_vTth[BH*DHEAD*NTOK], g_vTtl[BH*DHEAD*NTOK];
__device__ float g_kTf[BH*NTOK*DHEAD], g_vTf[BH*NTOK*DHEAD];
__device__ float g_sm  [4096];
__device__ float g_pattn[16*DIM];
__device__ float g_pool [16*DIM];
__device__ float g_pln  [16*DIM];
__device__ __half g_w[WTOTAL];

// ---------------------------------------------------------------------------
// Helpers
// ---------------------------------------------------------------------------
__device__ __forceinline__ uint32_t smem_u32(const void* p) {
    uint32_t a;
    asm("{ .reg .u64 t; cvta.to.shared.u64 t, %1; cvt.u32.u64 %0, t; }" : "=r"(a) : "l"(p));
    return a;
}

#define LDSM4(r, addr) \
    asm volatile("ldmatrix.sync.aligned.m8n8.x4.shared.b16 {%0,%1,%2,%3}, [%4];" \
        : "=r"((r)[0]), "=r"((r)[1]), "=r"((r)[2]), "=r"((r)[3]) : "r"(addr))

#define MMA16816(d, a, b) \
    asm volatile("mma.sync.aligned.m16n8k16.row.col.f32.bf16.bf16.f32 " \
        "{%0,%1,%2,%3}, {%4,%5,%6,%7}, {%8,%9}, {%0,%1,%2,%3};" \
        : "+f"((d)[0]), "+f"((d)[1]), "+f"((d)[2]), "+f"((d)[3]) \
        : "r"((a)[0]), "r"((a)[1]), "r"((a)[2]), "r"((a)[3]), "r"((b)[0]), "r"((b)[1]))

#define MMAH16816(d, a, b) \
    asm volatile("mma.sync.aligned.m16n8k16.row.col.f32.f16.f16.f32 " \
        "{%0,%1,%2,%3}, {%4,%5,%6,%7}, {%8,%9}, {%0,%1,%2,%3};" \
        : "+f"((d)[0]), "+f"((d)[1]), "+f"((d)[2]), "+f"((d)[3]) \
        : "r"((a)[0]), "r"((a)[1]), "r"((a)[2]), "r"((a)[3]), "r"((b)[0]), "r"((b)[1]))

#define CPA16(dst, src) \
    asm volatile("cp.async.cg.shared.global [%0], [%1], 16;" :: "r"(dst), "l"(src))
#define CP_COMMIT() asm volatile("cp.async.commit_group;" ::: "memory")
#define CP_WAIT0()  asm volatile("cp.async.wait_group 0;" ::: "memory")
#define CP_WAIT1()  asm volatile("cp.async.wait_group 1;" ::: "memory")

__device__ __forceinline__ void split2(float v, __nv_bfloat16& h, __nv_bfloat16& l) {
    h = __float2bfloat16(v);
    l = __float2bfloat16(v - __bfloat162float(h));
}
__device__ __forceinline__ uint32_t bfu(__nv_bfloat16 b) { return (uint32_t)__bfloat16_as_ushort(b); }

template<typename T>
__device__ __forceinline__ void cpa_tile(uint32_t smbase, const T* __restrict__ g,
                                         int ldk, int chunks, int tid)
{
    for (int i = tid; i < chunks; i += 256) {
        int r = i >> 3, c = i & 7;
        uint32_t off = r * 128 + c * 16;
        uint32_t sw = off ^ ((off >> 3) & 0x70);
        CPA16(smbase + sw, g + (size_t)r * ldk + c * 8);
    }
}

// ---------------------------------------------------------------------------
// Weight convert+transpose, family-batched: z = layer.
// ---------------------------------------------------------------------------
__global__ void wconv_kernel(const float* __restrict__ W, __half* __restrict__ out,
                             int K, int N, long srcStride, long dstStride)
{
    __shared__ float t[32][33];
    int z = blockIdx.z;
    const float* Wz = W + (size_t)z * srcStride;
    __half* oz = out + (size_t)z * dstStride;
    int n0 = blockIdx.x * 32, k0 = blockIdx.y * 32;
    int tx = threadIdx.x, ty = threadIdx.y;
#pragma unroll
    for (int r = 0; r < 4; r++)
        t[ty + r*8][tx] = Wz[(size_t)(k0 + ty + r*8) * N + n0 + tx];
    __syncthreads();
#pragma unroll
    for (int r = 0; r < 4; r++) {
        int n = n0 + ty + r*8, k = k0 + tx;
        oz[(size_t)n * K + k] = __float2half(t[tx][ty + r*8]);
    }
}

// ---------------------------------------------------------------------------
// Pipelined mma.sync fp16 GEMM, single pass, 2-stage, 2 CTAs/SM.
// ---------------------------------------------------------------------------
__global__ void __launch_bounds__(256, 2) mma_gemm(
    const __half* __restrict__ A, const __half* __restrict__ B,
    const float* __restrict__ bias, const float* __restrict__ res,
    float* __restrict__ C, __half* __restrict__ Ch,
    int M, int N, int K, int flags)
{
    constexpr int A_SZ = 16384;
    constexpr int STG  = 2 * A_SZ;

    extern __shared__ char smem[];
    uint32_t uS = smem_u32(smem);

    const int tid = threadIdx.x;
    const int wid = tid >> 5, lane = tid & 31;
    const int m0 = blockIdx.y * 128, n0 = blockIdx.x * 128;
    const int wm = wid & 1, wn = wid >> 1;

    const __half* Az = A + (size_t)m0 * K;
    const __half* Bz = B + (size_t)n0 * K;

    float acc[4][4][4] = {};

    const int a_row = wm * 64 + (lane & 15);
    const int a_cb  = (lane >> 4) * 16;
    const int b_row = wn * 32 + (lane & 7) + ((lane >> 4) << 3);
    const int b_cb  = ((lane >> 3) & 1) * 16;

    const int KT = K >> 6;
    {
        cpa_tile(uS,         Az, K, 1024, tid);
        cpa_tile(uS + A_SZ,  Bz, K, 1024, tid);
        CP_COMMIT();
    }

    for (int kt = 0; kt < KT; kt++) {
        if (kt + 1 < KT) {
            uint32_t base = uS + ((kt + 1) & 1) * STG;
            cpa_tile(base,        Az + (kt + 1) * 64, K, 1024, tid);
            cpa_tile(base + A_SZ, Bz + (kt + 1) * 64, K, 1024, tid);
            CP_COMMIT();
            CP_WAIT1();
        } else {
            CP_WAIT0();
        }
        __syncthreads();

        uint32_t bA = uS + (kt & 1) * STG;
        uint32_t bB = bA + A_SZ;

#pragma unroll
        for (int ks = 0; ks < 4; ks++) {
            uint32_t ah[4][4], bh[2][4];
#pragma unroll
            for (int mt = 0; mt < 4; mt++) {
                int row = a_row + mt * 16;
                uint32_t off = row * 128 + ((a_cb + ks * 32) ^ ((row & 7) << 4));
                LDSM4(ah[mt], bA + off);
            }
#pragma unroll
            for (int q = 0; q < 2; q++) {
                int row = b_row + q * 16;
                uint32_t off = row * 128 + ((b_cb + ks * 32) ^ ((row & 7) << 4));
                LDSM4(bh[q], bB + off);
            }
#pragma unroll
            for (int mt = 0; mt < 4; mt++)
#pragma unroll
                for (int nt = 0; nt < 4; nt++)
                    MMAH16816(acc[mt][nt], ah[mt], &bh[nt >> 1][(nt & 1) * 2]);
        }
        __syncthreads();
    }

    const int rbase = m0 + wm * 64;
#pragma unroll
    for (int mt = 0; mt < 4; mt++) {
#pragma unroll
        for (int nt = 0; nt < 4; nt++) {
            int c = n0 + wn * 32 + nt * 8 + (lane & 3) * 2;
            float bv0 = 0.f, bv1 = 0.f;
            if (flags & FBIAS) { bv0 = bias[c]; bv1 = bias[c + 1]; }
#pragma unroll
            for (int half = 0; half < 2; half++) {
                int r = rbase + mt * 16 + (lane >> 2) + half * 8;
                float v0 = acc[mt][nt][half * 2 + 0];
                float v1 = acc[mt][nt][half * 2 + 1];
                if (flags & FBIAS) { v0 += bv0; v1 += bv1; }
                if (flags & FGELU) {
                    v0 = 0.5f * v0 * (1.f + erff(v0 * 0.70710678118654752f));
                    v1 = 0.5f * v1 * (1.f + erff(v1 * 0.70710678118654752f));
                }
                long idx = (long)r * N + c;
                if (flags & FRES) { v0 += res[idx]; v1 += res[idx + 1]; }
                if (C) *(float2*)(C + idx) = make_float2(v0, v1);
                if (Ch) {
                    __half2 hv = __floats2half2_rn(v0, v1);
                    *(__half2*)(Ch + idx) = hv;
                }
            }
        }
    }
}

// ---------------------------------------------------------------------------
// Fused flash attention (bf16 3-pass; fp16 output).
// Single KV stage -> 97KB smem -> 2 CTAs/SM (co-residency hides loads).
// ---------------------------------------------------------------------------
#define FA_SMEM 99712

__global__ void __launch_bounds__(256, 2) flash_attn(
    const __nv_bfloat16* __restrict__ Qh_, const __nv_bfloat16* __restrict__ Ql_,
    const __nv_bfloat16* __restrict__ Kh_, const __nv_bfloat16* __restrict__ Kl_,
    const __nv_bfloat16* __restrict__ Vh_, const __nv_bfloat16* __restrict__ Vl_,
    const int* __restrict__ image_ids, const int* __restrict__ lengths,
    __half* __restrict__ O_)
{
    extern __shared__ char smem[];
    uint32_t uS = smem_u32(smem);
    const int tid = threadIdx.x, wid = tid >> 5, lane = tid & 31;
    const int z = blockIdx.y, b = z / 12, h = z % 12;
    const int m0 = blockIdx.x * 128;

    int* s_cmin   = (int*)(smem + 98304);
    int* s_cmax   = s_cmin + 8;
    int* s_jlist  = s_cmax + 8;
    int* s_meta   = s_jlist + 8;
    int* s_imgRow = s_meta + 8;
    int* s_imgCol = s_imgRow + 128;

    const int len = lengths[b];

    {
        int4 v = *(const int4*)(image_ids + b*1024 + wid*128 + lane*4);
        int mn = min(min(v.x, v.y), min(v.z, v.w));
        int mx = max(max(v.x, v.y), max(v.z, v.w));
#pragma unroll
        for (int o = 16; o; o >>= 1) {
            mn = min(mn, __shfl_xor_sync(0xffffffffu, mn, o));
            mx = max(mx, __shfl_xor_sync(0xffffffffu, mx, o));
        }
        if (lane == 0) { s_cmin[wid] = mn; s_cmax[wid] = mx; }
    }
    if (tid < 128) s_imgRow[tid] = image_ids[b*1024 + m0 + tid];
    __syncthreads();
    if (tid == 0) {
        int rmin = s_cmin[blockIdx.x], rmax = s_cmax[blockIdx.x];
        int nj = 0;
        for (int jb = 0; jb < 8; jb++)
            if (jb * 128 < len && s_cmax[jb] >= rmin && s_cmin[jb] <= rmax)
                s_jlist[nj++] = jb;
        s_meta[0] = nj;
    }
    __syncthreads();
    const int nj = s_meta[0];

    // Q tiles (persist for whole kernel)
    const size_t qoff = ((size_t)z * 1024 + m0) * 64;
    cpa_tile(uS,         Qh_ + qoff, 64, 1024, tid);
    cpa_tile(uS + 16384, Ql_ + qoff, 64, 1024, tid);
    CP_COMMIT();

    // Single KV stage at uS + 32768 (K hi/lo 32KB, V hi/lo 32KB)
    const uint32_t bK  = uS + 32768;
    const uint32_t bKl = bK + 16384;
    const uint32_t bV  = bK + 32768;
    const uint32_t bVl = bK + 49152;

    auto load_kv = [&](int t) {
        int jb = s_jlist[t];
        size_t koff = ((size_t)z * 1024 + jb * 128) * 64;
        cpa_tile(bK,  Kh_ + koff, 64, 1024, tid);
        cpa_tile(bKl, Kl_ + koff, 64, 1024, tid);
        const __nv_bfloat16* vh = Vh_ + (size_t)z * 64 * 1024 + jb * 128;
        const __nv_bfloat16* vl = Vl_ + (size_t)z * 64 * 1024 + jb * 128;
        for (int i = tid; i < 1024; i += 256) {
            int r = i >> 4, c = i & 15;
            int kc = c >> 3, cc = c & 7;
            uint32_t off = r * 128 + cc * 16;
            uint32_t sw = off ^ ((off >> 3) & 0x70);
            CPA16(bV  + kc * 8192 + sw, vh + (size_t)r * 1024 + c * 8);
            CPA16(bVl + kc * 8192 + sw, vl + (size_t)r * 1024 + c * 8);
        }
        if (tid < 128) s_imgCol[tid] = image_ids[b*1024 + jb*128 + tid];
        CP_COMMIT();
    };

    float O[8][4] = {};
    float mA = -FLT_MAX, mB = -FLT_MAX, lA = 0.f, lB = 0.f;
    uint32_t qh[4][4], ql[4][4];
    bool qloaded = false;

    const int rA = lane >> 2;
    const int imgA = s_imgRow[wid * 16 + rA];
    const int imgB = s_imgRow[wid * 16 + rA + 8];

    const int a_row = wid * 16 + (lane & 15);
    const int a_cb  = (lane >> 4) * 16;
    const int b_row_base = (lane & 7) + ((lane >> 4) << 3);
    const int b_cb  = ((lane >> 3) & 1) * 16;

    for (int t = 0; t < nj; t++) {
        load_kv(t);
        CP_WAIT0();
        __syncthreads();

        if (!qloaded) {
            qloaded = true;
#pragma unroll
            for (int ks = 0; ks < 4; ks++) {
                uint32_t off = a_row * 128 + ((a_cb + ks * 32) ^ ((a_row & 7) << 4));
                LDSM4(qh[ks], uS + off);
                LDSM4(ql[ks], uS + 16384 + off);
            }
        }

        int jb = s_jlist[t];
        int j0 = jb * 128;
        const int* imgC = s_imgCol;

        float S[16][4] = {};
#pragma unroll
        for (int ks = 0; ks < 4; ks++) {
#pragma unroll
            for (int nb = 0; nb < 8; nb++) {
                uint32_t bh4[4], bl4[4];
                int row = nb * 16 + b_row_base;
                uint32_t off = row * 128 + ((b_cb + ks * 32) ^ ((row & 7) << 4));
                LDSM4(bh4, bK + off);
                LDSM4(bl4, bKl + off);
                MMA16816(S[2*nb],   qh[ks], bh4);
                MMA16816(S[2*nb+1], qh[ks], bh4 + 2);
                MMA16816(S[2*nb],   qh[ks], bl4);
                MMA16816(S[2*nb+1], qh[ks], bl4 + 2);
                MMA16816(S[2*nb],   ql[ks], bh4);
                MMA16816(S[2*nb+1], ql[ks], bh4 + 2);
            }
        }

        float mnA = mA, mnB = mB;
#pragma unroll
        for (int nt = 0; nt < 16; nt++) {
            int c0 = nt * 8 + (lane & 3) * 2;
            int i0 = imgC[c0], i1 = imgC[c0 + 1];
            bool v0 = (j0 + c0) < len, v1 = (j0 + c0 + 1) < len;
            if (i0 == imgA && v0) mnA = fmaxf(mnA, S[nt][0]);
            if (i1 == imgA && v1) mnA = fmaxf(mnA, S[nt][1]);
            if (i0 == imgB && v0) mnB = fmaxf(mnB, S[nt][2]);
            if (i1 == imgB && v1) mnB = fmaxf(mnB, S[nt][3]);
        }
#pragma unroll
        for (int o = 1; o <= 2; o <<= 1) {
            mnA = fmaxf(mnA, __shfl_xor_sync(0xffffffffu, mnA, o));
            mnB = fmaxf(mnB, __shfl_xor_sync(0xffffffffu, mnB, o));
        }
        float scA = __expf(mA - mnA), scB = __expf(mB - mnB);
        mA = mnA; mB = mnB;
        lA *= scA; lB *= scB;
#pragma unroll
        for (int nt = 0; nt < 16; nt++) {
            int c0 = nt * 8 + (lane & 3) * 2;
            int i0 = imgC[c0], i1 = imgC[c0 + 1];
            bool v0 = (j0 + c0) < len, v1 = (j0 + c0 + 1) < len;
            float p0 = (i0 == imgA && v0) ? __expf(S[nt][0] - mnA) : 0.f;
            float p1 = (i1 == imgA && v1) ? __expf(S[nt][1] - mnA) : 0.f;
            float p2 = (i0 == imgB && v0) ? __expf(S[nt][2] - mnB) : 0.f;
            float p3 = (i1 == imgB && v1) ? __expf(S[nt][3] - mnB) : 0.f;
            lA += p0 + p1; lB += p2 + p3;
            S[nt][0] = p0; S[nt][1] = p1; S[nt][2] = p2; S[nt][3] = p3;
        }
#pragma unroll
        for (int nt = 0; nt < 8; nt++) {
            O[nt][0] *= scA; O[nt][1] *= scA; O[nt][2] *= scB; O[nt][3] *= scB;
        }

#pragma unroll
        for (int kt = 0; kt < 8; kt++) {
            uint32_t ah4[4], al4[4];
            {
                __nv_bfloat16 h0, l0, h1, l1;
                split2(S[2*kt][0], h0, l0);   split2(S[2*kt][1], h1, l1);
                ah4[0] = bfu(h0) | (bfu(h1) << 16);  al4[0] = bfu(l0) | (bfu(l1) << 16);
                split2(S[2*kt][2], h0, l0);   split2(S[2*kt][3], h1, l1);
                ah4[1] = bfu(h0) | (bfu(h1) << 16);  al4[1] = bfu(l0) | (bfu(l1) << 16);
                split2(S[2*kt+1][0], h0, l0); split2(S[2*kt+1][1], h1, l1);
                ah4[2] = bfu(h0) | (bfu(h1) << 16);  al4[2] = bfu(l0) | (bfu(l1) << 16);
                split2(S[2*kt+1][2], h0, l0); split2(S[2*kt+1][3], h1, l1);
                ah4[3] = bfu(h0) | (bfu(h1) << 16);  al4[3] = bfu(l0) | (bfu(l1) << 16);
            }
            uint32_t tb  = bV  + (kt >> 2) * 8192;
            uint32_t tbl = bVl + (kt >> 2) * 8192;
#pragma unroll
            for (int nb = 0; nb < 4; nb++) {
                uint32_t vh4[4], vl4[4];
                int row = nb * 16 + b_row_base;
                uint32_t off = row * 128 + ((b_cb + (kt & 3) * 32) ^ ((row & 7) << 4));
                LDSM4(vh4, tb + off);
                LDSM4(vl4, tbl + off);
                MMA16816(O[2*nb],   ah4, vh4);
                MMA16816(O[2*nb+1], ah4, vh4 + 2);
                MMA16816(O[2*nb],   ah4, vl4);
                MMA16816(O[2*nb+1], ah4, vl4 + 2);
                MMA16816(O[2*nb],   al4, vh4);
                MMA16816(O[2*nb+1], al4, vh4 + 2);
            }
        }
        __syncthreads();
    }

#pragma unroll
    for (int o = 1; o <= 2; o <<= 1) {
        lA += __shfl_xor_sync(0xffffffffu, lA, o);
        lB += __shfl_xor_sync(0xffffffffu, lB, o);
    }
    float iA = lA > 0.f ? 1.f / lA : 0.f;
    float iB = lB > 0.f ? 1.f / lB : 0.f;
    size_t rowA = (size_t)(b * 1024 + m0 + wid * 16 + rA);
#pragma unroll
    for (int nt = 0; nt < 8; nt++) {
        int c = nt * 8 + (lane & 3) * 2;
        size_t idx = rowA * 768 + h * 64 + c;
        *(__half2*)(O_ + idx) = __floats2half2_rn(O[nt][0] * iA, O[nt][1] * iA);
        idx = (rowA + 8) * 768 + h * 64 + c;
        *(__half2*)(O_ + idx) = __floats2half2_rn(O[nt][2] * iB, O[nt][3] * iB);
    }
}

// ---------------------------------------------------------------------------
// LayerNorm over width 768. fp32 and/or fp16 outputs. Optional pos add.
// ---------------------------------------------------------------------------
__global__ void ln_kernel(const float* __restrict__ in, const float* __restrict__ g,
                          float* __restrict__ outf, __half* __restrict__ outh,
                          const float* __restrict__ pos_h, const float* __restrict__ pos_w,
                          const int* __restrict__ ppos)
{
    int row = blockIdx.x;
    int tid = threadIdx.x;
    const float* xr = in + (size_t)row * 768;
    float v[3]; float s = 0.f, q = 0.f;
#pragma unroll
    for (int i = 0; i < 3; i++) { float t = xr[tid + i*256]; v[i] = t; s += t; q += t*t; }
#pragma unroll
    for (int o = 16; o; o >>= 1) {
        s += __shfl_xor_sync(0xffffffffu, s, o);
        q += __shfl_xor_sync(0xffffffffu, q, o);
    }
    __shared__ float shs[8], shq[8], st[2];
    int w = tid >> 5;
    if ((tid & 31) == 0) { shs[w] = s; shq[w] = q; }
    __syncthreads();
    if (tid == 0) {
        float S = 0.f, Q = 0.f;
#pragma unroll
        for (int i = 0; i < 8; i++) { S += shs[i]; Q += shq[i]; }
        float mu = S * (1.f/768.f);
        st[0] = mu;
        st[1] = rsqrtf(Q * (1.f/768.f) - mu*mu + 1e-5f);
    }
    __syncthreads();
    float mu = st[0], rs = st[1];
    int p0 = 0, p1 = 0;
    if (ppos) { p0 = ppos[row*2]; p1 = ppos[row*2 + 1]; }
#pragma unroll
    for (int i = 0; i < 3; i++) {
        int c = tid + i*256;
        float y = (v[i] - mu) * rs * g[c];
        if (ppos) y += pos_h[p0*768 + c] + pos_w[p1*768 + c];
        size_t idx = (size_t)row*768 + c;
        if (outf) outf[idx] = y;
        if (outh) outh[idx] = __float2half(y);
    }
}

// ---------------------------------------------------------------------------
// Fused QKV postprocess (bf16 hi/lo outputs for flash).
// ---------------------------------------------------------------------------
__global__ void rmsT_all(const float* __restrict__ qkv,
                         const float* __restrict__ qg, const float* __restrict__ kg,
                         __nv_bfloat16* __restrict__ qh, __nv_bfloat16* __restrict__ ql,
                         __nv_bfloat16* __restrict__ kh, __nv_bfloat16* __restrict__ kl,
                         __nv_bfloat16* __restrict__ vh, __nv_bfloat16* __restrict__ vl)
{
    int token = blockIdx.x;
    int b = token >> 10, n = token & 1023;
    int w = threadIdx.x >> 5, lane = threadIdx.x & 31;
    const float* base = qkv + (size_t)token * 2304 + w * 64;
    __nv_bfloat16 hh, ll;

    {
        float v0 = base[lane], v1 = base[lane + 32];
        float ss = v0*v0 + v1*v1;
#pragma unroll
        for (int o = 16; o; o >>= 1) ss += __shfl_xor_sync(0xffffffffu, ss, o);
        float inv = 8.0f / fmaxf(sqrtf(ss), 1e-12f);
        v0 *= inv * qg[w*64 + lane];
        v1 *= inv * qg[w*64 + lane + 32];
        size_t dst = ((size_t)(b*12 + w) * 1024 + n) * 64;
        split2(v0, hh, ll); qh[dst + lane] = hh;      ql[dst + lane] = ll;
        split2(v1, hh, ll); qh[dst + lane + 32] = hh; ql[dst + lane + 32] = ll;
    }
    {
        float v0 = base[768 + lane], v1 = base[768 + lane + 32];
        float ss = v0*v0 + v1*v1;
#pragma unroll
        for (int o = 16; o; o >>= 1) ss += __shfl_xor_sync(0xffffffffu, ss, o);
        float inv = 8.0f / fmaxf(sqrtf(ss), 1e-12f);
        v0 *= inv * kg[w*64 + lane];
        v1 *= inv * kg[w*64 + lane + 32];
        size_t dst = ((size_t)(b*12 + w) * 1024 + n) * 64;
        split2(v0, hh, ll); kh[dst + lane] = hh;      kl[dst + lane] = ll;
        split2(v1, hh, ll); kh[dst + lane + 32] = hh; kl[dst + lane + 32] = ll;
    }
    {
        float v0 = base[1536 + lane], v1 = base[1536 + lane + 32];
        size_t vb = ((size_t)(b*12 + w) * 64) * 1024 + n;
        split2(v0, hh, ll); vh[vb + (size_t)lane * 1024] = hh;        vl[vb + (size_t)lane * 1024] = ll;
        split2(v1, hh, ll); vh[vb + (size_t)(lane + 32) * 1024] = hh; vl[vb + (size_t)(lane + 32) * 1024] = ll;
    }
}

// Pool-path: one launch does k-rms + v copy (fp32 outputs).
__global__ void rmsT_pool(const float* __restrict__ kv,
                          const float* __restrict__ kg,
                          float* __restrict__ kT, float* __restrict__ vT)
{
    int token = blockIdx.x;
    int b = token >> 10, n = token & 1023;
    int w = threadIdx.x >> 5, lane = threadIdx.x & 31;
    const float* base = kv + (size_t)token * 1536 + w * 64;
    {
        float v0 = base[lane], v1 = base[lane + 32];
        float ss = v0*v0 + v1*v1;
#pragma unroll
        for (int o = 16; o; o >>= 1) ss += __shfl_xor_sync(0xffffffffu, ss, o);
        float inv = 8.0f / fmaxf(sqrtf(ss), 1e-12f);
        float* dst = kT + ((size_t)(b*12 + w) * 1024 + n) * 64;
        dst[lane]      = v0 * inv * kg[w*64 + lane];
        dst[lane + 32] = v1 * inv * kg[w*64 + lane + 32];
    }
    {
        float v0 = base[768 + lane], v1 = base[768 + lane + 32];
        float* dst = vT + ((size_t)(b*12 + w) * 1024 + n) * 64;
        dst[lane] = v0; dst[lane + 32] = v1;
    }
}

// ---------------------------------------------------------------------------
// Attention pooling (192 blocks), fp32 path.
// ---------------------------------------------------------------------------
__global__ void pool_attn_kernel(const float* __restrict__ pqn, const float* __restrict__ kT,
                                 const float* __restrict__ vT, const int* __restrict__ image_ids,
                                 const int* __restrict__ lengths, float* __restrict__ out)
{
    int idx = blockIdx.x;
    int h = idx % 12, img = (idx / 12) % 4, b = idx / 48;
    int tid = threadIdx.x;
    __shared__ float q[64];
    __shared__ float p[1024];
    __shared__ float sh[8];
    __shared__ float bs[2];
    __shared__ float sred[256];
    if (tid < 64) q[tid] = pqn[h*64 + tid];
    __syncthreads();

    const float* K = kT + (size_t)(b*12 + h) * 1024 * 64;
    int len = lengths[b];
    float loc[4]; float mx = -FLT_MAX;
#pragma unroll
    for (int t = 0; t < 4; t++) {
        int j = tid + t*256;
        const float* kr = K + (size_t)j * 64;
        float dot = 0.f;
#pragma unroll
        for (int d = 0; d < 64; d++) dot += q[d] * kr[d];
        bool ok = (image_ids[b*1024 + j] == img) && (j < len);
        loc[t] = ok ? dot : -FLT_MAX;
        mx = fmaxf(mx, loc[t]);
    }
#pragma unroll
    for (int o = 16; o; o >>= 1) mx = fmaxf(mx, __shfl_xor_sync(0xffffffffu, mx, o));
    int w = tid >> 5;
    if ((tid & 31) == 0) sh[w] = mx;
    __syncthreads();
    if (tid == 0) { float mm = sh[0]; for (int i = 1; i < 8; i++) mm = fmaxf(mm, sh[i]); bs[0] = mm; }
    __syncthreads();
    mx = bs[0];
    float s = 0.f;
#pragma unroll
    for (int t = 0; t < 4; t++) {
        float e = __expf(loc[t] - mx);
        p[tid + t*256] = e;
        s += e;
    }
#pragma unroll
    for (int o = 16; o; o >>= 1) s += __shfl_xor_sync(0xffffffffu, s, o);
    if ((tid & 31) == 0) sh[w] = s;
    __syncthreads();
    if (tid == 0) { float ss = 0.f; for (int i = 0; i < 8; i++) ss += sh[i]; bs[1] = 1.f / ss; }
    __syncthreads();
    float inv = bs[1];

    const float* V = vT + (size_t)(b*12 + h) * 1024 * 64;
    int d = tid & 63, grp = tid >> 6;
    float acc = 0.f;
    for (int j = grp; j < 1024; j += 4) acc += p[j] * V[(size_t)j*64 + d];
    sred[tid] = acc;
    __syncthreads();
    if (grp == 0) {
        float r = (sred[d] + sred[d + 64]) + (sred[d + 128] + sred[d + 192]);
        out[(size_t)(b*4 + img) * 768 + h*64 + d] = r * inv;
    }
}

__global__ void rms_vec_kernel(const float* __restrict__ in, const float* __restrict__ g,
                               float* __restrict__ out)
{
    int w = threadIdx.x >> 5, lane = threadIdx.x & 31;
    float v0 = in[w*64 + lane], v1 = in[w*64 + lane + 32];
    float ss = v0*v0 + v1*v1;
#pragma unroll
    for (int o = 16; o; o >>= 1) ss += __shfl_xor_sync(0xffffffffu, ss, o);
    float inv = 8.0f / fmaxf(sqrtf(ss), 1e-12f);
    out[w*64 + lane]      = v0 * inv * g[w*64 + lane];
    out[w*64 + lane + 32] = v1 * inv * g[w*64 + lane + 32];
}

__global__ void small_gemm_kernel(const float* __restrict__ A, const float* __restrict__ W,
                                  const float* __restrict__ addvec, float* __restrict__ C,
                                  int N, int K)
{
    __shared__ float a[768];
    int row = blockIdx.y;
    for (int i = threadIdx.x; i < K; i += 256) a[i] = A[(size_t)row*K + i];
    __syncthreads();
    int n = blockIdx.x * 256 + threadIdx.x;
    if (n >= N) return;
    float acc = addvec ? addvec[n] : 0.f;
#pragma unroll 4
    for (int k = 0; k < K; k++) acc += a[k] * W[(size_t)k*N + n];
    C[(size_t)row*N + n] = acc;
}

// ---------------------------------------------------------------------------
// Host side
// ---------------------------------------------------------------------------
extern "C" void kernel_launch(void* const* d_in, const int* in_sizes, int n_in,
                              void* d_out, int out_size)
{
    (void)in_sizes; (void)n_in; (void)out_size;
    const float* patches    = (const float*)d_in[0];
    const int*   ppos       = (const int*)  d_in[1];
    const int*   image_ids  = (const int*)  d_in[2];
    const int*   lengths    = (const int*)  d_in[3];
    const float* emb_ln_g   = (const float*)d_in[4];
    const float* W_emb      = (const float*)d_in[5];
    const float* b_emb      = (const float*)d_in[6];
    const float* emb_ln2_g  = (const float*)d_in[7];
    const float* pos_h      = (const float*)d_in[8];
    const float* pos_w      = (const float*)d_in[9];
    const float* ln_attn_g  = (const float*)d_in[10];
    const float* Wq         = (const float*)d_in[11];
    const float* Wkv        = (const float*)d_in[12];
    const float* qn_g       = (const float*)d_in[13];
    const float* kn_g       = (const float*)d_in[14];
    const float* Wo         = (const float*)d_in[15];
    const float* ln_ff_g    = (const float*)d_in[16];
    const float* W1         = (const float*)d_in[17];
    const float* b1         = (const float*)d_in[18];
    const float* W2         = (const float*)d_in[19];
    const float* b2         = (const float*)d_in[20];
    const float* final_ln_g = (const float*)d_in[21];
    const float* pool_q     = (const float*)d_in[22];
    const float* pool_ln_g  = (const float*)d_in[23];
    const float* pWq        = (const float*)d_in[24];
    const float* pWkv       = (const float*)d_in[25];
    const float* p_qn_g     = (const float*)d_in[26];
    const float* p_kn_g     = (const float*)d_in[27];
    const float* pWo        = (const float*)d_in[28];
    const float* head_ln_g  = (const float*)d_in[29];
    const float* W_head     = (const float*)d_in[30];

    float *x, *qkv, *kTf, *vTf, *sm, *pattn, *pool, *pln;
    __half *xn, *tmp, *ao, *w;
    __nv_bfloat16 *qTh, *qTl, *kTh, *kTl, *vTth, *vTtl;
    cudaGetSymbolAddress((void**)&x,    g_x);
    cudaGetSymbolAddress((void**)&qkv,  g_qkv);
    cudaGetSymbolAddress((void**)&kTf,  g_kTf);
    cudaGetSymbolAddress((void**)&vTf,  g_vTf);
    cudaGetSymbolAddress((void**)&sm,   g_sm);
    cudaGetSymbolAddress((void**)&pattn,g_pattn);
    cudaGetSymbolAddress((void**)&pool, g_pool);
    cudaGetSymbolAddress((void**)&pln,  g_pln);
    cudaGetSymbolAddress((void**)&xn,   g_xn);
    cudaGetSymbolAddress((void**)&tmp,  g_tmp);
    cudaGetSymbolAddress((void**)&ao,   g_ao);
    cudaGetSymbolAddress((void**)&qTh,  g_qTh);
    cudaGetSymbolAddress((void**)&qTl,  g_qTl);
    cudaGetSymbolAddress((void**)&kTh,  g_kTh);
    cudaGetSymbolAddress((void**)&kTl,  g_kTl);
    cudaGetSymbolAddress((void**)&vTth, g_vTth);
    cudaGetSymbolAddress((void**)&vTtl, g_vTtl);
    cudaGetSymbolAddress((void**)&w,    g_w);

    constexpr int SMEMG = 65536;
    cudaFuncSetAttribute(mma_gemm,   cudaFuncAttributeMaxDynamicSharedMemorySize, SMEMG);
    cudaFuncSetAttribute(flash_attn, cudaFuncAttributeMaxDynamicSharedMemorySize, FA_SMEM);

    // ---- Convert + transpose weights to fp16 [N,K], family-batched ----
    dim3 wb(32, 8);
    wconv_kernel<<<dim3(DIM/32,  DIM/32,  1), wb>>>(W_emb, w + WOFF_EMB, DIM, DIM, 0, 0);
    wconv_kernel<<<dim3(DIM/32,  DIM/32,  4), wb>>>(Wq,  w + WOFF_Q(0),  DIM,  DIM,   (long)DIM*DIM,   (long)WPERL);
    wconv_kernel<<<dim3(2*DIM/32,DIM/32,  4), wb>>>(Wkv, w + WOFF_KV(0), DIM,  2*DIM, (long)DIM*2*DIM, (long)WPERL);
    wconv_kernel<<<dim3(DIM/32,  DIM/32,  4), wb>>>(Wo,  w + WOFF_O(0),  DIM,  DIM,   (long)DIM*DIM,   (long)WPERL);
    wconv_kernel<<<dim3(MLPD/32, DIM/32,  4), wb>>>(W1,  w + WOFF_W1(0), DIM,  MLPD,  (long)DIM*MLPD,  (long)WPERL);
    wconv_kernel<<<dim3(DIM/32,  MLPD/32, 4), wb>>>(W2,  w + WOFF_W2(0), MLPD, DIM,   (long)MLPD*DIM,  (long)WPERL);
    wconv_kernel<<<dim3(2*DIM/32,DIM/32,  1), wb>>>(pWkv, w + WOFF_PKV, DIM, 2*DIM, 0, 0);

    auto G = [&](const __half* a, const __half* bw,
                 const float* bias, const float* res,
                 float* C, __half* Ch, int M, int N, int K, int flags) {
        mma_gemm<<<dim3(N/128, M/128), 256, SMEMG>>>(a, bw, bias, res, C, Ch, M, N, K, flags);
    };

    // ---- Embedding ----
    ln_kernel<<<TOKS, 256>>>(patches, emb_ln_g, nullptr, xn, nullptr, nullptr, nullptr);
    G(xn, w + WOFF_EMB, b_emb, nullptr, x, nullptr, TOKS, DIM, DIM, FBIAS);
    ln_kernel<<<TOKS, 256>>>(x, emb_ln2_g, x, nullptr, pos_h, pos_w, ppos);

    // ---- Transformer layers ----
    for (int l = 0; l < 4; l++) {
        ln_kernel<<<TOKS, 256>>>(x, ln_attn_g + l*DIM, nullptr, xn, nullptr, nullptr, nullptr);
        G(xn, w + WOFF_Q(l), nullptr, nullptr, qkv, nullptr, TOKS, 2304, DIM, 0);
        rmsT_all<<<TOKS, 384>>>(qkv, qn_g + l*DIM, kn_g + l*DIM, qTh, qTl, kTh, kTl, vTth, vTtl);
        flash_attn<<<dim3(8, BH), 256, FA_SMEM>>>(qTh, qTl, kTh, kTl, vTth, vTtl,
                                                  image_ids, lengths, ao);
        G(ao, w + WOFF_O(l), nullptr, x, x, nullptr, TOKS, DIM, DIM, FRES);
        ln_kernel<<<TOKS, 256>>>(x, ln_ff_g + l*DIM, nullptr, xn, nullptr, nullptr, nullptr);
        G(xn, w + WOFF_W1(l), b1 + l*MLPD, nullptr, nullptr, tmp, TOKS, MLPD, DIM, FBIAS|FGELU);
        G(tmp, w + WOFF_W2(l), b2 + l*DIM, x, x, nullptr, TOKS, DIM, MLPD, FBIAS|FRES);
    }

    // ---- Final LN ----
    ln_kernel<<<TOKS, 256>>>(x, final_ln_g, nullptr, xn, nullptr, nullptr, nullptr);

    // ---- Attention pooling ----
    ln_kernel<<<1, 256>>>(pool_q, pool_ln_g, sm, nullptr, nullptr, nullptr, nullptr);
    small_gemm_kernel<<<dim3(3, 1), 256>>>(sm, pWq, nullptr, sm + 768, DIM, DIM);
    rms_vec_kernel<<<1, 384>>>(sm + 768, p_qn_g, sm + 1536);
    G(xn, w + WOFF_PKV, nullptr, nullptr, qkv, nullptr, TOKS, 1536, DIM, 0);
    rmsT_pool<<<TOKS, 384>>>(qkv, p_kn_g, kTf, vTf);
    pool_attn_kernel<<<NB*IMGS*NHEAD, 256>>>(sm + 1536, kTf, vTf, image_ids, lengths, pattn);
    small_gemm_kernel<<<dim3(3, 16), 256>>>(pattn, pWo, pool_q, pool, DIM, DIM);
    ln_kernel<<<16, 256>>>(pool, head_ln_g, pln, nullptr, nullptr, nullptr, nullptr);
    small_gemm_kernel<<<dim3(4, 16), 256>>>(pln, W_head, nullptr, (float*)d_out, NCLS, DIM);
}

// round 12
// speedup vs baseline: 1.0796x; 1.0796x over previous
#include <cuda_runtime.h>
#include <cuda_bf16.h>
#include <cuda_fp16.h>
#include <math.h>
#include <float.h>
#include <stdint.h>

// ---------------------------------------------------------------------------
// Problem constants
// ---------------------------------------------------------------------------
#define NB      4
#define NTOK    1024
#define DIM     768
#define NHEAD   12
#define DHEAD   64
#define MLPD    3072
#define IMGS    4
#define NCLS    1000
#define TOKS    (NB*NTOK)
#define BH      (NB*NHEAD)

#define FBIAS 1
#define FGELU 2
#define FRES  4

#define WOFF_EMB 0ULL
#define WPERL    7077888ULL
#define WOFF_L(l)   (589824ULL + (unsigned long long)(l)*WPERL)
#define WOFF_Q(l)   (WOFF_L(l) + 0ULL)
#define WOFF_KV(l)  (WOFF_L(l) + 589824ULL)
#define WOFF_O(l)   (WOFF_L(l) + 1769472ULL)
#define WOFF_W1(l)  (WOFF_L(l) + 2359296ULL)
#define WOFF_W2(l)  (WOFF_L(l) + 4718592ULL)
#define WOFF_PKV    (589824ULL + 4ULL*WPERL)
#define WTOTAL      30081024ULL

// ---------------------------------------------------------------------------
// Device scratch
// ---------------------------------------------------------------------------
__device__ float g_x   [TOKS*DIM];
__device__ float g_qkv [TOKS*2304];
__device__ __half g_xn  [TOKS*DIM];
__device__ __half g_tmp [TOKS*MLPD];
__device__ __half g_ao  [TOKS*DIM];
__device__ __nv_bfloat16 g_qTh[BH*NTOK*DHEAD], g_qTl[BH*NTOK*DHEAD];
__device__ __nv_bfloat16 g_kTh[BH*NTOK*DHEAD], g_kTl[BH*NTOK*DHEAD];
__device__ __half g_vTt[BH*DHEAD*NTOK];
__device__ float g_kTf[BH*NTOK*DHEAD], g_vTf[BH*NTOK*DHEAD];
__device__ float g_sm  [4096];
__device__ float g_pattn[16*DIM];
__device__ float g_pool [16*DIM];
__device__ float g_pln  [16*DIM];
__device__ __half g_w[WTOTAL];

// ---------------------------------------------------------------------------
// Helpers
// ---------------------------------------------------------------------------
__device__ __forceinline__ uint32_t smem_u32(const void* p) {
    uint32_t a;
    asm("{ .reg .u64 t; cvta.to.shared.u64 t, %1; cvt.u32.u64 %0, t; }" : "=r"(a) : "l"(p));
    return a;
}

#define LDSM4(r, addr) \
    asm volatile("ldmatrix.sync.aligned.m8n8.x4.shared.b16 {%0,%1,%2,%3}, [%4];" \
        : "=r"((r)[0]), "=r"((r)[1]), "=r"((r)[2]), "=r"((r)[3]) : "r"(addr))

#define MMA16816(d, a, b) \
    asm volatile("mma.sync.aligned.m16n8k16.row.col.f32.bf16.bf16.f32 " \
        "{%0,%1,%2,%3}, {%4,%5,%6,%7}, {%8,%9}, {%0,%1,%2,%3};" \
        : "+f"((d)[0]), "+f"((d)[1]), "+f"((d)[2]), "+f"((d)[3]) \
        : "r"((a)[0]), "r"((a)[1]), "r"((a)[2]), "r"((a)[3]), "r"((b)[0]), "r"((b)[1]))

#define MMAH16816(d, a, b) \
    asm volatile("mma.sync.aligned.m16n8k16.row.col.f32.f16.f16.f32 " \
        "{%0,%1,%2,%3}, {%4,%5,%6,%7}, {%8,%9}, {%0,%1,%2,%3};" \
        : "+f"((d)[0]), "+f"((d)[1]), "+f"((d)[2]), "+f"((d)[3]) \
        : "r"((a)[0]), "r"((a)[1]), "r"((a)[2]), "r"((a)[3]), "r"((b)[0]), "r"((b)[1]))

#define CPA16(dst, src) \
    asm volatile("cp.async.cg.shared.global [%0], [%1], 16;" :: "r"(dst), "l"(src))
#define CP_COMMIT() asm volatile("cp.async.commit_group;" ::: "memory")
#define CP_WAIT0()  asm volatile("cp.async.wait_group 0;" ::: "memory")
#define CP_WAIT1()  asm volatile("cp.async.wait_group 1;" ::: "memory")

__device__ __forceinline__ void split2(float v, __nv_bfloat16& h, __nv_bfloat16& l) {
    h = __float2bfloat16(v);
    l = __float2bfloat16(v - __bfloat162float(h));
}
__device__ __forceinline__ uint32_t bfu(__nv_bfloat16 b) { return (uint32_t)__bfloat16_as_ushort(b); }

template<typename T>
__device__ __forceinline__ void cpa_tile(uint32_t smbase, const T* __restrict__ g,
                                         int ldk, int chunks, int tid)
{
    for (int i = tid; i < chunks; i += 256) {
        int r = i >> 3, c = i & 7;
        uint32_t off = r * 128 + c * 16;
        uint32_t sw = off ^ ((off >> 3) & 0x70);
        CPA16(smbase + sw, g + (size_t)r * ldk + c * 8);
    }
}

// ---------------------------------------------------------------------------
// Weight convert+transpose, family-batched: z = layer.
// ---------------------------------------------------------------------------
__global__ void wconv_kernel(const float* __restrict__ W, __half* __restrict__ out,
                             int K, int N, long srcStride, long dstStride)
{
    __shared__ float t[32][33];
    int z = blockIdx.z;
    const float* Wz = W + (size_t)z * srcStride;
    __half* oz = out + (size_t)z * dstStride;
    int n0 = blockIdx.x * 32, k0 = blockIdx.y * 32;
    int tx = threadIdx.x, ty = threadIdx.y;
#pragma unroll
    for (int r = 0; r < 4; r++)
        t[ty + r*8][tx] = Wz[(size_t)(k0 + ty + r*8) * N + n0 + tx];
    __syncthreads();
#pragma unroll
    for (int r = 0; r < 4; r++) {
        int n = n0 + ty + r*8, k = k0 + tx;
        oz[(size_t)n * K + k] = __float2half(t[tx][ty + r*8]);
    }
}

// ---------------------------------------------------------------------------
// Pipelined mma.sync fp16 GEMM, single pass, 2-stage, 2 CTAs/SM.
// ---------------------------------------------------------------------------
__global__ void __launch_bounds__(256, 2) mma_gemm(
    const __half* __restrict__ A, const __half* __restrict__ B,
    const float* __restrict__ bias, const float* __restrict__ res,
    float* __restrict__ C, __half* __restrict__ Ch,
    int M, int N, int K, int flags)
{
    constexpr int A_SZ = 16384;
    constexpr int STG  = 2 * A_SZ;

    extern __shared__ char smem[];
    uint32_t uS = smem_u32(smem);

    const int tid = threadIdx.x;
    const int wid = tid >> 5, lane = tid & 31;
    const int m0 = blockIdx.y * 128, n0 = blockIdx.x * 128;
    const int wm = wid & 1, wn = wid >> 1;

    const __half* Az = A + (size_t)m0 * K;
    const __half* Bz = B + (size_t)n0 * K;

    float acc[4][4][4] = {};

    const int a_row = wm * 64 + (lane & 15);
    const int a_cb  = (lane >> 4) * 16;
    const int b_row = wn * 32 + (lane & 7) + ((lane >> 4) << 3);
    const int b_cb  = ((lane >> 3) & 1) * 16;

    const int KT = K >> 6;
    {
        cpa_tile(uS,         Az, K, 1024, tid);
        cpa_tile(uS + A_SZ,  Bz, K, 1024, tid);
        CP_COMMIT();
    }

    for (int kt = 0; kt < KT; kt++) {
        if (kt + 1 < KT) {
            uint32_t base = uS + ((kt + 1) & 1) * STG;
            cpa_tile(base,        Az + (kt + 1) * 64, K, 1024, tid);
            cpa_tile(base + A_SZ, Bz + (kt + 1) * 64, K, 1024, tid);
            CP_COMMIT();
            CP_WAIT1();
        } else {
            CP_WAIT0();
        }
        __syncthreads();

        uint32_t bA = uS + (kt & 1) * STG;
        uint32_t bB = bA + A_SZ;

#pragma unroll
        for (int ks = 0; ks < 4; ks++) {
            uint32_t ah[4][4], bh[2][4];
#pragma unroll
            for (int mt = 0; mt < 4; mt++) {
                int row = a_row + mt * 16;
                uint32_t off = row * 128 + ((a_cb + ks * 32) ^ ((row & 7) << 4));
                LDSM4(ah[mt], bA + off);
            }
#pragma unroll
            for (int q = 0; q < 2; q++) {
                int row = b_row + q * 16;
                uint32_t off = row * 128 + ((b_cb + ks * 32) ^ ((row & 7) << 4));
                LDSM4(bh[q], bB + off);
            }
#pragma unroll
            for (int mt = 0; mt < 4; mt++)
#pragma unroll
                for (int nt = 0; nt < 4; nt++)
                    MMAH16816(acc[mt][nt], ah[mt], &bh[nt >> 1][(nt & 1) * 2]);
        }
        __syncthreads();
    }

    const int rbase = m0 + wm * 64;
#pragma unroll
    for (int mt = 0; mt < 4; mt++) {
#pragma unroll
        for (int nt = 0; nt < 4; nt++) {
            int c = n0 + wn * 32 + nt * 8 + (lane & 3) * 2;
            float bv0 = 0.f, bv1 = 0.f;
            if (flags & FBIAS) { bv0 = bias[c]; bv1 = bias[c + 1]; }
#pragma unroll
            for (int half = 0; half < 2; half++) {
                int r = rbase + mt * 16 + (lane >> 2) + half * 8;
                float v0 = acc[mt][nt][half * 2 + 0];
                float v1 = acc[mt][nt][half * 2 + 1];
                if (flags & FBIAS) { v0 += bv0; v1 += bv1; }
                if (flags & FGELU) {
                    v0 = 0.5f * v0 * (1.f + erff(v0 * 0.70710678118654752f));
                    v1 = 0.5f * v1 * (1.f + erff(v1 * 0.70710678118654752f));
                }
                long idx = (long)r * N + c;
                if (flags & FRES) { v0 += res[idx]; v1 += res[idx + 1]; }
                if (C) *(float2*)(C + idx) = make_float2(v0, v1);
                if (Ch) {
                    __half2 hv = __floats2half2_rn(v0, v1);
                    *(__half2*)(Ch + idx) = hv;
                }
            }
        }
    }
}

// ---------------------------------------------------------------------------
// Fused flash attention. QK bf16 hi/lo 3-pass (accuracy-critical);
// PV single-pass fp16 (P in [0,1], V activation — benign quantization).
// Double-buffered KV stages (R10 structure). Stage = Khi 16K + Klo 16K + V 16K.
// ---------------------------------------------------------------------------
#define FA_SMEM 133120

__global__ void __launch_bounds__(256, 1) flash_attn(
    const __nv_bfloat16* __restrict__ Qh_, const __nv_bfloat16* __restrict__ Ql_,
    const __nv_bfloat16* __restrict__ Kh_, const __nv_bfloat16* __restrict__ Kl_,
    const __half* __restrict__ Vt_,
    const int* __restrict__ image_ids, const int* __restrict__ lengths,
    __half* __restrict__ O_)
{
    extern __shared__ char smem[];
    uint32_t uS = smem_u32(smem);
    const int tid = threadIdx.x, wid = tid >> 5, lane = tid & 31;
    const int z = blockIdx.y, b = z / 12, h = z % 12;
    const int m0 = blockIdx.x * 128;

    int* s_cmin   = (int*)(smem + 131072);
    int* s_cmax   = s_cmin + 8;
    int* s_jlist  = s_cmax + 8;
    int* s_meta   = s_jlist + 8;
    int* s_imgRow = s_meta + 8;
    int* s_imgCol = s_imgRow + 128;   // 2 stages x 128

    const int len = lengths[b];

    {
        int4 v = *(const int4*)(image_ids + b*1024 + wid*128 + lane*4);
        int mn = min(min(v.x, v.y), min(v.z, v.w));
        int mx = max(max(v.x, v.y), max(v.z, v.w));
#pragma unroll
        for (int o = 16; o; o >>= 1) {
            mn = min(mn, __shfl_xor_sync(0xffffffffu, mn, o));
            mx = max(mx, __shfl_xor_sync(0xffffffffu, mx, o));
        }
        if (lane == 0) { s_cmin[wid] = mn; s_cmax[wid] = mx; }
    }
    if (tid < 128) s_imgRow[tid] = image_ids[b*1024 + m0 + tid];
    __syncthreads();
    if (tid == 0) {
        int rmin = s_cmin[blockIdx.x], rmax = s_cmax[blockIdx.x];
        int nj = 0;
        for (int jb = 0; jb < 8; jb++)
            if (jb * 128 < len && s_cmax[jb] >= rmin && s_cmin[jb] <= rmax)
                s_jlist[nj++] = jb;
        s_meta[0] = nj;
    }
    __syncthreads();
    const int nj = s_meta[0];

    const size_t qoff = ((size_t)z * 1024 + m0) * 64;
    cpa_tile(uS,         Qh_ + qoff, 64, 1024, tid);
    cpa_tile(uS + 16384, Ql_ + qoff, 64, 1024, tid);

    auto prefetch = [&](int t) {
        int jb = s_jlist[t];
        int st = t & 1;
        uint32_t base = uS + 32768 + st * 49152;
        size_t koff = ((size_t)z * 1024 + jb * 128) * 64;
        cpa_tile(base,         Kh_ + koff, 64, 1024, tid);
        cpa_tile(base + 16384, Kl_ + koff, 64, 1024, tid);
        const __half* vt = Vt_ + (size_t)z * 64 * 1024 + jb * 128;
        for (int i = tid; i < 1024; i += 256) {   // 64 rows x 16 chunks (V fp16 single)
            int r = i >> 4, c = i & 15;
            int kc = c >> 3, cc = c & 7;
            uint32_t off = r * 128 + cc * 16;
            uint32_t sw = off ^ ((off >> 3) & 0x70);
            CPA16(base + 32768 + kc * 8192 + sw, vt + (size_t)r * 1024 + c * 8);
        }
        if (tid < 128) s_imgCol[st * 128 + tid] = image_ids[b*1024 + jb*128 + tid];
    };
    prefetch(0);
    CP_COMMIT();

    float O[8][4] = {};
    float mA = -FLT_MAX, mB = -FLT_MAX, lA = 0.f, lB = 0.f;
    uint32_t qh[4][4], ql[4][4];
    bool qloaded = false;

    const int rA = lane >> 2;
    const int imgA = s_imgRow[wid * 16 + rA];
    const int imgB = s_imgRow[wid * 16 + rA + 8];

    const int a_row = wid * 16 + (lane & 15);
    const int a_cb  = (lane >> 4) * 16;
    const int b_row_base = (lane & 7) + ((lane >> 4) << 3);
    const int b_cb  = ((lane >> 3) & 1) * 16;

    for (int t = 0; t < nj; t++) {
        if (t + 1 < nj) { prefetch(t + 1); CP_COMMIT(); CP_WAIT1(); }
        else CP_WAIT0();
        __syncthreads();

        if (!qloaded) {
            qloaded = true;
#pragma unroll
            for (int ks = 0; ks < 4; ks++) {
                uint32_t off = a_row * 128 + ((a_cb + ks * 32) ^ ((a_row & 7) << 4));
                LDSM4(qh[ks], uS + off);
                LDSM4(ql[ks], uS + 16384 + off);
            }
        }

        int st = t & 1;
        uint32_t bK  = uS + 32768 + st * 49152;
        uint32_t bKl = bK + 16384;
        uint32_t bV  = bK + 32768;
        int jb = s_jlist[t];
        int j0 = jb * 128;
        const int* imgC = s_imgCol + st * 128;

        float S[16][4] = {};
#pragma unroll
        for (int ks = 0; ks < 4; ks++) {
#pragma unroll
            for (int nb = 0; nb < 8; nb++) {
                uint32_t bh4[4], bl4[4];
                int row = nb * 16 + b_row_base;
                uint32_t off = row * 128 + ((b_cb + ks * 32) ^ ((row & 7) << 4));
                LDSM4(bh4, bK + off);
                LDSM4(bl4, bKl + off);
                MMA16816(S[2*nb],   qh[ks], bh4);
                MMA16816(S[2*nb+1], qh[ks], bh4 + 2);
                MMA16816(S[2*nb],   qh[ks], bl4);
                MMA16816(S[2*nb+1], qh[ks], bl4 + 2);
                MMA16816(S[2*nb],   ql[ks], bh4);
                MMA16816(S[2*nb+1], ql[ks], bh4 + 2);
            }
        }

        float mnA = mA, mnB = mB;
#pragma unroll
        for (int nt = 0; nt < 16; nt++) {
            int c0 = nt * 8 + (lane & 3) * 2;
            int i0 = imgC[c0], i1 = imgC[c0 + 1];
            bool v0 = (j0 + c0) < len, v1 = (j0 + c0 + 1) < len;
            if (i0 == imgA && v0) mnA = fmaxf(mnA, S[nt][0]);
            if (i1 == imgA && v1) mnA = fmaxf(mnA, S[nt][1]);
            if (i0 == imgB && v0) mnB = fmaxf(mnB, S[nt][2]);
            if (i1 == imgB && v1) mnB = fmaxf(mnB, S[nt][3]);
        }
#pragma unroll
        for (int o = 1; o <= 2; o <<= 1) {
            mnA = fmaxf(mnA, __shfl_xor_sync(0xffffffffu, mnA, o));
            mnB = fmaxf(mnB, __shfl_xor_sync(0xffffffffu, mnB, o));
        }
        float scA = __expf(mA - mnA), scB = __expf(mB - mnB);
        mA = mnA; mB = mnB;
        lA *= scA; lB *= scB;
#pragma unroll
        for (int nt = 0; nt < 16; nt++) {
            int c0 = nt * 8 + (lane & 3) * 2;
            int i0 = imgC[c0], i1 = imgC[c0 + 1];
            bool v0 = (j0 + c0) < len, v1 = (j0 + c0 + 1) < len;
            float p0 = (i0 == imgA && v0) ? __expf(S[nt][0] - mnA) : 0.f;
            float p1 = (i1 == imgA && v1) ? __expf(S[nt][1] - mnA) : 0.f;
            float p2 = (i0 == imgB && v0) ? __expf(S[nt][2] - mnB) : 0.f;
            float p3 = (i1 == imgB && v1) ? __expf(S[nt][3] - mnB) : 0.f;
            lA += p0 + p1; lB += p2 + p3;
            S[nt][0] = p0; S[nt][1] = p1; S[nt][2] = p2; S[nt][3] = p3;
        }
#pragma unroll
        for (int nt = 0; nt < 8; nt++) {
            O[nt][0] *= scA; O[nt][1] *= scA; O[nt][2] *= scB; O[nt][3] *= scB;
        }

        // ---- PV: single-pass fp16 (P from registers, V fp16) ----
#pragma unroll
        for (int kt = 0; kt < 8; kt++) {
            uint32_t ah4[4];
            {
                __half2 p0 = __floats2half2_rn(S[2*kt][0],   S[2*kt][1]);
                __half2 p1 = __floats2half2_rn(S[2*kt][2],   S[2*kt][3]);
                __half2 p2 = __floats2half2_rn(S[2*kt+1][0], S[2*kt+1][1]);
                __half2 p3 = __floats2half2_rn(S[2*kt+1][2], S[2*kt+1][3]);
                ah4[0] = *(uint32_t*)&p0; ah4[1] = *(uint32_t*)&p1;
                ah4[2] = *(uint32_t*)&p2; ah4[3] = *(uint32_t*)&p3;
            }
            uint32_t tb = bV + (kt >> 2) * 8192;
#pragma unroll
            for (int nb = 0; nb < 4; nb++) {
                uint32_t vh4[4];
                int row = nb * 16 + b_row_base;
                uint32_t off = row * 128 + ((b_cb + (kt & 3) * 32) ^ ((row & 7) << 4));
                LDSM4(vh4, tb + off);
                MMAH16816(O[2*nb],   ah4, vh4);
                MMAH16816(O[2*nb+1], ah4, vh4 + 2);
            }
        }
        __syncthreads();
    }

#pragma unroll
    for (int o = 1; o <= 2; o <<= 1) {
        lA += __shfl_xor_sync(0xffffffffu, lA, o);
        lB += __shfl_xor_sync(0xffffffffu, lB, o);
    }
    float iA = lA > 0.f ? 1.f / lA : 0.f;
    float iB = lB > 0.f ? 1.f / lB : 0.f;
    size_t rowA = (size_t)(b * 1024 + m0 + wid * 16 + rA);
#pragma unroll
    for (int nt = 0; nt < 8; nt++) {
        int c = nt * 8 + (lane & 3) * 2;
        size_t idx = rowA * 768 + h * 64 + c;
        *(__half2*)(O_ + idx) = __floats2half2_rn(O[nt][0] * iA, O[nt][1] * iA);
        idx = (rowA + 8) * 768 + h * 64 + c;
        *(__half2*)(O_ + idx) = __floats2half2_rn(O[nt][2] * iB, O[nt][3] * iB);
    }
}

// ---------------------------------------------------------------------------
// LayerNorm over width 768. fp32 and/or fp16 outputs. Optional pos add.
// ---------------------------------------------------------------------------
__global__ void ln_kernel(const float* __restrict__ in, const float* __restrict__ g,
                          float* __restrict__ outf, __half* __restrict__ outh,
                          const float* __restrict__ pos_h, const float* __restrict__ pos_w,
                          const int* __restrict__ ppos)
{
    int row = blockIdx.x;
    int tid = threadIdx.x;
    const float* xr = in + (size_t)row * 768;
    float v[3]; float s = 0.f, q = 0.f;
#pragma unroll
    for (int i = 0; i < 3; i++) { float t = xr[tid + i*256]; v[i] = t; s += t; q += t*t; }
#pragma unroll
    for (int o = 16; o; o >>= 1) {
        s += __shfl_xor_sync(0xffffffffu, s, o);
        q += __shfl_xor_sync(0xffffffffu, q, o);
    }
    __shared__ float shs[8], shq[8], st[2];
    int w = tid >> 5;
    if ((tid & 31) == 0) { shs[w] = s; shq[w] = q; }
    __syncthreads();
    if (tid == 0) {
        float S = 0.f, Q = 0.f;
#pragma unroll
        for (int i = 0; i < 8; i++) { S += shs[i]; Q += shq[i]; }
        float mu = S * (1.f/768.f);
        st[0] = mu;
        st[1] = rsqrtf(Q * (1.f/768.f) - mu*mu + 1e-5f);
    }
    __syncthreads();
    float mu = st[0], rs = st[1];
    int p0 = 0, p1 = 0;
    if (ppos) { p0 = ppos[row*2]; p1 = ppos[row*2 + 1]; }
#pragma unroll
    for (int i = 0; i < 3; i++) {
        int c = tid + i*256;
        float y = (v[i] - mu) * rs * g[c];
        if (ppos) y += pos_h[p0*768 + c] + pos_w[p1*768 + c];
        size_t idx = (size_t)row*768 + c;
        if (outf) outf[idx] = y;
        if (outh) outh[idx] = __float2half(y);
    }
}

// ---------------------------------------------------------------------------
// Fused QKV postprocess: q/k bf16 hi/lo, v fp16 single ([z][d][n]).
// ---------------------------------------------------------------------------
__global__ void rmsT_all(const float* __restrict__ qkv,
                         const float* __restrict__ qg, const float* __restrict__ kg,
                         __nv_bfloat16* __restrict__ qh, __nv_bfloat16* __restrict__ ql,
                         __nv_bfloat16* __restrict__ kh, __nv_bfloat16* __restrict__ kl,
                         __half* __restrict__ vt)
{
    int token = blockIdx.x;
    int b = token >> 10, n = token & 1023;
    int w = threadIdx.x >> 5, lane = threadIdx.x & 31;
    const float* base = qkv + (size_t)token * 2304 + w * 64;
    __nv_bfloat16 hh, ll;

    {
        float v0 = base[lane], v1 = base[lane + 32];
        float ss = v0*v0 + v1*v1;
#pragma unroll
        for (int o = 16; o; o >>= 1) ss += __shfl_xor_sync(0xffffffffu, ss, o);
        float inv = 8.0f / fmaxf(sqrtf(ss), 1e-12f);
        v0 *= inv * qg[w*64 + lane];
        v1 *= inv * qg[w*64 + lane + 32];
        size_t dst = ((size_t)(b*12 + w) * 1024 + n) * 64;
        split2(v0, hh, ll); qh[dst + lane] = hh;      ql[dst + lane] = ll;
        split2(v1, hh, ll); qh[dst + lane + 32] = hh; ql[dst + lane + 32] = ll;
    }
    {
        float v0 = base[768 + lane], v1 = base[768 + lane + 32];
        float ss = v0*v0 + v1*v1;
#pragma unroll
        for (int o = 16; o; o >>= 1) ss += __shfl_xor_sync(0xffffffffu, ss, o);
        float inv = 8.0f / fmaxf(sqrtf(ss), 1e-12f);
        v0 *= inv * kg[w*64 + lane];
        v1 *= inv * kg[w*64 + lane + 32];
        size_t dst = ((size_t)(b*12 + w) * 1024 + n) * 64;
        split2(v0, hh, ll); kh[dst + lane] = hh;      kl[dst + lane] = ll;
        split2(v1, hh, ll); kh[dst + lane + 32] = hh; kl[dst + lane + 32] = ll;
    }
    {
        float v0 = base[1536 + lane], v1 = base[1536 + lane + 32];
        size_t vb = ((size_t)(b*12 + w) * 64) * 1024 + n;
        vt[vb + (size_t)lane * 1024]        = __float2half(v0);
        vt[vb + (size_t)(lane + 32) * 1024] = __float2half(v1);
    }
}

// Pool-path: one launch does k-rms + v copy (fp32 outputs).
__global__ void rmsT_pool(const float* __restrict__ kv,
                          const float* __restrict__ kg,
                          float* __restrict__ kT, float* __restrict__ vT)
{
    int token = blockIdx.x;
    int b = token >> 10, n = token & 1023;
    int w = threadIdx.x >> 5, lane = threadIdx.x & 31;
    const float* base = kv + (size_t)token * 1536 + w * 64;
    {
        float v0 = base[lane], v1 = base[lane + 32];
        float ss = v0*v0 + v1*v1;
#pragma unroll
        for (int o = 16; o; o >>= 1) ss += __shfl_xor_sync(0xffffffffu, ss, o);
        float inv = 8.0f / fmaxf(sqrtf(ss), 1e-12f);
        float* dst = kT + ((size_t)(b*12 + w) * 1024 + n) * 64;
        dst[lane]      = v0 * inv * kg[w*64 + lane];
        dst[lane + 32] = v1 * inv * kg[w*64 + lane + 32];
    }
    {
        float v0 = base[768 + lane], v1 = base[768 + lane + 32];
        float* dst = vT + ((size_t)(b*12 + w) * 1024 + n) * 64;
        dst[lane] = v0; dst[lane + 32] = v1;
    }
}

// ---------------------------------------------------------------------------
// Attention pooling (192 blocks), fp32 path.
// ---------------------------------------------------------------------------
__global__ void pool_attn_kernel(const float* __restrict__ pqn, const float* __restrict__ kT,
                                 const float* __restrict__ vT, const int* __restrict__ image_ids,
                                 const int* __restrict__ lengths, float* __restrict__ out)
{
    int idx = blockIdx.x;
    int h = idx % 12, img = (idx / 12) % 4, b = idx / 48;
    int tid = threadIdx.x;
    __shared__ float q[64];
    __shared__ float p[1024];
    __shared__ float sh[8];
    __shared__ float bs[2];
    __shared__ float sred[256];
    if (tid < 64) q[tid] = pqn[h*64 + tid];
    __syncthreads();

    const float* K = kT + (size_t)(b*12 + h) * 1024 * 64;
    int len = lengths[b];
    float loc[4]; float mx = -FLT_MAX;
#pragma unroll
    for (int t = 0; t < 4; t++) {
        int j = tid + t*256;
        const float* kr = K + (size_t)j * 64;
        float dot = 0.f;
#pragma unroll
        for (int d = 0; d < 64; d++) dot += q[d] * kr[d];
        bool ok = (image_ids[b*1024 + j] == img) && (j < len);
        loc[t] = ok ? dot : -FLT_MAX;
        mx = fmaxf(mx, loc[t]);
    }
#pragma unroll
    for (int o = 16; o; o >>= 1) mx = fmaxf(mx, __shfl_xor_sync(0xffffffffu, mx, o));
    int w = tid >> 5;
    if ((tid & 31) == 0) sh[w] = mx;
    __syncthreads();
    if (tid == 0) { float mm = sh[0]; for (int i = 1; i < 8; i++) mm = fmaxf(mm, sh[i]); bs[0] = mm; }
    __syncthreads();
    mx = bs[0];
    float s = 0.f;
#pragma unroll
    for (int t = 0; t < 4; t++) {
        float e = __expf(loc[t] - mx);
        p[tid + t*256] = e;
        s += e;
    }
#pragma unroll
    for (int o = 16; o; o >>= 1) s += __shfl_xor_sync(0xffffffffu, s, o);
    if ((tid & 31) == 0) sh[w] = s;
    __syncthreads();
    if (tid == 0) { float ss = 0.f; for (int i = 0; i < 8; i++) ss += sh[i]; bs[1] = 1.f / ss; }
    __syncthreads();
    float inv = bs[1];

    const float* V = vT + (size_t)(b*12 + h) * 1024 * 64;
    int d = tid & 63, grp = tid >> 6;
    float acc = 0.f;
    for (int j = grp; j < 1024; j += 4) acc += p[j] * V[(size_t)j*64 + d];
    sred[tid] = acc;
    __syncthreads();
    if (grp == 0) {
        float r = (sred[d] + sred[d + 64]) + (sred[d + 128] + sred[d + 192]);
        out[(size_t)(b*4 + img) * 768 + h*64 + d] = r * inv;
    }
}

__global__ void rms_vec_kernel(const float* __restrict__ in, const float* __restrict__ g,
                               float* __restrict__ out)
{
    int w = threadIdx.x >> 5, lane = threadIdx.x & 31;
    float v0 = in[w*64 + lane], v1 = in[w*64 + lane + 32];
    float ss = v0*v0 + v1*v1;
#pragma unroll
    for (int o = 16; o; o >>= 1) ss += __shfl_xor_sync(0xffffffffu, ss, o);
    float inv = 8.0f / fmaxf(sqrtf(ss), 1e-12f);
    out[w*64 + lane]      = v0 * inv * g[w*64 + lane];
    out[w*64 + lane + 32] = v1 * inv * g[w*64 + lane + 32];
}

__global__ void small_gemm_kernel(const float* __restrict__ A, const float* __restrict__ W,
                                  const float* __restrict__ addvec, float* __restrict__ C,
                                  int N, int K)
{
    __shared__ float a[768];
    int row = blockIdx.y;
    for (int i = threadIdx.x; i < K; i += 256) a[i] = A[(size_t)row*K + i];
    __syncthreads();
    int n = blockIdx.x * 256 + threadIdx.x;
    if (n >= N) return;
    float acc = addvec ? addvec[n] : 0.f;
#pragma unroll 4
    for (int k = 0; k < K; k++) acc += a[k] * W[(size_t)k*N + n];
    C[(size_t)row*N + n] = acc;
}

// ---------------------------------------------------------------------------
// Host side
// ---------------------------------------------------------------------------
extern "C" void kernel_launch(void* const* d_in, const int* in_sizes, int n_in,
                              void* d_out, int out_size)
{
    (void)in_sizes; (void)n_in; (void)out_size;
    const float* patches    = (const float*)d_in[0];
    const int*   ppos       = (const int*)  d_in[1];
    const int*   image_ids  = (const int*)  d_in[2];
    const int*   lengths    = (const int*)  d_in[3];
    const float* emb_ln_g   = (const float*)d_in[4];
    const float* W_emb      = (const float*)d_in[5];
    const float* b_emb      = (const float*)d_in[6];
    const float* emb_ln2_g  = (const float*)d_in[7];
    const float* pos_h      = (const float*)d_in[8];
    const float* pos_w      = (const float*)d_in[9];
    const float* ln_attn_g  = (const float*)d_in[10];
    const float* Wq         = (const float*)d_in[11];
    const float* Wkv        = (const float*)d_in[12];
    const float* qn_g       = (const float*)d_in[13];
    const float* kn_g       = (const float*)d_in[14];
    const float* Wo         = (const float*)d_in[15];
    const float* ln_ff_g    = (const float*)d_in[16];
    const float* W1         = (const float*)d_in[17];
    const float* b1         = (const float*)d_in[18];
    const float* W2         = (const float*)d_in[19];
    const float* b2         = (const float*)d_in[20];
    const float* final_ln_g = (const float*)d_in[21];
    const float* pool_q     = (const float*)d_in[22];
    const float* pool_ln_g  = (const float*)d_in[23];
    const float* pWq        = (const float*)d_in[24];
    const float* pWkv       = (const float*)d_in[25];
    const float* p_qn_g     = (const float*)d_in[26];
    const float* p_kn_g     = (const float*)d_in[27];
    const float* pWo        = (const float*)d_in[28];
    const float* head_ln_g  = (const float*)d_in[29];
    const float* W_head     = (const float*)d_in[30];

    float *x, *qkv, *kTf, *vTf, *sm, *pattn, *pool, *pln;
    __half *xn, *tmp, *ao, *w, *vTt;
    __nv_bfloat16 *qTh, *qTl, *kTh, *kTl;
    cudaGetSymbolAddress((void**)&x,    g_x);
    cudaGetSymbolAddress((void**)&qkv,  g_qkv);
    cudaGetSymbolAddress((void**)&kTf,  g_kTf);
    cudaGetSymbolAddress((void**)&vTf,  g_vTf);
    cudaGetSymbolAddress((void**)&sm,   g_sm);
    cudaGetSymbolAddress((void**)&pattn,g_pattn);
    cudaGetSymbolAddress((void**)&pool, g_pool);
    cudaGetSymbolAddress((void**)&pln,  g_pln);
    cudaGetSymbolAddress((void**)&xn,   g_xn);
    cudaGetSymbolAddress((void**)&tmp,  g_tmp);
    cudaGetSymbolAddress((void**)&ao,   g_ao);
    cudaGetSymbolAddress((void**)&qTh,  g_qTh);
    cudaGetSymbolAddress((void**)&qTl,  g_qTl);
    cudaGetSymbolAddress((void**)&kTh,  g_kTh);
    cudaGetSymbolAddress((void**)&kTl,  g_kTl);
    cudaGetSymbolAddress((void**)&vTt,  g_vTt);
    cudaGetSymbolAddress((void**)&w,    g_w);

    constexpr int SMEMG = 65536;
    cudaFuncSetAttribute(mma_gemm,   cudaFuncAttributeMaxDynamicSharedMemorySize, SMEMG);
    cudaFuncSetAttribute(flash_attn, cudaFuncAttributeMaxDynamicSharedMemorySize, FA_SMEM);

    // ---- Convert + transpose weights to fp16 [N,K], family-batched ----
    dim3 wb(32, 8);
    wconv_kernel<<<dim3(DIM/32,  DIM/32,  1), wb>>>(W_emb, w + WOFF_EMB, DIM, DIM, 0, 0);
    wconv_kernel<<<dim3(DIM/32,  DIM/32,  4), wb>>>(Wq,  w + WOFF_Q(0),  DIM,  DIM,   (long)DIM*DIM,   (long)WPERL);
    wconv_kernel<<<dim3(2*DIM/32,DIM/32,  4), wb>>>(Wkv, w + WOFF_KV(0), DIM,  2*DIM, (long)DIM*2*DIM, (long)WPERL);
    wconv_kernel<<<dim3(DIM/32,  DIM/32,  4), wb>>>(Wo,  w + WOFF_O(0),  DIM,  DIM,   (long)DIM*DIM,   (long)WPERL);
    wconv_kernel<<<dim3(MLPD/32, DIM/32,  4), wb>>>(W1,  w + WOFF_W1(0), DIM,  MLPD,  (long)DIM*MLPD,  (long)WPERL);
    wconv_kernel<<<dim3(DIM/32,  MLPD/32, 4), wb>>>(W2,  w + WOFF_W2(0), MLPD, DIM,   (long)MLPD*DIM,  (long)WPERL);
    wconv_kernel<<<dim3(2*DIM/32,DIM/32,  1), wb>>>(pWkv, w + WOFF_PKV, DIM, 2*DIM, 0, 0);

    auto G = [&](const __half* a, const __half* bw,
                 const float* bias, const float* res,
                 float* C, __half* Ch, int M, int N, int K, int flags) {
        mma_gemm<<<dim3(N/128, M/128), 256, SMEMG>>>(a, bw, bias, res, C, Ch, M, N, K, flags);
    };

    // ---- Embedding ----
    ln_kernel<<<TOKS, 256>>>(patches, emb_ln_g, nullptr, xn, nullptr, nullptr, nullptr);
    G(xn, w + WOFF_EMB, b_emb, nullptr, x, nullptr, TOKS, DIM, DIM, FBIAS);
    ln_kernel<<<TOKS, 256>>>(x, emb_ln2_g, x, nullptr, pos_h, pos_w, ppos);

    // ---- Transformer layers ----
    for (int l = 0; l < 4; l++) {
        ln_kernel<<<TOKS, 256>>>(x, ln_attn_g + l*DIM, nullptr, xn, nullptr, nullptr, nullptr);
        G(xn, w + WOFF_Q(l), nullptr, nullptr, qkv, nullptr, TOKS, 2304, DIM, 0);
        rmsT_all<<<TOKS, 384>>>(qkv, qn_g + l*DIM, kn_g + l*DIM, qTh, qTl, kTh, kTl, vTt);
        flash_attn<<<dim3(8, BH), 256, FA_SMEM>>>(qTh, qTl, kTh, kTl, vTt,
                                                  image_ids, lengths, ao);
        G(ao, w + WOFF_O(l), nullptr, x, x, nullptr, TOKS, DIM, DIM, FRES);
        ln_kernel<<<TOKS, 256>>>(x, ln_ff_g + l*DIM, nullptr, xn, nullptr, nullptr, nullptr);
        G(xn, w + WOFF_W1(l), b1 + l*MLPD, nullptr, nullptr, tmp, TOKS, MLPD, DIM, FBIAS|FGELU);
        G(tmp, w + WOFF_W2(l), b2 + l*DIM, x, x, nullptr, TOKS, DIM, MLPD, FBIAS|FRES);
    }

    // ---- Final LN ----
    ln_kernel<<<TOKS, 256>>>(x, final_ln_g, nullptr, xn, nullptr, nullptr, nullptr);

    // ---- Attention pooling ----
    ln_kernel<<<1, 256>>>(pool_q, pool_ln_g, sm, nullptr, nullptr, nullptr, nullptr);
    small_gemm_kernel<<<dim3(3, 1), 256>>>(sm, pWq, nullptr, sm + 768, DIM, DIM);
    rms_vec_kernel<<<1, 384>>>(sm + 768, p_qn_g, sm + 1536);
    G(xn, w + WOFF_PKV, nullptr, nullptr, qkv, nullptr, TOKS, 1536, DIM, 0);
    rmsT_pool<<<TOKS, 384>>>(qkv, p_kn_g, kTf, vTf);
    pool_attn_kernel<<<NB*IMGS*NHEAD, 256>>>(sm + 1536, kTf, vTf, image_ids, lengths, pattn);
    small_gemm_kernel<<<dim3(3, 16), 256>>>(pattn, pWo, pool_q, pool, DIM, DIM);
    ln_kernel<<<16, 256>>>(pool, head_ln_g, pln, nullptr, nullptr, nullptr, nullptr);
    small_gemm_kernel<<<dim3(4, 16), 256>>>(pln, W_head, nullptr, (float*)d_out, NCLS, DIM);
}

// round 13
// speedup vs baseline: 1.0845x; 1.0045x over previous
#include <cuda_runtime.h>
#include <cuda_bf16.h>
#include <cuda_fp16.h>
#include <math.h>
#include <float.h>
#include <stdint.h>

// ---------------------------------------------------------------------------
// Problem constants
// ---------------------------------------------------------------------------
#define NB      4
#define NTOK    1024
#define DIM     768
#define NHEAD   12
#define DHEAD   64
#define MLPD    3072
#define IMGS    4
#define NCLS    1000
#define TOKS    (NB*NTOK)
#define BH      (NB*NHEAD)

#define FBIAS 1
#define FGELU 2
#define FRES  4

#define WOFF_EMB 0ULL
#define WPERL    7077888ULL
#define WOFF_L(l)   (589824ULL + (unsigned long long)(l)*WPERL)
#define WOFF_Q(l)   (WOFF_L(l) + 0ULL)
#define WOFF_KV(l)  (WOFF_L(l) + 589824ULL)
#define WOFF_O(l)   (WOFF_L(l) + 1769472ULL)
#define WOFF_W1(l)  (WOFF_L(l) + 2359296ULL)
#define WOFF_W2(l)  (WOFF_L(l) + 4718592ULL)
#define WOFF_PKV    (589824ULL + 4ULL*WPERL)
#define WTOTAL      30081024ULL

// ---------------------------------------------------------------------------
// Device scratch
// ---------------------------------------------------------------------------
__device__ float g_x   [TOKS*DIM];
__device__ float g_qkv [TOKS*2304];
__device__ __half g_xn  [TOKS*DIM];
__device__ __half g_tmp [TOKS*MLPD];
__device__ __half g_ao  [TOKS*DIM];
__device__ __nv_bfloat16 g_qTh[BH*NTOK*DHEAD], g_qTl[BH*NTOK*DHEAD];
__device__ __nv_bfloat16 g_kTh[BH*NTOK*DHEAD], g_kTl[BH*NTOK*DHEAD];
__device__ __half g_vTt[BH*DHEAD*NTOK];
__device__ float g_kTf[BH*NTOK*DHEAD], g_vTf[BH*NTOK*DHEAD];
__device__ float g_sm  [4096];
__device__ float g_pattn[16*DIM];
__device__ float g_pool [16*DIM];
__device__ float g_pln  [16*DIM];
__device__ __half g_w[WTOTAL];

// ---------------------------------------------------------------------------
// Helpers
// ---------------------------------------------------------------------------
__device__ __forceinline__ uint32_t smem_u32(const void* p) {
    uint32_t a;
    asm("{ .reg .u64 t; cvta.to.shared.u64 t, %1; cvt.u32.u64 %0, t; }" : "=r"(a) : "l"(p));
    return a;
}

#define LDSM4(r, addr) \
    asm volatile("ldmatrix.sync.aligned.m8n8.x4.shared.b16 {%0,%1,%2,%3}, [%4];" \
        : "=r"((r)[0]), "=r"((r)[1]), "=r"((r)[2]), "=r"((r)[3]) : "r"(addr))

#define MMA16816(d, a, b) \
    asm volatile("mma.sync.aligned.m16n8k16.row.col.f32.bf16.bf16.f32 " \
        "{%0,%1,%2,%3}, {%4,%5,%6,%7}, {%8,%9}, {%0,%1,%2,%3};" \
        : "+f"((d)[0]), "+f"((d)[1]), "+f"((d)[2]), "+f"((d)[3]) \
        : "r"((a)[0]), "r"((a)[1]), "r"((a)[2]), "r"((a)[3]), "r"((b)[0]), "r"((b)[1]))

#define MMAH16816(d, a, b) \
    asm volatile("mma.sync.aligned.m16n8k16.row.col.f32.f16.f16.f32 " \
        "{%0,%1,%2,%3}, {%4,%5,%6,%7}, {%8,%9}, {%0,%1,%2,%3};" \
        : "+f"((d)[0]), "+f"((d)[1]), "+f"((d)[2]), "+f"((d)[3]) \
        : "r"((a)[0]), "r"((a)[1]), "r"((a)[2]), "r"((a)[3]), "r"((b)[0]), "r"((b)[1]))

#define CPA16(dst, src) \
    asm volatile("cp.async.cg.shared.global [%0], [%1], 16;" :: "r"(dst), "l"(src))
#define CP_COMMIT() asm volatile("cp.async.commit_group;" ::: "memory")
#define CP_WAIT0()  asm volatile("cp.async.wait_group 0;" ::: "memory")
#define CP_WAIT1()  asm volatile("cp.async.wait_group 1;" ::: "memory")

__device__ __forceinline__ void split2(float v, __nv_bfloat16& h, __nv_bfloat16& l) {
    h = __float2bfloat16(v);
    l = __float2bfloat16(v - __bfloat162float(h));
}
__device__ __forceinline__ uint32_t bfu(__nv_bfloat16 b) { return (uint32_t)__bfloat16_as_ushort(b); }

template<typename T>
__device__ __forceinline__ void cpa_tile(uint32_t smbase, const T* __restrict__ g,
                                         int ldk, int chunks, int tid)
{
    for (int i = tid; i < chunks; i += 256) {
        int r = i >> 3, c = i & 7;
        uint32_t off = r * 128 + c * 16;
        uint32_t sw = off ^ ((off >> 3) & 0x70);
        CPA16(smbase + sw, g + (size_t)r * ldk + c * 8);
    }
}

// ---------------------------------------------------------------------------
// Weight convert+transpose, family-batched: z = layer.
// ---------------------------------------------------------------------------
__global__ void wconv_kernel(const float* __restrict__ W, __half* __restrict__ out,
                             int K, int N, long srcStride, long dstStride)
{
    __shared__ float t[32][33];
    int z = blockIdx.z;
    const float* Wz = W + (size_t)z * srcStride;
    __half* oz = out + (size_t)z * dstStride;
    int n0 = blockIdx.x * 32, k0 = blockIdx.y * 32;
    int tx = threadIdx.x, ty = threadIdx.y;
#pragma unroll
    for (int r = 0; r < 4; r++)
        t[ty + r*8][tx] = Wz[(size_t)(k0 + ty + r*8) * N + n0 + tx];
    __syncthreads();
#pragma unroll
    for (int r = 0; r < 4; r++) {
        int n = n0 + ty + r*8, k = k0 + tx;
        oz[(size_t)n * K + k] = __float2half(t[tx][ty + r*8]);
    }
}

// ---------------------------------------------------------------------------
// Pipelined mma.sync fp16 GEMM, single pass, 2-stage.
// MT=128: 8 warps 2Mx4N, 2 CTAs/SM.  MT=64: 8 warps 1Mx8N, 3 CTAs/SM
// (for N=768 GEMMs — doubles grid to kill wave quantization).
// ---------------------------------------------------------------------------
template<int MT>
__global__ void __launch_bounds__(256, (MT == 64) ? 3 : 2) mma_gemm(
    const __half* __restrict__ A, const __half* __restrict__ B,
    const float* __restrict__ bias, const float* __restrict__ res,
    float* __restrict__ C, __half* __restrict__ Ch,
    int M, int N, int K, int flags)
{
    constexpr int WM   = MT / 64;              // 1 or 2
    constexpr int NQ   = (MT == 128) ? 2 : 1;  // B x4-LDSMs per warp
    constexpr int NTL  = 2 * NQ;
    constexpr int NCOL = NQ * 16;
    constexpr int A_SZ = MT * 128;
    constexpr int STG  = A_SZ + 16384;

    extern __shared__ char smem[];
    uint32_t uS = smem_u32(smem);

    const int tid = threadIdx.x;
    const int wid = tid >> 5, lane = tid & 31;
    const int m0 = blockIdx.y * MT, n0 = blockIdx.x * 128;
    const int wm = wid & (WM - 1), wn = wid / WM;

    const __half* Az = A + (size_t)m0 * K;
    const __half* Bz = B + (size_t)n0 * K;

    float acc[4][NTL][4] = {};

    const int a_row = wm * 64 + (lane & 15);
    const int a_cb  = (lane >> 4) * 16;
    const int b_row = wn * NCOL + (lane & 7) + ((lane >> 4) << 3);
    const int b_cb  = ((lane >> 3) & 1) * 16;

    const int KT = K >> 6;
    {
        cpa_tile(uS,         Az, K, MT * 8, tid);
        cpa_tile(uS + A_SZ,  Bz, K, 1024,   tid);
        CP_COMMIT();
    }

    for (int kt = 0; kt < KT; kt++) {
        if (kt + 1 < KT) {
            uint32_t base = uS + ((kt + 1) & 1) * STG;
            cpa_tile(base,        Az + (kt + 1) * 64, K, MT * 8, tid);
            cpa_tile(base + A_SZ, Bz + (kt + 1) * 64, K, 1024,   tid);
            CP_COMMIT();
            CP_WAIT1();
        } else {
            CP_WAIT0();
        }
        __syncthreads();

        uint32_t bA = uS + (kt & 1) * STG;
        uint32_t bB = bA + A_SZ;

#pragma unroll
        for (int ks = 0; ks < 4; ks++) {
            uint32_t ah[4][4], bh[NQ][4];
#pragma unroll
            for (int mt = 0; mt < 4; mt++) {
                int row = a_row + mt * 16;
                uint32_t off = row * 128 + ((a_cb + ks * 32) ^ ((row & 7) << 4));
                LDSM4(ah[mt], bA + off);
            }
#pragma unroll
            for (int q = 0; q < NQ; q++) {
                int row = b_row + q * 16;
                uint32_t off = row * 128 + ((b_cb + ks * 32) ^ ((row & 7) << 4));
                LDSM4(bh[q], bB + off);
            }
#pragma unroll
            for (int mt = 0; mt < 4; mt++)
#pragma unroll
                for (int nt = 0; nt < NTL; nt++)
                    MMAH16816(acc[mt][nt], ah[mt], &bh[nt >> 1][(nt & 1) * 2]);
        }
        __syncthreads();
    }

    const int rbase = m0 + wm * 64;
#pragma unroll
    for (int mt = 0; mt < 4; mt++) {
#pragma unroll
        for (int nt = 0; nt < NTL; nt++) {
            int c = n0 + wn * NCOL + nt * 8 + (lane & 3) * 2;
            float bv0 = 0.f, bv1 = 0.f;
            if (flags & FBIAS) { bv0 = bias[c]; bv1 = bias[c + 1]; }
#pragma unroll
            for (int half = 0; half < 2; half++) {
                int r = rbase + mt * 16 + (lane >> 2) + half * 8;
                float v0 = acc[mt][nt][half * 2 + 0];
                float v1 = acc[mt][nt][half * 2 + 1];
                if (flags & FBIAS) { v0 += bv0; v1 += bv1; }
                if (flags & FGELU) {
                    v0 = 0.5f * v0 * (1.f + erff(v0 * 0.70710678118654752f));
                    v1 = 0.5f * v1 * (1.f + erff(v1 * 0.70710678118654752f));
                }
                long idx = (long)r * N + c;
                if (flags & FRES) { v0 += res[idx]; v1 += res[idx + 1]; }
                if (C) *(float2*)(C + idx) = make_float2(v0, v1);
                if (Ch) {
                    __half2 hv = __floats2half2_rn(v0, v1);
                    *(__half2*)(Ch + idx) = hv;
                }
            }
        }
    }
}

// ---------------------------------------------------------------------------
// Fused flash attention. QK bf16 hi/lo 3-pass; PV single-pass fp16.
// Double-buffered KV stages (R10/R12 structure, proven).
// ---------------------------------------------------------------------------
#define FA_SMEM 133120

__global__ void __launch_bounds__(256, 1) flash_attn(
    const __nv_bfloat16* __restrict__ Qh_, const __nv_bfloat16* __restrict__ Ql_,
    const __nv_bfloat16* __restrict__ Kh_, const __nv_bfloat16* __restrict__ Kl_,
    const __half* __restrict__ Vt_,
    const int* __restrict__ image_ids, const int* __restrict__ lengths,
    __half* __restrict__ O_)
{
    extern __shared__ char smem[];
    uint32_t uS = smem_u32(smem);
    const int tid = threadIdx.x, wid = tid >> 5, lane = tid & 31;
    const int z = blockIdx.y, b = z / 12, h = z % 12;
    const int m0 = blockIdx.x * 128;

    int* s_cmin   = (int*)(smem + 131072);
    int* s_cmax   = s_cmin + 8;
    int* s_jlist  = s_cmax + 8;
    int* s_meta   = s_jlist + 8;
    int* s_imgRow = s_meta + 8;
    int* s_imgCol = s_imgRow + 128;

    const int len = lengths[b];

    {
        int4 v = *(const int4*)(image_ids + b*1024 + wid*128 + lane*4);
        int mn = min(min(v.x, v.y), min(v.z, v.w));
        int mx = max(max(v.x, v.y), max(v.z, v.w));
#pragma unroll
        for (int o = 16; o; o >>= 1) {
            mn = min(mn, __shfl_xor_sync(0xffffffffu, mn, o));
            mx = max(mx, __shfl_xor_sync(0xffffffffu, mx, o));
        }
        if (lane == 0) { s_cmin[wid] = mn; s_cmax[wid] = mx; }
    }
    if (tid < 128) s_imgRow[tid] = image_ids[b*1024 + m0 + tid];
    __syncthreads();
    if (tid == 0) {
        int rmin = s_cmin[blockIdx.x], rmax = s_cmax[blockIdx.x];
        int nj = 0;
        for (int jb = 0; jb < 8; jb++)
            if (jb * 128 < len && s_cmax[jb] >= rmin && s_cmin[jb] <= rmax)
                s_jlist[nj++] = jb;
        s_meta[0] = nj;
    }
    __syncthreads();
    const int nj = s_meta[0];

    const size_t qoff = ((size_t)z * 1024 + m0) * 64;
    cpa_tile(uS,         Qh_ + qoff, 64, 1024, tid);
    cpa_tile(uS + 16384, Ql_ + qoff, 64, 1024, tid);

    auto prefetch = [&](int t) {
        int jb = s_jlist[t];
        int st = t & 1;
        uint32_t base = uS + 32768 + st * 49152;
        size_t koff = ((size_t)z * 1024 + jb * 128) * 64;
        cpa_tile(base,         Kh_ + koff, 64, 1024, tid);
        cpa_tile(base + 16384, Kl_ + koff, 64, 1024, tid);
        const __half* vt = Vt_ + (size_t)z * 64 * 1024 + jb * 128;
        for (int i = tid; i < 1024; i += 256) {
            int r = i >> 4, c = i & 15;
            int kc = c >> 3, cc = c & 7;
            uint32_t off = r * 128 + cc * 16;
            uint32_t sw = off ^ ((off >> 3) & 0x70);
            CPA16(base + 32768 + kc * 8192 + sw, vt + (size_t)r * 1024 + c * 8);
        }
        if (tid < 128) s_imgCol[st * 128 + tid] = image_ids[b*1024 + jb*128 + tid];
    };
    prefetch(0);
    CP_COMMIT();

    float O[8][4] = {};
    float mA = -FLT_MAX, mB = -FLT_MAX, lA = 0.f, lB = 0.f;
    uint32_t qh[4][4], ql[4][4];
    bool qloaded = false;

    const int rA = lane >> 2;
    const int imgA = s_imgRow[wid * 16 + rA];
    const int imgB = s_imgRow[wid * 16 + rA + 8];

    const int a_row = wid * 16 + (lane & 15);
    const int a_cb  = (lane >> 4) * 16;
    const int b_row_base = (lane & 7) + ((lane >> 4) << 3);
    const int b_cb  = ((lane >> 3) & 1) * 16;

    for (int t = 0; t < nj; t++) {
        if (t + 1 < nj) { prefetch(t + 1); CP_COMMIT(); CP_WAIT1(); }
        else CP_WAIT0();
        __syncthreads();

        if (!qloaded) {
            qloaded = true;
#pragma unroll
            for (int ks = 0; ks < 4; ks++) {
                uint32_t off = a_row * 128 + ((a_cb + ks * 32) ^ ((a_row & 7) << 4));
                LDSM4(qh[ks], uS + off);
                LDSM4(ql[ks], uS + 16384 + off);
            }
        }

        int st = t & 1;
        uint32_t bK  = uS + 32768 + st * 49152;
        uint32_t bKl = bK + 16384;
        uint32_t bV  = bK + 32768;
        int jb = s_jlist[t];
        int j0 = jb * 128;
        const int* imgC = s_imgCol + st * 128;

        float S[16][4] = {};
#pragma unroll
        for (int ks = 0; ks < 4; ks++) {
#pragma unroll
            for (int nb = 0; nb < 8; nb++) {
                uint32_t bh4[4], bl4[4];
                int row = nb * 16 + b_row_base;
                uint32_t off = row * 128 + ((b_cb + ks * 32) ^ ((row & 7) << 4));
                LDSM4(bh4, bK + off);
                LDSM4(bl4, bKl + off);
                MMA16816(S[2*nb],   qh[ks], bh4);
                MMA16816(S[2*nb+1], qh[ks], bh4 + 2);
                MMA16816(S[2*nb],   qh[ks], bl4);
                MMA16816(S[2*nb+1], qh[ks], bl4 + 2);
                MMA16816(S[2*nb],   ql[ks], bh4);
                MMA16816(S[2*nb+1], ql[ks], bh4 + 2);
            }
        }

        float mnA = mA, mnB = mB;
#pragma unroll
        for (int nt = 0; nt < 16; nt++) {
            int c0 = nt * 8 + (lane & 3) * 2;
            int i0 = imgC[c0], i1 = imgC[c0 + 1];
            bool v0 = (j0 + c0) < len, v1 = (j0 + c0 + 1) < len;
            if (i0 == imgA && v0) mnA = fmaxf(mnA, S[nt][0]);
            if (i1 == imgA && v1) mnA = fmaxf(mnA, S[nt][1]);
            if (i0 == imgB && v0) mnB = fmaxf(mnB, S[nt][2]);
            if (i1 == imgB && v1) mnB = fmaxf(mnB, S[nt][3]);
        }
#pragma unroll
        for (int o = 1; o <= 2; o <<= 1) {
            mnA = fmaxf(mnA, __shfl_xor_sync(0xffffffffu, mnA, o));
            mnB = fmaxf(mnB, __shfl_xor_sync(0xffffffffu, mnB, o));
        }
        float scA = __expf(mA - mnA), scB = __expf(mB - mnB);
        mA = mnA; mB = mnB;
        lA *= scA; lB *= scB;
#pragma unroll
        for (int nt = 0; nt < 16; nt++) {
            int c0 = nt * 8 + (lane & 3) * 2;
            int i0 = imgC[c0], i1 = imgC[c0 + 1];
            bool v0 = (j0 + c0) < len, v1 = (j0 + c0 + 1) < len;
            float p0 = (i0 == imgA && v0) ? __expf(S[nt][0] - mnA) : 0.f;
            float p1 = (i1 == imgA && v1) ? __expf(S[nt][1] - mnA) : 0.f;
            float p2 = (i0 == imgB && v0) ? __expf(S[nt][2] - mnB) : 0.f;
            float p3 = (i1 == imgB && v1) ? __expf(S[nt][3] - mnB) : 0.f;
            lA += p0 + p1; lB += p2 + p3;
            S[nt][0] = p0; S[nt][1] = p1; S[nt][2] = p2; S[nt][3] = p3;
        }
#pragma unroll
        for (int nt = 0; nt < 8; nt++) {
            O[nt][0] *= scA; O[nt][1] *= scA; O[nt][2] *= scB; O[nt][3] *= scB;
        }

#pragma unroll
        for (int kt = 0; kt < 8; kt++) {
            uint32_t ah4[4];
            {
                __half2 p0 = __floats2half2_rn(S[2*kt][0],   S[2*kt][1]);
                __half2 p1 = __floats2half2_rn(S[2*kt][2],   S[2*kt][3]);
                __half2 p2 = __floats2half2_rn(S[2*kt+1][0], S[2*kt+1][1]);
                __half2 p3 = __floats2half2_rn(S[2*kt+1][2], S[2*kt+1][3]);
                ah4[0] = *(uint32_t*)&p0; ah4[1] = *(uint32_t*)&p1;
                ah4[2] = *(uint32_t*)&p2; ah4[3] = *(uint32_t*)&p3;
            }
            uint32_t tb = bV + (kt >> 2) * 8192;
#pragma unroll
            for (int nb = 0; nb < 4; nb++) {
                uint32_t vh4[4];
                int row = nb * 16 + b_row_base;
                uint32_t off = row * 128 + ((b_cb + (kt & 3) * 32) ^ ((row & 7) << 4));
                LDSM4(vh4, tb + off);
                MMAH16816(O[2*nb],   ah4, vh4);
                MMAH16816(O[2*nb+1], ah4, vh4 + 2);
            }
        }
        __syncthreads();
    }

#pragma unroll
    for (int o = 1; o <= 2; o <<= 1) {
        lA += __shfl_xor_sync(0xffffffffu, lA, o);
        lB += __shfl_xor_sync(0xffffffffu, lB, o);
    }
    float iA = lA > 0.f ? 1.f / lA : 0.f;
    float iB = lB > 0.f ? 1.f / lB : 0.f;
    size_t rowA = (size_t)(b * 1024 + m0 + wid * 16 + rA);
#pragma unroll
    for (int nt = 0; nt < 8; nt++) {
        int c = nt * 8 + (lane & 3) * 2;
        size_t idx = rowA * 768 + h * 64 + c;
        *(__half2*)(O_ + idx) = __floats2half2_rn(O[nt][0] * iA, O[nt][1] * iA);
        idx = (rowA + 8) * 768 + h * 64 + c;
        *(__half2*)(O_ + idx) = __floats2half2_rn(O[nt][2] * iB, O[nt][3] * iB);
    }
}

// ---------------------------------------------------------------------------
// LayerNorm over width 768. fp32 and/or fp16 outputs. Optional pos add.
// ---------------------------------------------------------------------------
__global__ void ln_kernel(const float* __restrict__ in, const float* __restrict__ g,
                          float* __restrict__ outf, __half* __restrict__ outh,
                          const float* __restrict__ pos_h, const float* __restrict__ pos_w,
                          const int* __restrict__ ppos)
{
    int row = blockIdx.x;
    int tid = threadIdx.x;
    const float* xr = in + (size_t)row * 768;
    float v[3]; float s = 0.f, q = 0.f;
#pragma unroll
    for (int i = 0; i < 3; i++) { float t = xr[tid + i*256]; v[i] = t; s += t; q += t*t; }
#pragma unroll
    for (int o = 16; o; o >>= 1) {
        s += __shfl_xor_sync(0xffffffffu, s, o);
        q += __shfl_xor_sync(0xffffffffu, q, o);
    }
    __shared__ float shs[8], shq[8], st[2];
    int w = tid >> 5;
    if ((tid & 31) == 0) { shs[w] = s; shq[w] = q; }
    __syncthreads();
    if (tid == 0) {
        float S = 0.f, Q = 0.f;
#pragma unroll
        for (int i = 0; i < 8; i++) { S += shs[i]; Q += shq[i]; }
        float mu = S * (1.f/768.f);
        st[0] = mu;
        st[1] = rsqrtf(Q * (1.f/768.f) - mu*mu + 1e-5f);
    }
    __syncthreads();
    float mu = st[0], rs = st[1];
    int p0 = 0, p1 = 0;
    if (ppos) { p0 = ppos[row*2]; p1 = ppos[row*2 + 1]; }
#pragma unroll
    for (int i = 0; i < 3; i++) {
        int c = tid + i*256;
        float y = (v[i] - mu) * rs * g[c];
        if (ppos) y += pos_h[p0*768 + c] + pos_w[p1*768 + c];
        size_t idx = (size_t)row*768 + c;
        if (outf) outf[idx] = y;
        if (outh) outh[idx] = __float2half(y);
    }
}

// ---------------------------------------------------------------------------
// Fused QKV postprocess: q/k bf16 hi/lo, v fp16 single ([z][d][n]).
// ---------------------------------------------------------------------------
__global__ void rmsT_all(const float* __restrict__ qkv,
                         const float* __restrict__ qg, const float* __restrict__ kg,
                         __nv_bfloat16* __restrict__ qh, __nv_bfloat16* __restrict__ ql,
                         __nv_bfloat16* __restrict__ kh, __nv_bfloat16* __restrict__ kl,
                         __half* __restrict__ vt)
{
    int token = blockIdx.x;
    int b = token >> 10, n = token & 1023;
    int w = threadIdx.x >> 5, lane = threadIdx.x & 31;
    const float* base = qkv + (size_t)token * 2304 + w * 64;
    __nv_bfloat16 hh, ll;

    {
        float v0 = base[lane], v1 = base[lane + 32];
        float ss = v0*v0 + v1*v1;
#pragma unroll
        for (int o = 16; o; o >>= 1) ss += __shfl_xor_sync(0xffffffffu, ss, o);
        float inv = 8.0f / fmaxf(sqrtf(ss), 1e-12f);
        v0 *= inv * qg[w*64 + lane];
        v1 *= inv * qg[w*64 + lane + 32];
        size_t dst = ((size_t)(b*12 + w) * 1024 + n) * 64;
        split2(v0, hh, ll); qh[dst + lane] = hh;      ql[dst + lane] = ll;
        split2(v1, hh, ll); qh[dst + lane + 32] = hh; ql[dst + lane + 32] = ll;
    }
    {
        float v0 = base[768 + lane], v1 = base[768 + lane + 32];
        float ss = v0*v0 + v1*v1;
#pragma unroll
        for (int o = 16; o; o >>= 1) ss += __shfl_xor_sync(0xffffffffu, ss, o);
        float inv = 8.0f / fmaxf(sqrtf(ss), 1e-12f);
        v0 *= inv * kg[w*64 + lane];
        v1 *= inv * kg[w*64 + lane + 32];
        size_t dst = ((size_t)(b*12 + w) * 1024 + n) * 64;
        split2(v0, hh, ll); kh[dst + lane] = hh;      kl[dst + lane] = ll;
        split2(v1, hh, ll); kh[dst + lane + 32] = hh; kl[dst + lane + 32] = ll;
    }
    {
        float v0 = base[1536 + lane], v1 = base[1536 + lane + 32];
        size_t vb = ((size_t)(b*12 + w) * 64) * 1024 + n;
        vt[vb + (size_t)lane * 1024]        = __float2half(v0);
        vt[vb + (size_t)(lane + 32) * 1024] = __float2half(v1);
    }
}

// Pool-path: one launch does k-rms + v copy (fp32 outputs).
__global__ void rmsT_pool(const float* __restrict__ kv,
                          const float* __restrict__ kg,
                          float* __restrict__ kT, float* __restrict__ vT)
{
    int token = blockIdx.x;
    int b = token >> 10, n = token & 1023;
    int w = threadIdx.x >> 5, lane = threadIdx.x & 31;
    const float* base = kv + (size_t)token * 1536 + w * 64;
    {
        float v0 = base[lane], v1 = base[lane + 32];
        float ss = v0*v0 + v1*v1;
#pragma unroll
        for (int o = 16; o; o >>= 1) ss += __shfl_xor_sync(0xffffffffu, ss, o);
        float inv = 8.0f / fmaxf(sqrtf(ss), 1e-12f);
        float* dst = kT + ((size_t)(b*12 + w) * 1024 + n) * 64;
        dst[lane]      = v0 * inv * kg[w*64 + lane];
        dst[lane + 32] = v1 * inv * kg[w*64 + lane + 32];
    }
    {
        float v0 = base[768 + lane], v1 = base[768 + lane + 32];
        float* dst = vT + ((size_t)(b*12 + w) * 1024 + n) * 64;
        dst[lane] = v0; dst[lane + 32] = v1;
    }
}

// ---------------------------------------------------------------------------
// Attention pooling (192 blocks), fp32 path.
// ---------------------------------------------------------------------------
__global__ void pool_attn_kernel(const float* __restrict__ pqn, const float* __restrict__ kT,
                                 const float* __restrict__ vT, const int* __restrict__ image_ids,
                                 const int* __restrict__ lengths, float* __restrict__ out)
{
    int idx = blockIdx.x;
    int h = idx % 12, img = (idx / 12) % 4, b = idx / 48;
    int tid = threadIdx.x;
    __shared__ float q[64];
    __shared__ float p[1024];
    __shared__ float sh[8];
    __shared__ float bs[2];
    __shared__ float sred[256];
    if (tid < 64) q[tid] = pqn[h*64 + tid];
    __syncthreads();

    const float* K = kT + (size_t)(b*12 + h) * 1024 * 64;
    int len = lengths[b];
    float loc[4]; float mx = -FLT_MAX;
#pragma unroll
    for (int t = 0; t < 4; t++) {
        int j = tid + t*256;
        const float* kr = K + (size_t)j * 64;
        float dot = 0.f;
#pragma unroll
        for (int d = 0; d < 64; d++) dot += q[d] * kr[d];
        bool ok = (image_ids[b*1024 + j] == img) && (j < len);
        loc[t] = ok ? dot : -FLT_MAX;
        mx = fmaxf(mx, loc[t]);
    }
#pragma unroll
    for (int o = 16; o; o >>= 1) mx = fmaxf(mx, __shfl_xor_sync(0xffffffffu, mx, o));
    int w = tid >> 5;
    if ((tid & 31) == 0) sh[w] = mx;
    __syncthreads();
    if (tid == 0) { float mm = sh[0]; for (int i = 1; i < 8; i++) mm = fmaxf(mm, sh[i]); bs[0] = mm; }
    __syncthreads();
    mx = bs[0];
    float s = 0.f;
#pragma unroll
    for (int t = 0; t < 4; t++) {
        float e = __expf(loc[t] - mx);
        p[tid + t*256] = e;
        s += e;
    }
#pragma unroll
    for (int o = 16; o; o >>= 1) s += __shfl_xor_sync(0xffffffffu, s, o);
    if ((tid & 31) == 0) sh[w] = s;
    __syncthreads();
    if (tid == 0) { float ss = 0.f; for (int i = 0; i < 8; i++) ss += sh[i]; bs[1] = 1.f / ss; }
    __syncthreads();
    float inv = bs[1];

    const float* V = vT + (size_t)(b*12 + h) * 1024 * 64;
    int d = tid & 63, grp = tid >> 6;
    float acc = 0.f;
    for (int j = grp; j < 1024; j += 4) acc += p[j] * V[(size_t)j*64 + d];
    sred[tid] = acc;
    __syncthreads();
    if (grp == 0) {
        float r = (sred[d] + sred[d + 64]) + (sred[d + 128] + sred[d + 192]);
        out[(size_t)(b*4 + img) * 768 + h*64 + d] = r * inv;
    }
}

__global__ void rms_vec_kernel(const float* __restrict__ in, const float* __restrict__ g,
                               float* __restrict__ out)
{
    int w = threadIdx.x >> 5, lane = threadIdx.x & 31;
    float v0 = in[w*64 + lane], v1 = in[w*64 + lane + 32];
    float ss = v0*v0 + v1*v1;
#pragma unroll
    for (int o = 16; o; o >>= 1) ss += __shfl_xor_sync(0xffffffffu, ss, o);
    float inv = 8.0f / fmaxf(sqrtf(ss), 1e-12f);
    out[w*64 + lane]      = v0 * inv * g[w*64 + lane];
    out[w*64 + lane + 32] = v1 * inv * g[w*64 + lane + 32];
}

__global__ void small_gemm_kernel(const float* __restrict__ A, const float* __restrict__ W,
                                  const float* __restrict__ addvec, float* __restrict__ C,
                                  int N, int K)
{
    __shared__ float a[768];
    int row = blockIdx.y;
    for (int i = threadIdx.x; i < K; i += 256) a[i] = A[(size_t)row*K + i];
    __syncthreads();
    int n = blockIdx.x * 256 + threadIdx.x;
    if (n >= N) return;
    float acc = addvec ? addvec[n] : 0.f;
#pragma unroll 4
    for (int k = 0; k < K; k++) acc += a[k] * W[(size_t)k*N + n];
    C[(size_t)row*N + n] = acc;
}

// ---------------------------------------------------------------------------
// Host side
// ---------------------------------------------------------------------------
extern "C" void kernel_launch(void* const* d_in, const int* in_sizes, int n_in,
                              void* d_out, int out_size)
{
    (void)in_sizes; (void)n_in; (void)out_size;
    const float* patches    = (const float*)d_in[0];
    const int*   ppos       = (const int*)  d_in[1];
    const int*   image_ids  = (const int*)  d_in[2];
    const int*   lengths    = (const int*)  d_in[3];
    const float* emb_ln_g   = (const float*)d_in[4];
    const float* W_emb      = (const float*)d_in[5];
    const float* b_emb      = (const float*)d_in[6];
    const float* emb_ln2_g  = (const float*)d_in[7];
    const float* pos_h      = (const float*)d_in[8];
    const float* pos_w      = (const float*)d_in[9];
    const float* ln_attn_g  = (const float*)d_in[10];
    const float* Wq         = (const float*)d_in[11];
    const float* Wkv        = (const float*)d_in[12];
    const float* qn_g       = (const float*)d_in[13];
    const float* kn_g       = (const float*)d_in[14];
    const float* Wo         = (const float*)d_in[15];
    const float* ln_ff_g    = (const float*)d_in[16];
    const float* W1         = (const float*)d_in[17];
    const float* b1         = (const float*)d_in[18];
    const float* W2         = (const float*)d_in[19];
    const float* b2         = (const float*)d_in[20];
    const float* final_ln_g = (const float*)d_in[21];
    const float* pool_q     = (const float*)d_in[22];
    const float* pool_ln_g  = (const float*)d_in[23];
    const float* pWq        = (const float*)d_in[24];
    const float* pWkv       = (const float*)d_in[25];
    const float* p_qn_g     = (const float*)d_in[26];
    const float* p_kn_g     = (const float*)d_in[27];
    const float* pWo        = (const float*)d_in[28];
    const float* head_ln_g  = (const float*)d_in[29];
    const float* W_head     = (const float*)d_in[30];

    float *x, *qkv, *kTf, *vTf, *sm, *pattn, *pool, *pln;
    __half *xn, *tmp, *ao, *w, *vTt;
    __nv_bfloat16 *qTh, *qTl, *kTh, *kTl;
    cudaGetSymbolAddress((void**)&x,    g_x);
    cudaGetSymbolAddress((void**)&qkv,  g_qkv);
    cudaGetSymbolAddress((void**)&kTf,  g_kTf);
    cudaGetSymbolAddress((void**)&vTf,  g_vTf);
    cudaGetSymbolAddress((void**)&sm,   g_sm);
    cudaGetSymbolAddress((void**)&pattn,g_pattn);
    cudaGetSymbolAddress((void**)&pool, g_pool);
    cudaGetSymbolAddress((void**)&pln,  g_pln);
    cudaGetSymbolAddress((void**)&xn,   g_xn);
    cudaGetSymbolAddress((void**)&tmp,  g_tmp);
    cudaGetSymbolAddress((void**)&ao,   g_ao);
    cudaGetSymbolAddress((void**)&qTh,  g_qTh);
    cudaGetSymbolAddress((void**)&qTl,  g_qTl);
    cudaGetSymbolAddress((void**)&kTh,  g_kTh);
    cudaGetSymbolAddress((void**)&kTl,  g_kTl);
    cudaGetSymbolAddress((void**)&vTt,  g_vTt);
    cudaGetSymbolAddress((void**)&w,    g_w);

    constexpr int SMEM128 = 65536;   // 2 stages x (16KB A + 16KB B)
    constexpr int SMEM64  = 49152;   // 2 stages x ( 8KB A + 16KB B)
    cudaFuncSetAttribute(mma_gemm<128>, cudaFuncAttributeMaxDynamicSharedMemorySize, SMEM128);
    cudaFuncSetAttribute(mma_gemm<64>,  cudaFuncAttributeMaxDynamicSharedMemorySize, SMEM64);
    cudaFuncSetAttribute(flash_attn,    cudaFuncAttributeMaxDynamicSharedMemorySize, FA_SMEM);

    // ---- Convert + transpose weights to fp16 [N,K], family-batched ----
    dim3 wb(32, 8);
    wconv_kernel<<<dim3(DIM/32,  DIM/32,  1), wb>>>(W_emb, w + WOFF_EMB, DIM, DIM, 0, 0);
    wconv_kernel<<<dim3(DIM/32,  DIM/32,  4), wb>>>(Wq,  w + WOFF_Q(0),  DIM,  DIM,   (long)DIM*DIM,   (long)WPERL);
    wconv_kernel<<<dim3(2*DIM/32,DIM/32,  4), wb>>>(Wkv, w + WOFF_KV(0), DIM,  2*DIM, (long)DIM*2*DIM, (long)WPERL);
    wconv_kernel<<<dim3(DIM/32,  DIM/32,  4), wb>>>(Wo,  w + WOFF_O(0),  DIM,  DIM,   (long)DIM*DIM,   (long)WPERL);
    wconv_kernel<<<dim3(MLPD/32, DIM/32,  4), wb>>>(W1,  w + WOFF_W1(0), DIM,  MLPD,  (long)DIM*MLPD,  (long)WPERL);
    wconv_kernel<<<dim3(DIM/32,  MLPD/32, 4), wb>>>(W2,  w + WOFF_W2(0), MLPD, DIM,   (long)MLPD*DIM,  (long)WPERL);
    wconv_kernel<<<dim3(2*DIM/32,DIM/32,  1), wb>>>(pWkv, w + WOFF_PKV, DIM, 2*DIM, 0, 0);

    // MT=128 path (wide-N GEMMs), MT=64 path (N=768 GEMMs — full-wave)
    auto G128 = [&](const __half* a, const __half* bw,
                    const float* bias, const float* res,
                    float* C, __half* Ch, int M, int N, int K, int flags) {
        mma_gemm<128><<<dim3(N/128, M/128), 256, SMEM128>>>(a, bw, bias, res, C, Ch, M, N, K, flags);
    };
    auto G64 = [&](const __half* a, const __half* bw,
                   const float* bias, const float* res,
                   float* C, __half* Ch, int M, int N, int K, int flags) {
        mma_gemm<64><<<dim3(N/128, M/64), 256, SMEM64>>>(a, bw, bias, res, C, Ch, M, N, K, flags);
    };

    // ---- Embedding ----
    ln_kernel<<<TOKS, 256>>>(patches, emb_ln_g, nullptr, xn, nullptr, nullptr, nullptr);
    G64(xn, w + WOFF_EMB, b_emb, nullptr, x, nullptr, TOKS, DIM, DIM, FBIAS);
    ln_kernel<<<TOKS, 256>>>(x, emb_ln2_g, x, nullptr, pos_h, pos_w, ppos);

    // ---- Transformer layers ----
    for (int l = 0; l < 4; l++) {
        ln_kernel<<<TOKS, 256>>>(x, ln_attn_g + l*DIM, nullptr, xn, nullptr, nullptr, nullptr);
        G128(xn, w + WOFF_Q(l), nullptr, nullptr, qkv, nullptr, TOKS, 2304, DIM, 0);
        rmsT_all<<<TOKS, 384>>>(qkv, qn_g + l*DIM, kn_g + l*DIM, qTh, qTl, kTh, kTl, vTt);
        flash_attn<<<dim3(8, BH), 256, FA_SMEM>>>(qTh, qTl, kTh, kTl, vTt,
                                                  image_ids, lengths, ao);
        G64(ao, w + WOFF_O(l), nullptr, x, x, nullptr, TOKS, DIM, DIM, FRES);
        ln_kernel<<<TOKS, 256>>>(x, ln_ff_g + l*DIM, nullptr, xn, nullptr, nullptr, nullptr);
        G128(xn, w + WOFF_W1(l), b1 + l*MLPD, nullptr, nullptr, tmp, TOKS, MLPD, DIM, FBIAS|FGELU);
        G64(tmp, w + WOFF_W2(l), b2 + l*DIM, x, x, nullptr, TOKS, DIM, MLPD, FBIAS|FRES);
    }

    // ---- Final LN ----
    ln_kernel<<<TOKS, 256>>>(x, final_ln_g, nullptr, xn, nullptr, nullptr, nullptr);

    // ---- Attention pooling ----
    ln_kernel<<<1, 256>>>(pool_q, pool_ln_g, sm, nullptr, nullptr, nullptr, nullptr);
    small_gemm_kernel<<<dim3(3, 1), 256>>>(sm, pWq, nullptr, sm + 768, DIM, DIM);
    rms_vec_kernel<<<1, 384>>>(sm + 768, p_qn_g, sm + 1536);
    G128(xn, w + WOFF_PKV, nullptr, nullptr, qkv, nullptr, TOKS, 1536, DIM, 0);
    rmsT_pool<<<TOKS, 384>>>(qkv, p_kn_g, kTf, vTf);
    pool_attn_kernel<<<NB*IMGS*NHEAD, 256>>>(sm + 1536, kTf, vTf, image_ids, lengths, pattn);
    small_gemm_kernel<<<dim3(3, 16), 256>>>(pattn, pWo, pool_q, pool, DIM, DIM);
    ln_kernel<<<16, 256>>>(pool, head_ln_g, pln, nullptr, nullptr, nullptr, nullptr);
    small_gemm_kernel<<<dim3(4, 16), 256>>>(pln, W_head, nullptr, (float*)d_out, NCLS, DIM);
}

// round 14
// speedup vs baseline: 1.1280x; 1.0401x over previous
#include <cuda_runtime.h>
#include <cuda_bf16.h>
#include <cuda_fp16.h>
#include <math.h>
#include <float.h>
#include <stdint.h>

// ---------------------------------------------------------------------------
// Problem constants
// ---------------------------------------------------------------------------
#define NB      4
#define NTOK    1024
#define DIM     768
#define NHEAD   12
#define DHEAD   64
#define MLPD    3072
#define IMGS    4
#define NCLS    1000
#define TOKS    (NB*NTOK)
#define BH      (NB*NHEAD)

#define FBIAS 1
#define FGELU 2
#define FRES  4

#define WOFF_EMB 0ULL
#define WPERL    7077888ULL
#define WOFF_L(l)   (589824ULL + (unsigned long long)(l)*WPERL)
#define WOFF_Q(l)   (WOFF_L(l) + 0ULL)
#define WOFF_KV(l)  (WOFF_L(l) + 589824ULL)
#define WOFF_O(l)   (WOFF_L(l) + 1769472ULL)
#define WOFF_W1(l)  (WOFF_L(l) + 2359296ULL)
#define WOFF_W2(l)  (WOFF_L(l) + 4718592ULL)
#define WOFF_PKV    (589824ULL + 4ULL*WPERL)
#define WTOTAL      30081024ULL

// ---------------------------------------------------------------------------
// Device scratch
// ---------------------------------------------------------------------------
__device__ float g_x   [TOKS*DIM];
__device__ float g_qkv [TOKS*2304];
__device__ __half g_xn  [TOKS*DIM];
__device__ __half g_tmp [TOKS*MLPD];
__device__ __half g_ao  [TOKS*DIM];
__device__ __nv_bfloat16 g_qTh[BH*NTOK*DHEAD], g_qTl[BH*NTOK*DHEAD];
__device__ __nv_bfloat16 g_kTh[BH*NTOK*DHEAD], g_kTl[BH*NTOK*DHEAD];
__device__ __half g_vTt[BH*DHEAD*NTOK];
__device__ float g_kTf[BH*NTOK*DHEAD], g_vTf[BH*NTOK*DHEAD];
__device__ float g_sm  [4096];
__device__ float g_pattn[16*DIM];
__device__ float g_pool [16*DIM];
__device__ float g_pln  [16*DIM];
__device__ __half g_w[WTOTAL];

// ---------------------------------------------------------------------------
// Helpers
// ---------------------------------------------------------------------------
__device__ __forceinline__ uint32_t smem_u32(const void* p) {
    uint32_t a;
    asm("{ .reg .u64 t; cvta.to.shared.u64 t, %1; cvt.u32.u64 %0, t; }" : "=r"(a) : "l"(p));
    return a;
}

#define LDSM4(r, addr) \
    asm volatile("ldmatrix.sync.aligned.m8n8.x4.shared.b16 {%0,%1,%2,%3}, [%4];" \
        : "=r"((r)[0]), "=r"((r)[1]), "=r"((r)[2]), "=r"((r)[3]) : "r"(addr))

#define MMA16816(d, a, b) \
    asm volatile("mma.sync.aligned.m16n8k16.row.col.f32.bf16.bf16.f32 " \
        "{%0,%1,%2,%3}, {%4,%5,%6,%7}, {%8,%9}, {%0,%1,%2,%3};" \
        : "+f"((d)[0]), "+f"((d)[1]), "+f"((d)[2]), "+f"((d)[3]) \
        : "r"((a)[0]), "r"((a)[1]), "r"((a)[2]), "r"((a)[3]), "r"((b)[0]), "r"((b)[1]))

#define MMAH16816(d, a, b) \
    asm volatile("mma.sync.aligned.m16n8k16.row.col.f32.f16.f16.f32 " \
        "{%0,%1,%2,%3}, {%4,%5,%6,%7}, {%8,%9}, {%0,%1,%2,%3};" \
        : "+f"((d)[0]), "+f"((d)[1]), "+f"((d)[2]), "+f"((d)[3]) \
        : "r"((a)[0]), "r"((a)[1]), "r"((a)[2]), "r"((a)[3]), "r"((b)[0]), "r"((b)[1]))

#define CPA16(dst, src) \
    asm volatile("cp.async.cg.shared.global [%0], [%1], 16;" :: "r"(dst), "l"(src))
#define CP_COMMIT() asm volatile("cp.async.commit_group;" ::: "memory")
#define CP_WAIT0()  asm volatile("cp.async.wait_group 0;" ::: "memory")
#define CP_WAIT1()  asm volatile("cp.async.wait_group 1;" ::: "memory")

__device__ __forceinline__ void split2(float v, __nv_bfloat16& h, __nv_bfloat16& l) {
    h = __float2bfloat16(v);
    l = __float2bfloat16(v - __bfloat162float(h));
}
__device__ __forceinline__ uint32_t bfu(__nv_bfloat16 b) { return (uint32_t)__bfloat16_as_ushort(b); }

template<typename T>
__device__ __forceinline__ void cpa_tile(uint32_t smbase, const T* __restrict__ g,
                                         int ldk, int chunks, int tid)
{
    for (int i = tid; i < chunks; i += 256) {
        int r = i >> 3, c = i & 7;
        uint32_t off = r * 128 + c * 16;
        uint32_t sw = off ^ ((off >> 3) & 0x70);
        CPA16(smbase + sw, g + (size_t)r * ldk + c * 8);
    }
}

// ---------------------------------------------------------------------------
// Weight convert+transpose, family-batched: z = layer.
// ---------------------------------------------------------------------------
__global__ void wconv_kernel(const float* __restrict__ W, __half* __restrict__ out,
                             int K, int N, long srcStride, long dstStride)
{
    __shared__ float t[32][33];
    int z = blockIdx.z;
    const float* Wz = W + (size_t)z * srcStride;
    __half* oz = out + (size_t)z * dstStride;
    int n0 = blockIdx.x * 32, k0 = blockIdx.y * 32;
    int tx = threadIdx.x, ty = threadIdx.y;
#pragma unroll
    for (int r = 0; r < 4; r++)
        t[ty + r*8][tx] = Wz[(size_t)(k0 + ty + r*8) * N + n0 + tx];
    __syncthreads();
#pragma unroll
    for (int r = 0; r < 4; r++) {
        int n = n0 + ty + r*8, k = k0 + tx;
        oz[(size_t)n * K + k] = __float2half(t[tx][ty + r*8]);
    }
}

// ---------------------------------------------------------------------------
// Pipelined mma.sync fp16 GEMM, single pass, 2-stage.
// MT=128: 8 warps 2Mx4N, 2 CTAs/SM.  MT=64: 8 warps 1Mx8N, 3 CTAs/SM.
// ---------------------------------------------------------------------------
template<int MT>
__global__ void __launch_bounds__(256, (MT == 64) ? 3 : 2) mma_gemm(
    const __half* __restrict__ A, const __half* __restrict__ B,
    const float* __restrict__ bias, const float* __restrict__ res,
    float* __restrict__ C, __half* __restrict__ Ch,
    int M, int N, int K, int flags)
{
    constexpr int WM   = MT / 64;
    constexpr int NQ   = (MT == 128) ? 2 : 1;
    constexpr int NTL  = 2 * NQ;
    constexpr int NCOL = NQ * 16;
    constexpr int A_SZ = MT * 128;
    constexpr int STG  = A_SZ + 16384;

    extern __shared__ char smem[];
    uint32_t uS = smem_u32(smem);

    const int tid = threadIdx.x;
    const int wid = tid >> 5, lane = tid & 31;
    const int m0 = blockIdx.y * MT, n0 = blockIdx.x * 128;
    const int wm = wid & (WM - 1), wn = wid / WM;

    const __half* Az = A + (size_t)m0 * K;
    const __half* Bz = B + (size_t)n0 * K;

    float acc[4][NTL][4] = {};

    const int a_row = wm * 64 + (lane & 15);
    const int a_cb  = (lane >> 4) * 16;
    const int b_row = wn * NCOL + (lane & 7) + ((lane >> 4) << 3);
    const int b_cb  = ((lane >> 3) & 1) * 16;

    const int KT = K >> 6;
    {
        cpa_tile(uS,         Az, K, MT * 8, tid);
        cpa_tile(uS + A_SZ,  Bz, K, 1024,   tid);
        CP_COMMIT();
    }

    for (int kt = 0; kt < KT; kt++) {
        if (kt + 1 < KT) {
            uint32_t base = uS + ((kt + 1) & 1) * STG;
            cpa_tile(base,        Az + (kt + 1) * 64, K, MT * 8, tid);
            cpa_tile(base + A_SZ, Bz + (kt + 1) * 64, K, 1024,   tid);
            CP_COMMIT();
            CP_WAIT1();
        } else {
            CP_WAIT0();
        }
        __syncthreads();

        uint32_t bA = uS + (kt & 1) * STG;
        uint32_t bB = bA + A_SZ;

#pragma unroll
        for (int ks = 0; ks < 4; ks++) {
            uint32_t ah[4][4], bh[NQ][4];
#pragma unroll
            for (int mt = 0; mt < 4; mt++) {
                int row = a_row + mt * 16;
                uint32_t off = row * 128 + ((a_cb + ks * 32) ^ ((row & 7) << 4));
                LDSM4(ah[mt], bA + off);
            }
#pragma unroll
            for (int q = 0; q < NQ; q++) {
                int row = b_row + q * 16;
                uint32_t off = row * 128 + ((b_cb + ks * 32) ^ ((row & 7) << 4));
                LDSM4(bh[q], bB + off);
            }
#pragma unroll
            for (int mt = 0; mt < 4; mt++)
#pragma unroll
                for (int nt = 0; nt < NTL; nt++)
                    MMAH16816(acc[mt][nt], ah[mt], &bh[nt >> 1][(nt & 1) * 2]);
        }
        __syncthreads();
    }

    const int rbase = m0 + wm * 64;
#pragma unroll
    for (int mt = 0; mt < 4; mt++) {
#pragma unroll
        for (int nt = 0; nt < NTL; nt++) {
            int c = n0 + wn * NCOL + nt * 8 + (lane & 3) * 2;
            float bv0 = 0.f, bv1 = 0.f;
            if (flags & FBIAS) { bv0 = bias[c]; bv1 = bias[c + 1]; }
#pragma unroll
            for (int half = 0; half < 2; half++) {
                int r = rbase + mt * 16 + (lane >> 2) + half * 8;
                float v0 = acc[mt][nt][half * 2 + 0];
                float v1 = acc[mt][nt][half * 2 + 1];
                if (flags & FBIAS) { v0 += bv0; v1 += bv1; }
                if (flags & FGELU) {
                    v0 = 0.5f * v0 * (1.f + erff(v0 * 0.70710678118654752f));
                    v1 = 0.5f * v1 * (1.f + erff(v1 * 0.70710678118654752f));
                }
                long idx = (long)r * N + c;
                if (flags & FRES) { v0 += res[idx]; v1 += res[idx + 1]; }
                if (C) *(float2*)(C + idx) = make_float2(v0, v1);
                if (Ch) {
                    __half2 hv = __floats2half2_rn(v0, v1);
                    *(__half2*)(Ch + idx) = hv;
                }
            }
        }
    }
}

// ---------------------------------------------------------------------------
// Fused flash attention. QK bf16 hi/lo 3-pass; PV single-pass fp16.
// Mask folded into S once; max pass unconditional; exp guarded by float cmp.
// ---------------------------------------------------------------------------
#define FA_SMEM 133120
#define NEGBIG  -1e30f

__global__ void __launch_bounds__(256, 1) flash_attn(
    const __nv_bfloat16* __restrict__ Qh_, const __nv_bfloat16* __restrict__ Ql_,
    const __nv_bfloat16* __restrict__ Kh_, const __nv_bfloat16* __restrict__ Kl_,
    const __half* __restrict__ Vt_,
    const int* __restrict__ image_ids, const int* __restrict__ lengths,
    __half* __restrict__ O_)
{
    extern __shared__ char smem[];
    uint32_t uS = smem_u32(smem);
    const int tid = threadIdx.x, wid = tid >> 5, lane = tid & 31;
    const int z = blockIdx.y, b = z / 12, h = z % 12;
    const int m0 = blockIdx.x * 128;

    int* s_cmin   = (int*)(smem + 131072);
    int* s_cmax   = s_cmin + 8;
    int* s_jlist  = s_cmax + 8;
    int* s_meta   = s_jlist + 8;
    int* s_imgRow = s_meta + 8;
    int* s_imgCol = s_imgRow + 128;

    const int len = lengths[b];

    {
        int4 v = *(const int4*)(image_ids + b*1024 + wid*128 + lane*4);
        int mn = min(min(v.x, v.y), min(v.z, v.w));
        int mx = max(max(v.x, v.y), max(v.z, v.w));
#pragma unroll
        for (int o = 16; o; o >>= 1) {
            mn = min(mn, __shfl_xor_sync(0xffffffffu, mn, o));
            mx = max(mx, __shfl_xor_sync(0xffffffffu, mx, o));
        }
        if (lane == 0) { s_cmin[wid] = mn; s_cmax[wid] = mx; }
    }
    if (tid < 128) s_imgRow[tid] = image_ids[b*1024 + m0 + tid];
    __syncthreads();
    if (tid == 0) {
        int rmin = s_cmin[blockIdx.x], rmax = s_cmax[blockIdx.x];
        int nj = 0;
        for (int jb = 0; jb < 8; jb++)
            if (jb * 128 < len && s_cmax[jb] >= rmin && s_cmin[jb] <= rmax)
                s_jlist[nj++] = jb;
        s_meta[0] = nj;
    }
    __syncthreads();
    const int nj = s_meta[0];

    const size_t qoff = ((size_t)z * 1024 + m0) * 64;
    cpa_tile(uS,         Qh_ + qoff, 64, 1024, tid);
    cpa_tile(uS + 16384, Ql_ + qoff, 64, 1024, tid);

    auto prefetch = [&](int t) {
        int jb = s_jlist[t];
        int st = t & 1;
        uint32_t base = uS + 32768 + st * 49152;
        size_t koff = ((size_t)z * 1024 + jb * 128) * 64;
        cpa_tile(base,         Kh_ + koff, 64, 1024, tid);
        cpa_tile(base + 16384, Kl_ + koff, 64, 1024, tid);
        const __half* vt = Vt_ + (size_t)z * 64 * 1024 + jb * 128;
        for (int i = tid; i < 1024; i += 256) {
            int r = i >> 4, c = i & 15;
            int kc = c >> 3, cc = c & 7;
            uint32_t off = r * 128 + cc * 16;
            uint32_t sw = off ^ ((off >> 3) & 0x70);
            CPA16(base + 32768 + kc * 8192 + sw, vt + (size_t)r * 1024 + c * 8);
        }
        if (tid < 128) s_imgCol[st * 128 + tid] = image_ids[b*1024 + jb*128 + tid];
    };
    prefetch(0);
    CP_COMMIT();

    float O[8][4] = {};
    float mA = -FLT_MAX, mB = -FLT_MAX, lA = 0.f, lB = 0.f;
    uint32_t qh[4][4], ql[4][4];
    bool qloaded = false;

    const int rA = lane >> 2;
    const int imgA = s_imgRow[wid * 16 + rA];
    const int imgB = s_imgRow[wid * 16 + rA + 8];

    const int a_row = wid * 16 + (lane & 15);
    const int a_cb  = (lane >> 4) * 16;
    const int b_row_base = (lane & 7) + ((lane >> 4) << 3);
    const int b_cb  = ((lane >> 3) & 1) * 16;

    for (int t = 0; t < nj; t++) {
        if (t + 1 < nj) { prefetch(t + 1); CP_COMMIT(); CP_WAIT1(); }
        else CP_WAIT0();
        __syncthreads();

        if (!qloaded) {
            qloaded = true;
#pragma unroll
            for (int ks = 0; ks < 4; ks++) {
                uint32_t off = a_row * 128 + ((a_cb + ks * 32) ^ ((a_row & 7) << 4));
                LDSM4(qh[ks], uS + off);
                LDSM4(ql[ks], uS + 16384 + off);
            }
        }

        int st = t & 1;
        uint32_t bK  = uS + 32768 + st * 49152;
        uint32_t bKl = bK + 16384;
        uint32_t bV  = bK + 32768;
        int jb = s_jlist[t];
        int j0 = jb * 128;
        const int* imgC = s_imgCol + st * 128;

        float S[16][4] = {};
#pragma unroll
        for (int ks = 0; ks < 4; ks++) {
#pragma unroll
            for (int nb = 0; nb < 8; nb++) {
                uint32_t bh4[4], bl4[4];
                int row = nb * 16 + b_row_base;
                uint32_t off = row * 128 + ((b_cb + ks * 32) ^ ((row & 7) << 4));
                LDSM4(bh4, bK + off);
                LDSM4(bl4, bKl + off);
                MMA16816(S[2*nb],   qh[ks], bh4);
                MMA16816(S[2*nb+1], qh[ks], bh4 + 2);
                MMA16816(S[2*nb],   qh[ks], bl4);
                MMA16816(S[2*nb+1], qh[ks], bl4 + 2);
                MMA16816(S[2*nb],   ql[ks], bh4);
                MMA16816(S[2*nb+1], ql[ks], bh4 + 2);
            }
        }

        // ---- fold mask into S (once) ----
#pragma unroll
        for (int nt = 0; nt < 16; nt++) {
            int c0 = nt * 8 + (lane & 3) * 2;
            int i0 = imgC[c0], i1 = imgC[c0 + 1];
            bool v0 = (j0 + c0) < len, v1 = (j0 + c0 + 1) < len;
            if (!(i0 == imgA && v0)) S[nt][0] = NEGBIG;
            if (!(i1 == imgA && v1)) S[nt][1] = NEGBIG;
            if (!(i0 == imgB && v0)) S[nt][2] = NEGBIG;
            if (!(i1 == imgB && v1)) S[nt][3] = NEGBIG;
        }
        // ---- unconditional max ----
        float mnA = mA, mnB = mB;
#pragma unroll
        for (int nt = 0; nt < 16; nt++) {
            mnA = fmaxf(mnA, fmaxf(S[nt][0], S[nt][1]));
            mnB = fmaxf(mnB, fmaxf(S[nt][2], S[nt][3]));
        }
#pragma unroll
        for (int o = 1; o <= 2; o <<= 1) {
            mnA = fmaxf(mnA, __shfl_xor_sync(0xffffffffu, mnA, o));
            mnB = fmaxf(mnB, __shfl_xor_sync(0xffffffffu, mnB, o));
        }
        float scA = __expf(mA - mnA), scB = __expf(mB - mnB);
        mA = mnA; mB = mnB;
        lA *= scA; lB *= scB;
        // ---- exp with float-compare guard ----
#pragma unroll
        for (int nt = 0; nt < 16; nt++) {
            float p0 = (S[nt][0] > -1e29f) ? __expf(S[nt][0] - mnA) : 0.f;
            float p1 = (S[nt][1] > -1e29f) ? __expf(S[nt][1] - mnA) : 0.f;
            float p2 = (S[nt][2] > -1e29f) ? __expf(S[nt][2] - mnB) : 0.f;
            float p3 = (S[nt][3] > -1e29f) ? __expf(S[nt][3] - mnB) : 0.f;
            lA += p0 + p1; lB += p2 + p3;
            S[nt][0] = p0; S[nt][1] = p1; S[nt][2] = p2; S[nt][3] = p3;
        }
#pragma unroll
        for (int nt = 0; nt < 8; nt++) {
            O[nt][0] *= scA; O[nt][1] *= scA; O[nt][2] *= scB; O[nt][3] *= scB;
        }

#pragma unroll
        for (int kt = 0; kt < 8; kt++) {
            uint32_t ah4[4];
            {
                __half2 p0 = __floats2half2_rn(S[2*kt][0],   S[2*kt][1]);
                __half2 p1 = __floats2half2_rn(S[2*kt][2],   S[2*kt][3]);
                __half2 p2 = __floats2half2_rn(S[2*kt+1][0], S[2*kt+1][1]);
                __half2 p3 = __floats2half2_rn(S[2*kt+1][2], S[2*kt+1][3]);
                ah4[0] = *(uint32_t*)&p0; ah4[1] = *(uint32_t*)&p1;
                ah4[2] = *(uint32_t*)&p2; ah4[3] = *(uint32_t*)&p3;
            }
            uint32_t tb = bV + (kt >> 2) * 8192;
#pragma unroll
            for (int nb = 0; nb < 4; nb++) {
                uint32_t vh4[4];
                int row = nb * 16 + b_row_base;
                uint32_t off = row * 128 + ((b_cb + (kt & 3) * 32) ^ ((row & 7) << 4));
                LDSM4(vh4, tb + off);
                MMAH16816(O[2*nb],   ah4, vh4);
                MMAH16816(O[2*nb+1], ah4, vh4 + 2);
            }
        }
        __syncthreads();
    }

#pragma unroll
    for (int o = 1; o <= 2; o <<= 1) {
        lA += __shfl_xor_sync(0xffffffffu, lA, o);
        lB += __shfl_xor_sync(0xffffffffu, lB, o);
    }
    float iA = lA > 0.f ? 1.f / lA : 0.f;
    float iB = lB > 0.f ? 1.f / lB : 0.f;
    size_t rowA = (size_t)(b * 1024 + m0 + wid * 16 + rA);
#pragma unroll
    for (int nt = 0; nt < 8; nt++) {
        int c = nt * 8 + (lane & 3) * 2;
        size_t idx = rowA * 768 + h * 64 + c;
        *(__half2*)(O_ + idx) = __floats2half2_rn(O[nt][0] * iA, O[nt][1] * iA);
        idx = (rowA + 8) * 768 + h * 64 + c;
        *(__half2*)(O_ + idx) = __floats2half2_rn(O[nt][2] * iB, O[nt][3] * iB);
    }
}

// ---------------------------------------------------------------------------
// LayerNorm over width 768. fp32 and/or fp16 outputs. Optional pos add.
// ---------------------------------------------------------------------------
__global__ void ln_kernel(const float* __restrict__ in, const float* __restrict__ g,
                          float* __restrict__ outf, __half* __restrict__ outh,
                          const float* __restrict__ pos_h, const float* __restrict__ pos_w,
                          const int* __restrict__ ppos)
{
    int row = blockIdx.x;
    int tid = threadIdx.x;
    const float* xr = in + (size_t)row * 768;
    float v[3]; float s = 0.f, q = 0.f;
#pragma unroll
    for (int i = 0; i < 3; i++) { float t = xr[tid + i*256]; v[i] = t; s += t; q += t*t; }
#pragma unroll
    for (int o = 16; o; o >>= 1) {
        s += __shfl_xor_sync(0xffffffffu, s, o);
        q += __shfl_xor_sync(0xffffffffu, q, o);
    }
    __shared__ float shs[8], shq[8], st[2];
    int w = tid >> 5;
    if ((tid & 31) == 0) { shs[w] = s; shq[w] = q; }
    __syncthreads();
    if (tid == 0) {
        float S = 0.f, Q = 0.f;
#pragma unroll
        for (int i = 0; i < 8; i++) { S += shs[i]; Q += shq[i]; }
        float mu = S * (1.f/768.f);
        st[0] = mu;
        st[1] = rsqrtf(Q * (1.f/768.f) - mu*mu + 1e-5f);
    }
    __syncthreads();
    float mu = st[0], rs = st[1];
    int p0 = 0, p1 = 0;
    if (ppos) { p0 = ppos[row*2]; p1 = ppos[row*2 + 1]; }
#pragma unroll
    for (int i = 0; i < 3; i++) {
        int c = tid + i*256;
        float y = (v[i] - mu) * rs * g[c];
        if (ppos) y += pos_h[p0*768 + c] + pos_w[p1*768 + c];
        size_t idx = (size_t)row*768 + c;
        if (outf) outf[idx] = y;
        if (outh) outh[idx] = __float2half(y);
    }
}

// ---------------------------------------------------------------------------
// Fused QKV postprocess: 2 tokens per block (better ILP, half2 V stores).
// q/k bf16 hi/lo [z][n][64]; v fp16 [z][d][n].
// ---------------------------------------------------------------------------
__global__ void rmsT_all(const float* __restrict__ qkv,
                         const float* __restrict__ qg, const float* __restrict__ kg,
                         __nv_bfloat16* __restrict__ qh, __nv_bfloat16* __restrict__ ql,
                         __nv_bfloat16* __restrict__ kh, __nv_bfloat16* __restrict__ kl,
                         __half* __restrict__ vt)
{
    int t0 = blockIdx.x * 2;
    int b = t0 >> 10, n0 = t0 & 1023;
    int w = threadIdx.x >> 5, lane = threadIdx.x & 31;
    const float* base0 = qkv + (size_t)t0 * 2304 + w * 64;
    const float* base1 = base0 + 2304;
    __nv_bfloat16 hh, ll;

    // Q (both tokens)
    {
        float a0 = base0[lane], a1 = base0[lane + 32];
        float b0 = base1[lane], b1 = base1[lane + 32];
        float s0 = a0*a0 + a1*a1, s1 = b0*b0 + b1*b1;
#pragma unroll
        for (int o = 16; o; o >>= 1) {
            s0 += __shfl_xor_sync(0xffffffffu, s0, o);
            s1 += __shfl_xor_sync(0xffffffffu, s1, o);
        }
        float i0 = 8.0f / fmaxf(sqrtf(s0), 1e-12f);
        float i1 = 8.0f / fmaxf(sqrtf(s1), 1e-12f);
        float g0 = qg[w*64 + lane], g1 = qg[w*64 + lane + 32];
        size_t d0 = ((size_t)(b*12 + w) * 1024 + n0) * 64;
        split2(a0 * i0 * g0, hh, ll); qh[d0 + lane] = hh;      ql[d0 + lane] = ll;
        split2(a1 * i0 * g1, hh, ll); qh[d0 + lane + 32] = hh; ql[d0 + lane + 32] = ll;
        split2(b0 * i1 * g0, hh, ll); qh[d0 + 64 + lane] = hh;      ql[d0 + 64 + lane] = ll;
        split2(b1 * i1 * g1, hh, ll); qh[d0 + 64 + lane + 32] = hh; ql[d0 + 64 + lane + 32] = ll;
    }
    // K (both tokens)
    {
        float a0 = base0[768 + lane], a1 = base0[768 + lane + 32];
        float b0 = base1[768 + lane], b1 = base1[768 + lane + 32];
        float s0 = a0*a0 + a1*a1, s1 = b0*b0 + b1*b1;
#pragma unroll
        for (int o = 16; o; o >>= 1) {
            s0 += __shfl_xor_sync(0xffffffffu, s0, o);
            s1 += __shfl_xor_sync(0xffffffffu, s1, o);
        }
        float i0 = 8.0f / fmaxf(sqrtf(s0), 1e-12f);
        float i1 = 8.0f / fmaxf(sqrtf(s1), 1e-12f);
        float g0 = kg[w*64 + lane], g1 = kg[w*64 + lane + 32];
        size_t d0 = ((size_t)(b*12 + w) * 1024 + n0) * 64;
        split2(a0 * i0 * g0, hh, ll); kh[d0 + lane] = hh;      kl[d0 + lane] = ll;
        split2(a1 * i0 * g1, hh, ll); kh[d0 + lane + 32] = hh; kl[d0 + lane + 32] = ll;
        split2(b0 * i1 * g0, hh, ll); kh[d0 + 64 + lane] = hh;      kl[d0 + 64 + lane] = ll;
        split2(b1 * i1 * g1, hh, ll); kh[d0 + 64 + lane + 32] = hh; kl[d0 + 64 + lane + 32] = ll;
    }
    // V (both tokens, half2 store per dim)
    {
        float a0 = base0[1536 + lane], a1 = base0[1536 + lane + 32];
        float b0 = base1[1536 + lane], b1 = base1[1536 + lane + 32];
        size_t vb = ((size_t)(b*12 + w) * 64) * 1024 + n0;
        *(__half2*)(vt + vb + (size_t)lane * 1024)        = __floats2half2_rn(a0, b0);
        *(__half2*)(vt + vb + (size_t)(lane + 32) * 1024) = __floats2half2_rn(a1, b1);
    }
}

// Pool-path: one launch does k-rms + v copy (fp32 outputs).
__global__ void rmsT_pool(const float* __restrict__ kv,
                          const float* __restrict__ kg,
                          float* __restrict__ kT, float* __restrict__ vT)
{
    int token = blockIdx.x;
    int b = token >> 10, n = token & 1023;
    int w = threadIdx.x >> 5, lane = threadIdx.x & 31;
    const float* base = kv + (size_t)token * 1536 + w * 64;
    {
        float v0 = base[lane], v1 = base[lane + 32];
        float ss = v0*v0 + v1*v1;
#pragma unroll
        for (int o = 16; o; o >>= 1) ss += __shfl_xor_sync(0xffffffffu, ss, o);
        float inv = 8.0f / fmaxf(sqrtf(ss), 1e-12f);
        float* dst = kT + ((size_t)(b*12 + w) * 1024 + n) * 64;
        dst[lane]      = v0 * inv * kg[w*64 + lane];
        dst[lane + 32] = v1 * inv * kg[w*64 + lane + 32];
    }
    {
        float v0 = base[768 + lane], v1 = base[768 + lane + 32];
        float* dst = vT + ((size_t)(b*12 + w) * 1024 + n) * 64;
        dst[lane] = v0; dst[lane + 32] = v1;
    }
}

// ---------------------------------------------------------------------------
// Attention pooling (192 blocks), fp32 path.
// ---------------------------------------------------------------------------
__global__ void pool_attn_kernel(const float* __restrict__ pqn, const float* __restrict__ kT,
                                 const float* __restrict__ vT, const int* __restrict__ image_ids,
                                 const int* __restrict__ lengths, float* __restrict__ out)
{
    int idx = blockIdx.x;
    int h = idx % 12, img = (idx / 12) % 4, b = idx / 48;
    int tid = threadIdx.x;
    __shared__ float q[64];
    __shared__ float p[1024];
    __shared__ float sh[8];
    __shared__ float bs[2];
    __shared__ float sred[256];
    if (tid < 64) q[tid] = pqn[h*64 + tid];
    __syncthreads();

    const float* K = kT + (size_t)(b*12 + h) * 1024 * 64;
    int len = lengths[b];
    float loc[4]; float mx = -FLT_MAX;
#pragma unroll
    for (int t = 0; t < 4; t++) {
        int j = tid + t*256;
        const float* kr = K + (size_t)j * 64;
        float dot = 0.f;
#pragma unroll
        for (int d = 0; d < 64; d++) dot += q[d] * kr[d];
        bool ok = (image_ids[b*1024 + j] == img) && (j < len);
        loc[t] = ok ? dot : -FLT_MAX;
        mx = fmaxf(mx, loc[t]);
    }
#pragma unroll
    for (int o = 16; o; o >>= 1) mx = fmaxf(mx, __shfl_xor_sync(0xffffffffu, mx, o));
    int w = tid >> 5;
    if ((tid & 31) == 0) sh[w] = mx;
    __syncthreads();
    if (tid == 0) { float mm = sh[0]; for (int i = 1; i < 8; i++) mm = fmaxf(mm, sh[i]); bs[0] = mm; }
    __syncthreads();
    mx = bs[0];
    float s = 0.f;
#pragma unroll
    for (int t = 0; t < 4; t++) {
        float e = __expf(loc[t] - mx);
        p[tid + t*256] = e;
        s += e;
    }
#pragma unroll
    for (int o = 16; o; o >>= 1) s += __shfl_xor_sync(0xffffffffu, s, o);
    if ((tid & 31) == 0) sh[w] = s;
    __syncthreads();
    if (tid == 0) { float ss = 0.f; for (int i = 0; i < 8; i++) ss += sh[i]; bs[1] = 1.f / ss; }
    __syncthreads();
    float inv = bs[1];

    const float* V = vT + (size_t)(b*12 + h) * 1024 * 64;
    int d = tid & 63, grp = tid >> 6;
    float acc = 0.f;
    for (int j = grp; j < 1024; j += 4) acc += p[j] * V[(size_t)j*64 + d];
    sred[tid] = acc;
    __syncthreads();
    if (grp == 0) {
        float r = (sred[d] + sred[d + 64]) + (sred[d + 128] + sred[d + 192]);
        out[(size_t)(b*4 + img) * 768 + h*64 + d] = r * inv;
    }
}

__global__ void rms_vec_kernel(const float* __restrict__ in, const float* __restrict__ g,
                               float* __restrict__ out)
{
    int w = threadIdx.x >> 5, lane = threadIdx.x & 31;
    float v0 = in[w*64 + lane], v1 = in[w*64 + lane + 32];
    float ss = v0*v0 + v1*v1;
#pragma unroll
    for (int o = 16; o; o >>= 1) ss += __shfl_xor_sync(0xffffffffu, ss, o);
    float inv = 8.0f / fmaxf(sqrtf(ss), 1e-12f);
    out[w*64 + lane]      = v0 * inv * g[w*64 + lane];
    out[w*64 + lane + 32] = v1 * inv * g[w*64 + lane + 32];
}

__global__ void small_gemm_kernel(const float* __restrict__ A, const float* __restrict__ W,
                                  const float* __restrict__ addvec, float* __restrict__ C,
                                  int N, int K)
{
    __shared__ float a[768];
    int row = blockIdx.y;
    for (int i = threadIdx.x; i < K; i += 256) a[i] = A[(size_t)row*K + i];
    __syncthreads();
    int n = blockIdx.x * 256 + threadIdx.x;
    if (n >= N) return;
    float acc = addvec ? addvec[n] : 0.f;
#pragma unroll 4
    for (int k = 0; k < K; k++) acc += a[k] * W[(size_t)k*N + n];
    C[(size_t)row*N + n] = acc;
}

// ---------------------------------------------------------------------------
// Host side
// ---------------------------------------------------------------------------
extern "C" void kernel_launch(void* const* d_in, const int* in_sizes, int n_in,
                              void* d_out, int out_size)
{
    (void)in_sizes; (void)n_in; (void)out_size;
    const float* patches    = (const float*)d_in[0];
    const int*   ppos       = (const int*)  d_in[1];
    const int*   image_ids  = (const int*)  d_in[2];
    const int*   lengths    = (const int*)  d_in[3];
    const float* emb_ln_g   = (const float*)d_in[4];
    const float* W_emb      = (const float*)d_in[5];
    const float* b_emb      = (const float*)d_in[6];
    const float* emb_ln2_g  = (const float*)d_in[7];
    const float* pos_h      = (const float*)d_in[8];
    const float* pos_w      = (const float*)d_in[9];
    const float* ln_attn_g  = (const float*)d_in[10];
    const float* Wq         = (const float*)d_in[11];
    const float* Wkv        = (const float*)d_in[12];
    const float* qn_g       = (const float*)d_in[13];
    const float* kn_g       = (const float*)d_in[14];
    const float* Wo         = (const float*)d_in[15];
    const float* ln_ff_g    = (const float*)d_in[16];
    const float* W1         = (const float*)d_in[17];
    const float* b1         = (const float*)d_in[18];
    const float* W2         = (const float*)d_in[19];
    const float* b2         = (const float*)d_in[20];
    const float* final_ln_g = (const float*)d_in[21];
    const float* pool_q     = (const float*)d_in[22];
    const float* pool_ln_g  = (const float*)d_in[23];
    const float* pWq        = (const float*)d_in[24];
    const float* pWkv       = (const float*)d_in[25];
    const float* p_qn_g     = (const float*)d_in[26];
    const float* p_kn_g     = (const float*)d_in[27];
    const float* pWo        = (const float*)d_in[28];
    const float* head_ln_g  = (const float*)d_in[29];
    const float* W_head     = (const float*)d_in[30];

    float *x, *qkv, *kTf, *vTf, *sm, *pattn, *pool, *pln;
    __half *xn, *tmp, *ao, *w, *vTt;
    __nv_bfloat16 *qTh, *qTl, *kTh, *kTl;
    cudaGetSymbolAddress((void**)&x,    g_x);
    cudaGetSymbolAddress((void**)&qkv,  g_qkv);
    cudaGetSymbolAddress((void**)&kTf,  g_kTf);
    cudaGetSymbolAddress((void**)&vTf,  g_vTf);
    cudaGetSymbolAddress((void**)&sm,   g_sm);
    cudaGetSymbolAddress((void**)&pattn,g_pattn);
    cudaGetSymbolAddress((void**)&pool, g_pool);
    cudaGetSymbolAddress((void**)&pln,  g_pln);
    cudaGetSymbolAddress((void**)&xn,   g_xn);
    cudaGetSymbolAddress((void**)&tmp,  g_tmp);
    cudaGetSymbolAddress((void**)&ao,   g_ao);
    cudaGetSymbolAddress((void**)&qTh,  g_qTh);
    cudaGetSymbolAddress((void**)&qTl,  g_qTl);
    cudaGetSymbolAddress((void**)&kTh,  g_kTh);
    cudaGetSymbolAddress((void**)&kTl,  g_kTl);
    cudaGetSymbolAddress((void**)&vTt,  g_vTt);
    cudaGetSymbolAddress((void**)&w,    g_w);

    constexpr int SMEM128 = 65536;
    constexpr int SMEM64  = 49152;
    cudaFuncSetAttribute(mma_gemm<128>, cudaFuncAttributeMaxDynamicSharedMemorySize, SMEM128);
    cudaFuncSetAttribute(mma_gemm<64>,  cudaFuncAttributeMaxDynamicSharedMemorySize, SMEM64);
    cudaFuncSetAttribute(flash_attn,    cudaFuncAttributeMaxDynamicSharedMemorySize, FA_SMEM);

    // ---- Convert + transpose weights to fp16 [N,K], family-batched ----
    dim3 wb(32, 8);
    wconv_kernel<<<dim3(DIM/32,  DIM/32,  1), wb>>>(W_emb, w + WOFF_EMB, DIM, DIM, 0, 0);
    wconv_kernel<<<dim3(DIM/32,  DIM/32,  4), wb>>>(Wq,  w + WOFF_Q(0),  DIM,  DIM,   (long)DIM*DIM,   (long)WPERL);
    wconv_kernel<<<dim3(2*DIM/32,DIM/32,  4), wb>>>(Wkv, w + WOFF_KV(0), DIM,  2*DIM, (long)DIM*2*DIM, (long)WPERL);
    wconv_kernel<<<dim3(DIM/32,  DIM/32,  4), wb>>>(Wo,  w + WOFF_O(0),  DIM,  DIM,   (long)DIM*DIM,   (long)WPERL);
    wconv_kernel<<<dim3(MLPD/32, DIM/32,  4), wb>>>(W1,  w + WOFF_W1(0), DIM,  MLPD,  (long)DIM*MLPD,  (long)WPERL);
    wconv_kernel<<<dim3(DIM/32,  MLPD/32, 4), wb>>>(W2,  w + WOFF_W2(0), MLPD, DIM,   (long)MLPD*DIM,  (long)WPERL);
    wconv_kernel<<<dim3(2*DIM/32,DIM/32,  1), wb>>>(pWkv, w + WOFF_PKV, DIM, 2*DIM, 0, 0);

    auto G128 = [&](const __half* a, const __half* bw,
                    const float* bias, const float* res,
                    float* C, __half* Ch, int M, int N, int K, int flags) {
        mma_gemm<128><<<dim3(N/128, M/128), 256, SMEM128>>>(a, bw, bias, res, C, Ch, M, N, K, flags);
    };
    auto G64 = [&](const __half* a, const __half* bw,
                   const float* bias, const float* res,
                   float* C, __half* Ch, int M, int N, int K, int flags) {
        mma_gemm<64><<<dim3(N/128, M/64), 256, SMEM64>>>(a, bw, bias, res, C, Ch, M, N, K, flags);
    };

    // ---- Embedding ----
    ln_kernel<<<TOKS, 256>>>(patches, emb_ln_g, nullptr, xn, nullptr, nullptr, nullptr);
    G64(xn, w + WOFF_EMB, b_emb, nullptr, x, nullptr, TOKS, DIM, DIM, FBIAS);
    ln_kernel<<<TOKS, 256>>>(x, emb_ln2_g, x, nullptr, pos_h, pos_w, ppos);

    // ---- Transformer layers ----
    for (int l = 0; l < 4; l++) {
        ln_kernel<<<TOKS, 256>>>(x, ln_attn_g + l*DIM, nullptr, xn, nullptr, nullptr, nullptr);
        G128(xn, w + WOFF_Q(l), nullptr, nullptr, qkv, nullptr, TOKS, 2304, DIM, 0);
        rmsT_all<<<TOKS/2, 384>>>(qkv, qn_g + l*DIM, kn_g + l*DIM, qTh, qTl, kTh, kTl, vTt);
        flash_attn<<<dim3(8, BH), 256, FA_SMEM>>>(qTh, qTl, kTh, kTl, vTt,
                                                  image_ids, lengths, ao);
        G64(ao, w + WOFF_O(l), nullptr, x, x, nullptr, TOKS, DIM, DIM, FRES);
        ln_kernel<<<TOKS, 256>>>(x, ln_ff_g + l*DIM, nullptr, xn, nullptr, nullptr, nullptr);
        G128(xn, w + WOFF_W1(l), b1 + l*MLPD, nullptr, nullptr, tmp, TOKS, MLPD, DIM, FBIAS|FGELU);
        G64(tmp, w + WOFF_W2(l), b2 + l*DIM, x, x, nullptr, TOKS, DIM, MLPD, FBIAS|FRES);
    }

    // ---- Final LN ----
    ln_kernel<<<TOKS, 256>>>(x, final_ln_g, nullptr, xn, nullptr, nullptr, nullptr);

    // ---- Attention pooling ----
    ln_kernel<<<1, 256>>>(pool_q, pool_ln_g, sm, nullptr, nullptr, nullptr, nullptr);
    small_gemm_kernel<<<dim3(3, 1), 256>>>(sm, pWq, nullptr, sm + 768, DIM, DIM);
    rms_vec_kernel<<<1, 384>>>(sm + 768, p_qn_g, sm + 1536);
    G128(xn, w + WOFF_PKV, nullptr, nullptr, qkv, nullptr, TOKS, 1536, DIM, 0);
    rmsT_pool<<<TOKS, 384>>>(qkv, p_kn_g, kTf, vTf);
    pool_attn_kernel<<<NB*IMGS*NHEAD, 256>>>(sm + 1536, kTf, vTf, image_ids, lengths, pattn);
    small_gemm_kernel<<<dim3(3, 16), 256>>>(pattn, pWo, pool_q, pool, DIM, DIM);
    ln_kernel<<<16, 256>>>(pool, head_ln_g, pln, nullptr, nullptr, nullptr, nullptr);
    small_gemm_kernel<<<dim3(4, 16), 256>>>(pln, W_head, nullptr, (float*)d_out, NCLS, DIM);
}

// round 15
// speedup vs baseline: 1.1398x; 1.0105x over previous
#include <cuda_runtime.h>
#include <cuda_bf16.h>
#include <cuda_fp16.h>
#include <math.h>
#include <float.h>
#include <stdint.h>

// ---------------------------------------------------------------------------
// Problem constants
// ---------------------------------------------------------------------------
#define NB      4
#define NTOK    1024
#define DIM     768
#define NHEAD   12
#define DHEAD   64
#define MLPD    3072
#define IMGS    4
#define NCLS    1000
#define TOKS    (NB*NTOK)
#define BH      (NB*NHEAD)

#define FBIAS 1
#define FGELU 2
#define FRES  4

#define WOFF_EMB 0ULL
#define WPERL    7077888ULL
#define WOFF_L(l)   (589824ULL + (unsigned long long)(l)*WPERL)
#define WOFF_Q(l)   (WOFF_L(l) + 0ULL)
#define WOFF_KV(l)  (WOFF_L(l) + 589824ULL)
#define WOFF_O(l)   (WOFF_L(l) + 1769472ULL)
#define WOFF_W1(l)  (WOFF_L(l) + 2359296ULL)
#define WOFF_W2(l)  (WOFF_L(l) + 4718592ULL)
#define WOFF_PKV    (589824ULL + 4ULL*WPERL)
#define WTOTAL      30081024ULL

// ---------------------------------------------------------------------------
// Device scratch
// ---------------------------------------------------------------------------
__device__ float g_x   [TOKS*DIM];
__device__ float g_qkv [TOKS*2304];
__device__ __half g_xn  [TOKS*DIM];
__device__ __half g_tmp [TOKS*MLPD];
__device__ __half g_ao  [TOKS*DIM];
__device__ __nv_bfloat16 g_qTh[BH*NTOK*DHEAD], g_qTl[BH*NTOK*DHEAD];
__device__ __nv_bfloat16 g_kTh[BH*NTOK*DHEAD], g_kTl[BH*NTOK*DHEAD];
__device__ __half g_vTt[BH*DHEAD*NTOK];
__device__ float g_kTf[BH*NTOK*DHEAD], g_vTf[BH*NTOK*DHEAD];
__device__ float g_sm  [4096];
__device__ float g_pattn[16*DIM];
__device__ float g_pool [16*DIM];
__device__ float g_pln  [16*DIM];
__device__ __half g_w[WTOTAL];

// ---------------------------------------------------------------------------
// Helpers
// ---------------------------------------------------------------------------
__device__ __forceinline__ uint32_t smem_u32(const void* p) {
    uint32_t a;
    asm("{ .reg .u64 t; cvta.to.shared.u64 t, %1; cvt.u32.u64 %0, t; }" : "=r"(a) : "l"(p));
    return a;
}

#define LDSM4(r, addr) \
    asm volatile("ldmatrix.sync.aligned.m8n8.x4.shared.b16 {%0,%1,%2,%3}, [%4];" \
        : "=r"((r)[0]), "=r"((r)[1]), "=r"((r)[2]), "=r"((r)[3]) : "r"(addr))

#define MMA16816(d, a, b) \
    asm volatile("mma.sync.aligned.m16n8k16.row.col.f32.bf16.bf16.f32 " \
        "{%0,%1,%2,%3}, {%4,%5,%6,%7}, {%8,%9}, {%0,%1,%2,%3};" \
        : "+f"((d)[0]), "+f"((d)[1]), "+f"((d)[2]), "+f"((d)[3]) \
        : "r"((a)[0]), "r"((a)[1]), "r"((a)[2]), "r"((a)[3]), "r"((b)[0]), "r"((b)[1]))

#define MMAH16816(d, a, b) \
    asm volatile("mma.sync.aligned.m16n8k16.row.col.f32.f16.f16.f32 " \
        "{%0,%1,%2,%3}, {%4,%5,%6,%7}, {%8,%9}, {%0,%1,%2,%3};" \
        : "+f"((d)[0]), "+f"((d)[1]), "+f"((d)[2]), "+f"((d)[3]) \
        : "r"((a)[0]), "r"((a)[1]), "r"((a)[2]), "r"((a)[3]), "r"((b)[0]), "r"((b)[1]))

#define CPA16(dst, src) \
    asm volatile("cp.async.cg.shared.global [%0], [%1], 16;" :: "r"(dst), "l"(src))
#define CP_COMMIT() asm volatile("cp.async.commit_group;" ::: "memory")
#define CP_WAIT0()  asm volatile("cp.async.wait_group 0;" ::: "memory")
#define CP_WAIT1()  asm volatile("cp.async.wait_group 1;" ::: "memory")

__device__ __forceinline__ void split2(float v, __nv_bfloat16& h, __nv_bfloat16& l) {
    h = __float2bfloat16(v);
    l = __float2bfloat16(v - __bfloat162float(h));
}
__device__ __forceinline__ uint32_t bfu(__nv_bfloat16 b) { return (uint32_t)__bfloat16_as_ushort(b); }

template<typename T>
__device__ __forceinline__ void cpa_tile(uint32_t smbase, const T* __restrict__ g,
                                         int ldk, int chunks, int tid)
{
    for (int i = tid; i < chunks; i += 256) {
        int r = i >> 3, c = i & 7;
        uint32_t off = r * 128 + c * 16;
        uint32_t sw = off ^ ((off >> 3) & 0x70);
        CPA16(smbase + sw, g + (size_t)r * ldk + c * 8);
    }
}

// ---------------------------------------------------------------------------
// Weight convert+transpose, family-batched: z = layer.
// ---------------------------------------------------------------------------
__global__ void wconv_kernel(const float* __restrict__ W, __half* __restrict__ out,
                             int K, int N, long srcStride, long dstStride)
{
    __shared__ float t[32][33];
    int z = blockIdx.z;
    const float* Wz = W + (size_t)z * srcStride;
    __half* oz = out + (size_t)z * dstStride;
    int n0 = blockIdx.x * 32, k0 = blockIdx.y * 32;
    int tx = threadIdx.x, ty = threadIdx.y;
#pragma unroll
    for (int r = 0; r < 4; r++)
        t[ty + r*8][tx] = Wz[(size_t)(k0 + ty + r*8) * N + n0 + tx];
    __syncthreads();
#pragma unroll
    for (int r = 0; r < 4; r++) {
        int n = n0 + ty + r*8, k = k0 + tx;
        oz[(size_t)n * K + k] = __float2half(t[tx][ty + r*8]);
    }
}

// ---------------------------------------------------------------------------
// Pipelined mma.sync fp16 GEMM, single pass, 2-stage.
// MT=128: 8 warps 2Mx4N, 2 CTAs/SM.  MT=64: 8 warps 1Mx8N, 3 CTAs/SM.
// ---------------------------------------------------------------------------
template<int MT>
__global__ void __launch_bounds__(256, (MT == 64) ? 3 : 2) mma_gemm(
    const __half* __restrict__ A, const __half* __restrict__ B,
    const float* __restrict__ bias, const float* __restrict__ res,
    float* __restrict__ C, __half* __restrict__ Ch,
    int M, int N, int K, int flags)
{
    constexpr int WM   = MT / 64;
    constexpr int NQ   = (MT == 128) ? 2 : 1;
    constexpr int NTL  = 2 * NQ;
    constexpr int NCOL = NQ * 16;
    constexpr int A_SZ = MT * 128;
    constexpr int STG  = A_SZ + 16384;

    extern __shared__ char smem[];
    uint32_t uS = smem_u32(smem);

    const int tid = threadIdx.x;
    const int wid = tid >> 5, lane = tid & 31;
    const int m0 = blockIdx.y * MT, n0 = blockIdx.x * 128;
    const int wm = wid & (WM - 1), wn = wid / WM;

    const __half* Az = A + (size_t)m0 * K;
    const __half* Bz = B + (size_t)n0 * K;

    float acc[4][NTL][4] = {};

    const int a_row = wm * 64 + (lane & 15);
    const int a_cb  = (lane >> 4) * 16;
    const int b_row = wn * NCOL + (lane & 7) + ((lane >> 4) << 3);
    const int b_cb  = ((lane >> 3) & 1) * 16;

    const int KT = K >> 6;
    {
        cpa_tile(uS,         Az, K, MT * 8, tid);
        cpa_tile(uS + A_SZ,  Bz, K, 1024,   tid);
        CP_COMMIT();
    }

    for (int kt = 0; kt < KT; kt++) {
        if (kt + 1 < KT) {
            uint32_t base = uS + ((kt + 1) & 1) * STG;
            cpa_tile(base,        Az + (kt + 1) * 64, K, MT * 8, tid);
            cpa_tile(base + A_SZ, Bz + (kt + 1) * 64, K, 1024,   tid);
            CP_COMMIT();
            CP_WAIT1();
        } else {
            CP_WAIT0();
        }
        __syncthreads();

        uint32_t bA = uS + (kt & 1) * STG;
        uint32_t bB = bA + A_SZ;

#pragma unroll
        for (int ks = 0; ks < 4; ks++) {
            uint32_t ah[4][4], bh[NQ][4];
#pragma unroll
            for (int mt = 0; mt < 4; mt++) {
                int row = a_row + mt * 16;
                uint32_t off = row * 128 + ((a_cb + ks * 32) ^ ((row & 7) << 4));
                LDSM4(ah[mt], bA + off);
            }
#pragma unroll
            for (int q = 0; q < NQ; q++) {
                int row = b_row + q * 16;
                uint32_t off = row * 128 + ((b_cb + ks * 32) ^ ((row & 7) << 4));
                LDSM4(bh[q], bB + off);
            }
#pragma unroll
            for (int mt = 0; mt < 4; mt++)
#pragma unroll
                for (int nt = 0; nt < NTL; nt++)
                    MMAH16816(acc[mt][nt], ah[mt], &bh[nt >> 1][(nt & 1) * 2]);
        }
        __syncthreads();
    }

    const int rbase = m0 + wm * 64;
#pragma unroll
    for (int mt = 0; mt < 4; mt++) {
#pragma unroll
        for (int nt = 0; nt < NTL; nt++) {
            int c = n0 + wn * NCOL + nt * 8 + (lane & 3) * 2;
            float bv0 = 0.f, bv1 = 0.f;
            if (flags & FBIAS) { bv0 = bias[c]; bv1 = bias[c + 1]; }
#pragma unroll
            for (int half = 0; half < 2; half++) {
                int r = rbase + mt * 16 + (lane >> 2) + half * 8;
                float v0 = acc[mt][nt][half * 2 + 0];
                float v1 = acc[mt][nt][half * 2 + 1];
                if (flags & FBIAS) { v0 += bv0; v1 += bv1; }
                if (flags & FGELU) {
                    v0 = 0.5f * v0 * (1.f + erff(v0 * 0.70710678118654752f));
                    v1 = 0.5f * v1 * (1.f + erff(v1 * 0.70710678118654752f));
                }
                long idx = (long)r * N + c;
                if (flags & FRES) { v0 += res[idx]; v1 += res[idx + 1]; }
                if (C) *(float2*)(C + idx) = make_float2(v0, v1);
                if (Ch) {
                    __half2 hv = __floats2half2_rn(v0, v1);
                    *(__half2*)(Ch + idx) = hv;
                }
            }
        }
    }
}

// ---------------------------------------------------------------------------
// Fused flash attention. QK bf16 hi/lo 3-pass; PV single-pass fp16.
// ---------------------------------------------------------------------------
#define FA_SMEM 133120
#define NEGBIG  -1e30f

__global__ void __launch_bounds__(256, 1) flash_attn(
    const __nv_bfloat16* __restrict__ Qh_, const __nv_bfloat16* __restrict__ Ql_,
    const __nv_bfloat16* __restrict__ Kh_, const __nv_bfloat16* __restrict__ Kl_,
    const __half* __restrict__ Vt_,
    const int* __restrict__ image_ids, const int* __restrict__ lengths,
    __half* __restrict__ O_)
{
    extern __shared__ char smem[];
    uint32_t uS = smem_u32(smem);
    const int tid = threadIdx.x, wid = tid >> 5, lane = tid & 31;
    const int z = blockIdx.y, b = z / 12, h = z % 12;
    const int m0 = blockIdx.x * 128;

    int* s_cmin   = (int*)(smem + 131072);
    int* s_cmax   = s_cmin + 8;
    int* s_jlist  = s_cmax + 8;
    int* s_meta   = s_jlist + 8;
    int* s_imgRow = s_meta + 8;
    int* s_imgCol = s_imgRow + 128;

    const int len = lengths[b];

    {
        int4 v = *(const int4*)(image_ids + b*1024 + wid*128 + lane*4);
        int mn = min(min(v.x, v.y), min(v.z, v.w));
        int mx = max(max(v.x, v.y), max(v.z, v.w));
#pragma unroll
        for (int o = 16; o; o >>= 1) {
            mn = min(mn, __shfl_xor_sync(0xffffffffu, mn, o));
            mx = max(mx, __shfl_xor_sync(0xffffffffu, mx, o));
        }
        if (lane == 0) { s_cmin[wid] = mn; s_cmax[wid] = mx; }
    }
    if (tid < 128) s_imgRow[tid] = image_ids[b*1024 + m0 + tid];
    __syncthreads();
    if (tid == 0) {
        int rmin = s_cmin[blockIdx.x], rmax = s_cmax[blockIdx.x];
        int nj = 0;
        for (int jb = 0; jb < 8; jb++)
            if (jb * 128 < len && s_cmax[jb] >= rmin && s_cmin[jb] <= rmax)
                s_jlist[nj++] = jb;
        s_meta[0] = nj;
    }
    __syncthreads();
    const int nj = s_meta[0];

    const size_t qoff = ((size_t)z * 1024 + m0) * 64;
    cpa_tile(uS,         Qh_ + qoff, 64, 1024, tid);
    cpa_tile(uS + 16384, Ql_ + qoff, 64, 1024, tid);

    auto prefetch = [&](int t) {
        int jb = s_jlist[t];
        int st = t & 1;
        uint32_t base = uS + 32768 + st * 49152;
        size_t koff = ((size_t)z * 1024 + jb * 128) * 64;
        cpa_tile(base,         Kh_ + koff, 64, 1024, tid);
        cpa_tile(base + 16384, Kl_ + koff, 64, 1024, tid);
        const __half* vt = Vt_ + (size_t)z * 64 * 1024 + jb * 128;
        for (int i = tid; i < 1024; i += 256) {
            int r = i >> 4, c = i & 15;
            int kc = c >> 3, cc = c & 7;
            uint32_t off = r * 128 + cc * 16;
            uint32_t sw = off ^ ((off >> 3) & 0x70);
            CPA16(base + 32768 + kc * 8192 + sw, vt + (size_t)r * 1024 + c * 8);
        }
        if (tid < 128) s_imgCol[st * 128 + tid] = image_ids[b*1024 + jb*128 + tid];
    };
    prefetch(0);
    CP_COMMIT();

    float O[8][4] = {};
    float mA = -FLT_MAX, mB = -FLT_MAX, lA = 0.f, lB = 0.f;
    uint32_t qh[4][4], ql[4][4];
    bool qloaded = false;

    const int rA = lane >> 2;
    const int imgA = s_imgRow[wid * 16 + rA];
    const int imgB = s_imgRow[wid * 16 + rA + 8];

    const int a_row = wid * 16 + (lane & 15);
    const int a_cb  = (lane >> 4) * 16;
    const int b_row_base = (lane & 7) + ((lane >> 4) << 3);
    const int b_cb  = ((lane >> 3) & 1) * 16;

    for (int t = 0; t < nj; t++) {
        if (t + 1 < nj) { prefetch(t + 1); CP_COMMIT(); CP_WAIT1(); }
        else CP_WAIT0();
        __syncthreads();

        if (!qloaded) {
            qloaded = true;
#pragma unroll
            for (int ks = 0; ks < 4; ks++) {
                uint32_t off = a_row * 128 + ((a_cb + ks * 32) ^ ((a_row & 7) << 4));
                LDSM4(qh[ks], uS + off);
                LDSM4(ql[ks], uS + 16384 + off);
            }
        }

        int st = t & 1;
        uint32_t bK  = uS + 32768 + st * 49152;
        uint32_t bKl = bK + 16384;
        uint32_t bV  = bK + 32768;
        int jb = s_jlist[t];
        int j0 = jb * 128;
        const int* imgC = s_imgCol + st * 128;

        float S[16][4] = {};
#pragma unroll
        for (int ks = 0; ks < 4; ks++) {
#pragma unroll
            for (int nb = 0; nb < 8; nb++) {
                uint32_t bh4[4], bl4[4];
                int row = nb * 16 + b_row_base;
                uint32_t off = row * 128 + ((b_cb + ks * 32) ^ ((row & 7) << 4));
                LDSM4(bh4, bK + off);
                LDSM4(bl4, bKl + off);
                MMA16816(S[2*nb],   qh[ks], bh4);
                MMA16816(S[2*nb+1], qh[ks], bh4 + 2);
                MMA16816(S[2*nb],   qh[ks], bl4);
                MMA16816(S[2*nb+1], qh[ks], bl4 + 2);
                MMA16816(S[2*nb],   ql[ks], bh4);
                MMA16816(S[2*nb+1], ql[ks], bh4 + 2);
            }
        }

#pragma unroll
        for (int nt = 0; nt < 16; nt++) {
            int c0 = nt * 8 + (lane & 3) * 2;
            int i0 = imgC[c0], i1 = imgC[c0 + 1];
            bool v0 = (j0 + c0) < len, v1 = (j0 + c0 + 1) < len;
            if (!(i0 == imgA && v0)) S[nt][0] = NEGBIG;
            if (!(i1 == imgA && v1)) S[nt][1] = NEGBIG;
            if (!(i0 == imgB && v0)) S[nt][2] = NEGBIG;
            if (!(i1 == imgB && v1)) S[nt][3] = NEGBIG;
        }
        float mnA = mA, mnB = mB;
#pragma unroll
        for (int nt = 0; nt < 16; nt++) {
            mnA = fmaxf(mnA, fmaxf(S[nt][0], S[nt][1]));
            mnB = fmaxf(mnB, fmaxf(S[nt][2], S[nt][3]));
        }
#pragma unroll
        for (int o = 1; o <= 2; o <<= 1) {
            mnA = fmaxf(mnA, __shfl_xor_sync(0xffffffffu, mnA, o));
            mnB = fmaxf(mnB, __shfl_xor_sync(0xffffffffu, mnB, o));
        }
        float scA = __expf(mA - mnA), scB = __expf(mB - mnB);
        mA = mnA; mB = mnB;
        lA *= scA; lB *= scB;
#pragma unroll
        for (int nt = 0; nt < 16; nt++) {
            float p0 = (S[nt][0] > -1e29f) ? __expf(S[nt][0] - mnA) : 0.f;
            float p1 = (S[nt][1] > -1e29f) ? __expf(S[nt][1] - mnA) : 0.f;
            float p2 = (S[nt][2] > -1e29f) ? __expf(S[nt][2] - mnB) : 0.f;
            float p3 = (S[nt][3] > -1e29f) ? __expf(S[nt][3] - mnB) : 0.f;
            lA += p0 + p1; lB += p2 + p3;
            S[nt][0] = p0; S[nt][1] = p1; S[nt][2] = p2; S[nt][3] = p3;
        }
#pragma unroll
        for (int nt = 0; nt < 8; nt++) {
            O[nt][0] *= scA; O[nt][1] *= scA; O[nt][2] *= scB; O[nt][3] *= scB;
        }

#pragma unroll
        for (int kt = 0; kt < 8; kt++) {
            uint32_t ah4[4];
            {
                __half2 p0 = __floats2half2_rn(S[2*kt][0],   S[2*kt][1]);
                __half2 p1 = __floats2half2_rn(S[2*kt][2],   S[2*kt][3]);
                __half2 p2 = __floats2half2_rn(S[2*kt+1][0], S[2*kt+1][1]);
                __half2 p3 = __floats2half2_rn(S[2*kt+1][2], S[2*kt+1][3]);
                ah4[0] = *(uint32_t*)&p0; ah4[1] = *(uint32_t*)&p1;
                ah4[2] = *(uint32_t*)&p2; ah4[3] = *(uint32_t*)&p3;
            }
            uint32_t tb = bV + (kt >> 2) * 8192;
#pragma unroll
            for (int nb = 0; nb < 4; nb++) {
                uint32_t vh4[4];
                int row = nb * 16 + b_row_base;
                uint32_t off = row * 128 + ((b_cb + (kt & 3) * 32) ^ ((row & 7) << 4));
                LDSM4(vh4, tb + off);
                MMAH16816(O[2*nb],   ah4, vh4);
                MMAH16816(O[2*nb+1], ah4, vh4 + 2);
            }
        }
        __syncthreads();
    }

#pragma unroll
    for (int o = 1; o <= 2; o <<= 1) {
        lA += __shfl_xor_sync(0xffffffffu, lA, o);
        lB += __shfl_xor_sync(0xffffffffu, lB, o);
    }
    float iA = lA > 0.f ? 1.f / lA : 0.f;
    float iB = lB > 0.f ? 1.f / lB : 0.f;
    size_t rowA = (size_t)(b * 1024 + m0 + wid * 16 + rA);
#pragma unroll
    for (int nt = 0; nt < 8; nt++) {
        int c = nt * 8 + (lane & 3) * 2;
        size_t idx = rowA * 768 + h * 64 + c;
        *(__half2*)(O_ + idx) = __floats2half2_rn(O[nt][0] * iA, O[nt][1] * iA);
        idx = (rowA + 8) * 768 + h * 64 + c;
        *(__half2*)(O_ + idx) = __floats2half2_rn(O[nt][2] * iB, O[nt][3] * iB);
    }
}

// ---------------------------------------------------------------------------
// LayerNorm over width 768, 4 rows per block (MLP=12 hides DRAM latency).
// fp32 and/or fp16 outputs. Optional pos add. grid = ceil(nrows/4).
// ---------------------------------------------------------------------------
__global__ void ln_kernel(const float* __restrict__ in, const float* __restrict__ g,
                          float* __restrict__ outf, __half* __restrict__ outh,
                          const float* __restrict__ pos_h, const float* __restrict__ pos_w,
                          const int* __restrict__ ppos, int nrows)
{
    const int r0 = blockIdx.x * 4;
    const int tid = threadIdx.x;
    const int w = tid >> 5;

    float v[4][3];
    float s[4], q[4];
#pragma unroll
    for (int j = 0; j < 4; j++) { s[j] = 0.f; q[j] = 0.f; }
#pragma unroll
    for (int j = 0; j < 4; j++) {
        int row = r0 + j;
        if (row < nrows) {
            const float* xr = in + (size_t)row * 768;
#pragma unroll
            for (int i = 0; i < 3; i++) {
                float t = xr[tid + i*256];
                v[j][i] = t; s[j] += t; q[j] += t*t;
            }
        }
    }
#pragma unroll
    for (int o = 16; o; o >>= 1) {
#pragma unroll
        for (int j = 0; j < 4; j++) {
            s[j] += __shfl_xor_sync(0xffffffffu, s[j], o);
            q[j] += __shfl_xor_sync(0xffffffffu, q[j], o);
        }
    }
    __shared__ float shs[8][4], shq[8][4], st[4][2];
    if ((tid & 31) == 0) {
#pragma unroll
        for (int j = 0; j < 4; j++) { shs[w][j] = s[j]; shq[w][j] = q[j]; }
    }
    __syncthreads();
    if (tid < 4) {
        float S = 0.f, Q = 0.f;
#pragma unroll
        for (int i = 0; i < 8; i++) { S += shs[i][tid]; Q += shq[i][tid]; }
        float mu = S * (1.f/768.f);
        st[tid][0] = mu;
        st[tid][1] = rsqrtf(Q * (1.f/768.f) - mu*mu + 1e-5f);
    }
    __syncthreads();

#pragma unroll
    for (int j = 0; j < 4; j++) {
        int row = r0 + j;
        if (row >= nrows) continue;
        float mu = st[j][0], rs = st[j][1];
        int p0 = 0, p1 = 0;
        if (ppos) { p0 = ppos[row*2]; p1 = ppos[row*2 + 1]; }
#pragma unroll
        for (int i = 0; i < 3; i++) {
            int c = tid + i*256;
            float y = (v[j][i] - mu) * rs * g[c];
            if (ppos) y += pos_h[p0*768 + c] + pos_w[p1*768 + c];
            size_t idx = (size_t)row*768 + c;
            if (outf) outf[idx] = y;
            if (outh) outh[idx] = __float2half(y);
        }
    }
}

// ---------------------------------------------------------------------------
// Fused QKV postprocess: 2 tokens per block.
// ---------------------------------------------------------------------------
__global__ void rmsT_all(const float* __restrict__ qkv,
                         const float* __restrict__ qg, const float* __restrict__ kg,
                         __nv_bfloat16* __restrict__ qh, __nv_bfloat16* __restrict__ ql,
                         __nv_bfloat16* __restrict__ kh, __nv_bfloat16* __restrict__ kl,
                         __half* __restrict__ vt)
{
    int t0 = blockIdx.x * 2;
    int b = t0 >> 10, n0 = t0 & 1023;
    int w = threadIdx.x >> 5, lane = threadIdx.x & 31;
    const float* base0 = qkv + (size_t)t0 * 2304 + w * 64;
    const float* base1 = base0 + 2304;
    __nv_bfloat16 hh, ll;

    {
        float a0 = base0[lane], a1 = base0[lane + 32];
        float b0 = base1[lane], b1 = base1[lane + 32];
        float s0 = a0*a0 + a1*a1, s1 = b0*b0 + b1*b1;
#pragma unroll
        for (int o = 16; o; o >>= 1) {
            s0 += __shfl_xor_sync(0xffffffffu, s0, o);
            s1 += __shfl_xor_sync(0xffffffffu, s1, o);
        }
        float i0 = 8.0f / fmaxf(sqrtf(s0), 1e-12f);
        float i1 = 8.0f / fmaxf(sqrtf(s1), 1e-12f);
        float g0 = qg[w*64 + lane], g1 = qg[w*64 + lane + 32];
        size_t d0 = ((size_t)(b*12 + w) * 1024 + n0) * 64;
        split2(a0 * i0 * g0, hh, ll); qh[d0 + lane] = hh;      ql[d0 + lane] = ll;
        split2(a1 * i0 * g1, hh, ll); qh[d0 + lane + 32] = hh; ql[d0 + lane + 32] = ll;
        split2(b0 * i1 * g0, hh, ll); qh[d0 + 64 + lane] = hh;      ql[d0 + 64 + lane] = ll;
        split2(b1 * i1 * g1, hh, ll); qh[d0 + 64 + lane + 32] = hh; ql[d0 + 64 + lane + 32] = ll;
    }
    {
        float a0 = base0[768 + lane], a1 = base0[768 + lane + 32];
        float b0 = base1[768 + lane], b1 = base1[768 + lane + 32];
        float s0 = a0*a0 + a1*a1, s1 = b0*b0 + b1*b1;
#pragma unroll
        for (int o = 16; o; o >>= 1) {
            s0 += __shfl_xor_sync(0xffffffffu, s0, o);
            s1 += __shfl_xor_sync(0xffffffffu, s1, o);
        }
        float i0 = 8.0f / fmaxf(sqrtf(s0), 1e-12f);
        float i1 = 8.0f / fmaxf(sqrtf(s1), 1e-12f);
        float g0 = kg[w*64 + lane], g1 = kg[w*64 + lane + 32];
        size_t d0 = ((size_t)(b*12 + w) * 1024 + n0) * 64;
        split2(a0 * i0 * g0, hh, ll); kh[d0 + lane] = hh;      kl[d0 + lane] = ll;
        split2(a1 * i0 * g1, hh, ll); kh[d0 + lane + 32] = hh; kl[d0 + lane + 32] = ll;
        split2(b0 * i1 * g0, hh, ll); kh[d0 + 64 + lane] = hh;      kl[d0 + 64 + lane] = ll;
        split2(b1 * i1 * g1, hh, ll); kh[d0 + 64 + lane + 32] = hh; kl[d0 + 64 + lane + 32] = ll;
    }
    {
        float a0 = base0[1536 + lane], a1 = base0[1536 + lane + 32];
        float b0 = base1[1536 + lane], b1 = base1[1536 + lane + 32];
        size_t vb = ((size_t)(b*12 + w) * 64) * 1024 + n0;
        *(__half2*)(vt + vb + (size_t)lane * 1024)        = __floats2half2_rn(a0, b0);
        *(__half2*)(vt + vb + (size_t)(lane + 32) * 1024) = __floats2half2_rn(a1, b1);
    }
}

// Pool-path: one launch does k-rms + v copy (fp32 outputs).
__global__ void rmsT_pool(const float* __restrict__ kv,
                          const float* __restrict__ kg,
                          float* __restrict__ kT, float* __restrict__ vT)
{
    int token = blockIdx.x;
    int b = token >> 10, n = token & 1023;
    int w = threadIdx.x >> 5, lane = threadIdx.x & 31;
    const float* base = kv + (size_t)token * 1536 + w * 64;
    {
        float v0 = base[lane], v1 = base[lane + 32];
        float ss = v0*v0 + v1*v1;
#pragma unroll
        for (int o = 16; o; o >>= 1) ss += __shfl_xor_sync(0xffffffffu, ss, o);
        float inv = 8.0f / fmaxf(sqrtf(ss), 1e-12f);
        float* dst = kT + ((size_t)(b*12 + w) * 1024 + n) * 64;
        dst[lane]      = v0 * inv * kg[w*64 + lane];
        dst[lane + 32] = v1 * inv * kg[w*64 + lane + 32];
    }
    {
        float v0 = base[768 + lane], v1 = base[768 + lane + 32];
        float* dst = vT + ((size_t)(b*12 + w) * 1024 + n) * 64;
        dst[lane] = v0; dst[lane + 32] = v1;
    }
}

// ---------------------------------------------------------------------------
// Attention pooling (192 blocks), fp32 path.
// ---------------------------------------------------------------------------
__global__ void pool_attn_kernel(const float* __restrict__ pqn, const float* __restrict__ kT,
                                 const float* __restrict__ vT, const int* __restrict__ image_ids,
                                 const int* __restrict__ lengths, float* __restrict__ out)
{
    int idx = blockIdx.x;
    int h = idx % 12, img = (idx / 12) % 4, b = idx / 48;
    int tid = threadIdx.x;
    __shared__ float q[64];
    __shared__ float p[1024];
    __shared__ float sh[8];
    __shared__ float bs[2];
    __shared__ float sred[256];
    if (tid < 64) q[tid] = pqn[h*64 + tid];
    __syncthreads();

    const float* K = kT + (size_t)(b*12 + h) * 1024 * 64;
    int len = lengths[b];
    float loc[4]; float mx = -FLT_MAX;
#pragma unroll
    for (int t = 0; t < 4; t++) {
        int j = tid + t*256;
        const float* kr = K + (size_t)j * 64;
        float dot = 0.f;
#pragma unroll
        for (int d = 0; d < 64; d++) dot += q[d] * kr[d];
        bool ok = (image_ids[b*1024 + j] == img) && (j < len);
        loc[t] = ok ? dot : -FLT_MAX;
        mx = fmaxf(mx, loc[t]);
    }
#pragma unroll
    for (int o = 16; o; o >>= 1) mx = fmaxf(mx, __shfl_xor_sync(0xffffffffu, mx, o));
    int w = tid >> 5;
    if ((tid & 31) == 0) sh[w] = mx;
    __syncthreads();
    if (tid == 0) { float mm = sh[0]; for (int i = 1; i < 8; i++) mm = fmaxf(mm, sh[i]); bs[0] = mm; }
    __syncthreads();
    mx = bs[0];
    float s = 0.f;
#pragma unroll
    for (int t = 0; t < 4; t++) {
        float e = __expf(loc[t] - mx);
        p[tid + t*256] = e;
        s += e;
    }
#pragma unroll
    for (int o = 16; o; o >>= 1) s += __shfl_xor_sync(0xffffffffu, s, o);
    if ((tid & 31) == 0) sh[w] = s;
    __syncthreads();
    if (tid == 0) { float ss = 0.f; for (int i = 0; i < 8; i++) ss += sh[i]; bs[1] = 1.f / ss; }
    __syncthreads();
    float inv = bs[1];

    const float* V = vT + (size_t)(b*12 + h) * 1024 * 64;
    int d = tid & 63, grp = tid >> 6;
    float acc = 0.f;
    for (int j = grp; j < 1024; j += 4) acc += p[j] * V[(size_t)j*64 + d];
    sred[tid] = acc;
    __syncthreads();
    if (grp == 0) {
        float r = (sred[d] + sred[d + 64]) + (sred[d + 128] + sred[d + 192]);
        out[(size_t)(b*4 + img) * 768 + h*64 + d] = r * inv;
    }
}

__global__ void rms_vec_kernel(const float* __restrict__ in, const float* __restrict__ g,
                               float* __restrict__ out)
{
    int w = threadIdx.x >> 5, lane = threadIdx.x & 31;
    float v0 = in[w*64 + lane], v1 = in[w*64 + lane + 32];
    float ss = v0*v0 + v1*v1;
#pragma unroll
    for (int o = 16; o; o >>= 1) ss += __shfl_xor_sync(0xffffffffu, ss, o);
    float inv = 8.0f / fmaxf(sqrtf(ss), 1e-12f);
    out[w*64 + lane]      = v0 * inv * g[w*64 + lane];
    out[w*64 + lane + 32] = v1 * inv * g[w*64 + lane + 32];
}

__global__ void small_gemm_kernel(const float* __restrict__ A, const float* __restrict__ W,
                                  const float* __restrict__ addvec, float* __restrict__ C,
                                  int N, int K)
{
    __shared__ float a[768];
    int row = blockIdx.y;
    for (int i = threadIdx.x; i < K; i += 256) a[i] = A[(size_t)row*K + i];
    __syncthreads();
    int n = blockIdx.x * 256 + threadIdx.x;
    if (n >= N) return;
    float acc = addvec ? addvec[n] : 0.f;
#pragma unroll 4
    for (int k = 0; k < K; k++) acc += a[k] * W[(size_t)k*N + n];
    C[(size_t)row*N + n] = acc;
}

// ---------------------------------------------------------------------------
// Host side
// ---------------------------------------------------------------------------
extern "C" void kernel_launch(void* const* d_in, const int* in_sizes, int n_in,
                              void* d_out, int out_size)
{
    (void)in_sizes; (void)n_in; (void)out_size;
    const float* patches    = (const float*)d_in[0];
    const int*   ppos       = (const int*)  d_in[1];
    const int*   image_ids  = (const int*)  d_in[2];
    const int*   lengths    = (const int*)  d_in[3];
    const float* emb_ln_g   = (const float*)d_in[4];
    const float* W_emb      = (const float*)d_in[5];
    const float* b_emb      = (const float*)d_in[6];
    const float* emb_ln2_g  = (const float*)d_in[7];
    const float* pos_h      = (const float*)d_in[8];
    const float* pos_w      = (const float*)d_in[9];
    const float* ln_attn_g  = (const float*)d_in[10];
    const float* Wq         = (const float*)d_in[11];
    const float* Wkv        = (const float*)d_in[12];
    const float* qn_g       = (const float*)d_in[13];
    const float* kn_g       = (const float*)d_in[14];
    const float* Wo         = (const float*)d_in[15];
    const float* ln_ff_g    = (const float*)d_in[16];
    const float* W1         = (const float*)d_in[17];
    const float* b1         = (const float*)d_in[18];
    const float* W2         = (const float*)d_in[19];
    const float* b2         = (const float*)d_in[20];
    const float* final_ln_g = (const float*)d_in[21];
    const float* pool_q     = (const float*)d_in[22];
    const float* pool_ln_g  = (const float*)d_in[23];
    const float* pWq        = (const float*)d_in[24];
    const float* pWkv       = (const float*)d_in[25];
    const float* p_qn_g     = (const float*)d_in[26];
    const float* p_kn_g     = (const float*)d_in[27];
    const float* pWo        = (const float*)d_in[28];
    const float* head_ln_g  = (const float*)d_in[29];
    const float* W_head     = (const float*)d_in[30];

    float *x, *qkv, *kTf, *vTf, *sm, *pattn, *pool, *pln;
    __half *xn, *tmp, *ao, *w, *vTt;
    __nv_bfloat16 *qTh, *qTl, *kTh, *kTl;
    cudaGetSymbolAddress((void**)&x,    g_x);
    cudaGetSymbolAddress((void**)&qkv,  g_qkv);
    cudaGetSymbolAddress((void**)&kTf,  g_kTf);
    cudaGetSymbolAddress((void**)&vTf,  g_vTf);
    cudaGetSymbolAddress((void**)&sm,   g_sm);
    cudaGetSymbolAddress((void**)&pattn,g_pattn);
    cudaGetSymbolAddress((void**)&pool, g_pool);
    cudaGetSymbolAddress((void**)&pln,  g_pln);
    cudaGetSymbolAddress((void**)&xn,   g_xn);
    cudaGetSymbolAddress((void**)&tmp,  g_tmp);
    cudaGetSymbolAddress((void**)&ao,   g_ao);
    cudaGetSymbolAddress((void**)&qTh,  g_qTh);
    cudaGetSymbolAddress((void**)&qTl,  g_qTl);
    cudaGetSymbolAddress((void**)&kTh,  g_kTh);
    cudaGetSymbolAddress((void**)&kTl,  g_kTl);
    cudaGetSymbolAddress((void**)&vTt,  g_vTt);
    cudaGetSymbolAddress((void**)&w,    g_w);

    constexpr int SMEM128 = 65536;
    constexpr int SMEM64  = 49152;
    cudaFuncSetAttribute(mma_gemm<128>, cudaFuncAttributeMaxDynamicSharedMemorySize, SMEM128);
    cudaFuncSetAttribute(mma_gemm<64>,  cudaFuncAttributeMaxDynamicSharedMemorySize, SMEM64);
    cudaFuncSetAttribute(flash_attn,    cudaFuncAttributeMaxDynamicSharedMemorySize, FA_SMEM);

    // ---- Convert + transpose weights to fp16 [N,K], family-batched ----
    dim3 wb(32, 8);
    wconv_kernel<<<dim3(DIM/32,  DIM/32,  1), wb>>>(W_emb, w + WOFF_EMB, DIM, DIM, 0, 0);
    wconv_kernel<<<dim3(DIM/32,  DIM/32,  4), wb>>>(Wq,  w + WOFF_Q(0),  DIM,  DIM,   (long)DIM*DIM,   (long)WPERL);
    wconv_kernel<<<dim3(2*DIM/32,DIM/32,  4), wb>>>(Wkv, w + WOFF_KV(0), DIM,  2*DIM, (long)DIM*2*DIM, (long)WPERL);
    wconv_kernel<<<dim3(DIM/32,  DIM/32,  4), wb>>>(Wo,  w + WOFF_O(0),  DIM,  DIM,   (long)DIM*DIM,   (long)WPERL);
    wconv_kernel<<<dim3(MLPD/32, DIM/32,  4), wb>>>(W1,  w + WOFF_W1(0), DIM,  MLPD,  (long)DIM*MLPD,  (long)WPERL);
    wconv_kernel<<<dim3(DIM/32,  MLPD/32, 4), wb>>>(W2,  w + WOFF_W2(0), MLPD, DIM,   (long)MLPD*DIM,  (long)WPERL);
    wconv_kernel<<<dim3(2*DIM/32,DIM/32,  1), wb>>>(pWkv, w + WOFF_PKV, DIM, 2*DIM, 0, 0);

    auto G128 = [&](const __half* a, const __half* bw,
                    const float* bias, const float* res,
                    float* C, __half* Ch, int M, int N, int K, int flags) {
        mma_gemm<128><<<dim3(N/128, M/128), 256, SMEM128>>>(a, bw, bias, res, C, Ch, M, N, K, flags);
    };
    auto G64 = [&](const __half* a, const __half* bw,
                   const float* bias, const float* res,
                   float* C, __half* Ch, int M, int N, int K, int flags) {
        mma_gemm<64><<<dim3(N/128, M/64), 256, SMEM64>>>(a, bw, bias, res, C, Ch, M, N, K, flags);
    };
    auto LN = [&](const float* in, const float* g, float* outf, __half* outh,
                  const float* ph, const float* pw, const int* pp, int nrows) {
        ln_kernel<<<(nrows + 3) / 4, 256>>>(in, g, outf, outh, ph, pw, pp, nrows);
    };

    // ---- Embedding ----
    LN(patches, emb_ln_g, nullptr, xn, nullptr, nullptr, nullptr, TOKS);
    G64(xn, w + WOFF_EMB, b_emb, nullptr, x, nullptr, TOKS, DIM, DIM, FBIAS);
    LN(x, emb_ln2_g, x, nullptr, pos_h, pos_w, ppos, TOKS);

    // ---- Transformer layers ----
    for (int l = 0; l < 4; l++) {
        LN(x, ln_attn_g + l*DIM, nullptr, xn, nullptr, nullptr, nullptr, TOKS);
        G128(xn, w + WOFF_Q(l), nullptr, nullptr, qkv, nullptr, TOKS, 2304, DIM, 0);
        rmsT_all<<<TOKS/2, 384>>>(qkv, qn_g + l*DIM, kn_g + l*DIM, qTh, qTl, kTh, kTl, vTt);
        flash_attn<<<dim3(8, BH), 256, FA_SMEM>>>(qTh, qTl, kTh, kTl, vTt,
                                                  image_ids, lengths, ao);
        G64(ao, w + WOFF_O(l), nullptr, x, x, nullptr, TOKS, DIM, DIM, FRES);
        LN(x, ln_ff_g + l*DIM, nullptr, xn, nullptr, nullptr, nullptr, TOKS);
        G128(xn, w + WOFF_W1(l), b1 + l*MLPD, nullptr, nullptr, tmp, TOKS, MLPD, DIM, FBIAS|FGELU);
        G64(tmp, w + WOFF_W2(l), b2 + l*DIM, x, x, nullptr, TOKS, DIM, MLPD, FBIAS|FRES);
    }

    // ---- Final LN ----
    LN(x, final_ln_g, nullptr, xn, nullptr, nullptr, nullptr, TOKS);

    // ---- Attention pooling ----
    LN(pool_q, pool_ln_g, sm, nullptr, nullptr, nullptr, nullptr, 1);
    small_gemm_kernel<<<dim3(3, 1), 256>>>(sm, pWq, nullptr, sm + 768, DIM, DIM);
    rms_vec_kernel<<<1, 384>>>(sm + 768, p_qn_g, sm + 1536);
    G128(xn, w + WOFF_PKV, nullptr, nullptr, qkv, nullptr, TOKS, 1536, DIM, 0);
    rmsT_pool<<<TOKS, 384>>>(qkv, p_kn_g, kTf, vTf);
    pool_attn_kernel<<<NB*IMGS*NHEAD, 256>>>(sm + 1536, kTf, vTf, image_ids, lengths, pattn);
    small_gemm_kernel<<<dim3(3, 16), 256>>>(pattn, pWo, pool_q, pool, DIM, DIM);
    LN(pool, head_ln_g, pln, nullptr, nullptr, nullptr, nullptr, 16);
    small_gemm_kernel<<<dim3(4, 16), 256>>>(pln, W_head, nullptr, (float*)d_out, NCLS, DIM);
}

// round 16
// speedup vs baseline: 1.1528x; 1.0115x over previous
#include <cuda_runtime.h>
#include <cuda_bf16.h>
#include <cuda_fp16.h>
#include <math.h>
#include <float.h>
#include <stdint.h>

// ---------------------------------------------------------------------------
// Problem constants
// ---------------------------------------------------------------------------
#define NB      4
#define NTOK    1024
#define DIM     768
#define NHEAD   12
#define DHEAD   64
#define MLPD    3072
#define IMGS    4
#define NCLS    1000
#define TOKS    (NB*NTOK)
#define BH      (NB*NHEAD)

#define FBIAS 1
#define FGELU 2
#define FRES  4

#define WOFF_EMB 0ULL
#define WPERL    7077888ULL
#define WOFF_L(l)   (589824ULL + (unsigned long long)(l)*WPERL)
#define WOFF_Q(l)   (WOFF_L(l) + 0ULL)
#define WOFF_KV(l)  (WOFF_L(l) + 589824ULL)
#define WOFF_O(l)   (WOFF_L(l) + 1769472ULL)
#define WOFF_W1(l)  (WOFF_L(l) + 2359296ULL)
#define WOFF_W2(l)  (WOFF_L(l) + 4718592ULL)
#define WOFF_PKV    (589824ULL + 4ULL*WPERL)
#define WTOTAL      30081024ULL

// ---------------------------------------------------------------------------
// Device scratch
// ---------------------------------------------------------------------------
__device__ float g_x   [TOKS*DIM];
__device__ float g_qkv [TOKS*2304];
__device__ __half g_xn  [TOKS*DIM];
__device__ __half g_tmp [TOKS*MLPD];
__device__ __half g_ao  [TOKS*DIM];
__device__ __nv_bfloat16 g_qTh[BH*NTOK*DHEAD], g_qTl[BH*NTOK*DHEAD];
__device__ __nv_bfloat16 g_kTh[BH*NTOK*DHEAD], g_kTl[BH*NTOK*DHEAD];
__device__ __half g_vTt[BH*DHEAD*NTOK];
__device__ float g_kTf[BH*NTOK*DHEAD], g_vTf[BH*NTOK*DHEAD];
__device__ float g_sm  [4096];
__device__ float g_pattn[16*DIM];
__device__ float g_pool [16*DIM];
__device__ float g_pln  [16*DIM];
__device__ __half g_w[WTOTAL];

// ---------------------------------------------------------------------------
// Helpers
// ---------------------------------------------------------------------------
__device__ __forceinline__ uint32_t smem_u32(const void* p) {
    uint32_t a;
    asm("{ .reg .u64 t; cvta.to.shared.u64 t, %1; cvt.u32.u64 %0, t; }" : "=r"(a) : "l"(p));
    return a;
}

#define LDSM4(r, addr) \
    asm volatile("ldmatrix.sync.aligned.m8n8.x4.shared.b16 {%0,%1,%2,%3}, [%4];" \
        : "=r"((r)[0]), "=r"((r)[1]), "=r"((r)[2]), "=r"((r)[3]) : "r"(addr))

#define MMA16816(d, a, b) \
    asm volatile("mma.sync.aligned.m16n8k16.row.col.f32.bf16.bf16.f32 " \
        "{%0,%1,%2,%3}, {%4,%5,%6,%7}, {%8,%9}, {%0,%1,%2,%3};" \
        : "+f"((d)[0]), "+f"((d)[1]), "+f"((d)[2]), "+f"((d)[3]) \
        : "r"((a)[0]), "r"((a)[1]), "r"((a)[2]), "r"((a)[3]), "r"((b)[0]), "r"((b)[1]))

#define MMAH16816(d, a, b) \
    asm volatile("mma.sync.aligned.m16n8k16.row.col.f32.f16.f16.f32 " \
        "{%0,%1,%2,%3}, {%4,%5,%6,%7}, {%8,%9}, {%0,%1,%2,%3};" \
        : "+f"((d)[0]), "+f"((d)[1]), "+f"((d)[2]), "+f"((d)[3]) \
        : "r"((a)[0]), "r"((a)[1]), "r"((a)[2]), "r"((a)[3]), "r"((b)[0]), "r"((b)[1]))

#define CPA16(dst, src) \
    asm volatile("cp.async.cg.shared.global [%0], [%1], 16;" :: "r"(dst), "l"(src))
#define CP_COMMIT() asm volatile("cp.async.commit_group;" ::: "memory")
#define CP_WAIT0()  asm volatile("cp.async.wait_group 0;" ::: "memory")
#define CP_WAIT1()  asm volatile("cp.async.wait_group 1;" ::: "memory")

__device__ __forceinline__ void split2(float v, __nv_bfloat16& h, __nv_bfloat16& l) {
    h = __float2bfloat16(v);
    l = __float2bfloat16(v - __bfloat162float(h));
}
__device__ __forceinline__ uint32_t bfu(__nv_bfloat16 b) { return (uint32_t)__bfloat16_as_ushort(b); }

template<typename T>
__device__ __forceinline__ void cpa_tile(uint32_t smbase, const T* __restrict__ g,
                                         int ldk, int chunks, int tid)
{
    for (int i = tid; i < chunks; i += 256) {
        int r = i >> 3, c = i & 7;
        uint32_t off = r * 128 + c * 16;
        uint32_t sw = off ^ ((off >> 3) & 0x70);
        CPA16(smbase + sw, g + (size_t)r * ldk + c * 8);
    }
}

// ---------------------------------------------------------------------------
// Weight convert+transpose, family-batched: z = layer.
// ---------------------------------------------------------------------------
__global__ void wconv_kernel(const float* __restrict__ W, __half* __restrict__ out,
                             int K, int N, long srcStride, long dstStride)
{
    __shared__ float t[32][33];
    int z = blockIdx.z;
    const float* Wz = W + (size_t)z * srcStride;
    __half* oz = out + (size_t)z * dstStride;
    int n0 = blockIdx.x * 32, k0 = blockIdx.y * 32;
    int tx = threadIdx.x, ty = threadIdx.y;
#pragma unroll
    for (int r = 0; r < 4; r++)
        t[ty + r*8][tx] = Wz[(size_t)(k0 + ty + r*8) * N + n0 + tx];
    __syncthreads();
#pragma unroll
    for (int r = 0; r < 4; r++) {
        int n = n0 + ty + r*8, k = k0 + tx;
        oz[(size_t)n * K + k] = __float2half(t[tx][ty + r*8]);
    }
}

// ---------------------------------------------------------------------------
// Pipelined mma.sync fp16 GEMM, single pass, 2-stage.
// MT=128: 8 warps 2Mx4N, 2 CTAs/SM.  MT=64: 8 warps 1Mx8N, 3 CTAs/SM.
// ---------------------------------------------------------------------------
template<int MT>
__global__ void __launch_bounds__(256, (MT == 64) ? 3 : 2) mma_gemm(
    const __half* __restrict__ A, const __half* __restrict__ B,
    const float* __restrict__ bias, const float* __restrict__ res,
    float* __restrict__ C, __half* __restrict__ Ch,
    int M, int N, int K, int flags)
{
    constexpr int WM   = MT / 64;
    constexpr int NQ   = (MT == 128) ? 2 : 1;
    constexpr int NTL  = 2 * NQ;
    constexpr int NCOL = NQ * 16;
    constexpr int A_SZ = MT * 128;
    constexpr int STG  = A_SZ + 16384;

    extern __shared__ char smem[];
    uint32_t uS = smem_u32(smem);

    const int tid = threadIdx.x;
    const int wid = tid >> 5, lane = tid & 31;
    const int m0 = blockIdx.y * MT, n0 = blockIdx.x * 128;
    const int wm = wid & (WM - 1), wn = wid / WM;

    const __half* Az = A + (size_t)m0 * K;
    const __half* Bz = B + (size_t)n0 * K;

    float acc[4][NTL][4] = {};

    const int a_row = wm * 64 + (lane & 15);
    const int a_cb  = (lane >> 4) * 16;
    const int b_row = wn * NCOL + (lane & 7) + ((lane >> 4) << 3);
    const int b_cb  = ((lane >> 3) & 1) * 16;

    const int KT = K >> 6;
    {
        cpa_tile(uS,         Az, K, MT * 8, tid);
        cpa_tile(uS + A_SZ,  Bz, K, 1024,   tid);
        CP_COMMIT();
    }

    for (int kt = 0; kt < KT; kt++) {
        if (kt + 1 < KT) {
            uint32_t base = uS + ((kt + 1) & 1) * STG;
            cpa_tile(base,        Az + (kt + 1) * 64, K, MT * 8, tid);
            cpa_tile(base + A_SZ, Bz + (kt + 1) * 64, K, 1024,   tid);
            CP_COMMIT();
            CP_WAIT1();
        } else {
            CP_WAIT0();
        }
        __syncthreads();

        uint32_t bA = uS + (kt & 1) * STG;
        uint32_t bB = bA + A_SZ;

#pragma unroll
        for (int ks = 0; ks < 4; ks++) {
            uint32_t ah[4][4], bh[NQ][4];
#pragma unroll
            for (int mt = 0; mt < 4; mt++) {
                int row = a_row + mt * 16;
                uint32_t off = row * 128 + ((a_cb + ks * 32) ^ ((row & 7) << 4));
                LDSM4(ah[mt], bA + off);
            }
#pragma unroll
            for (int q = 0; q < NQ; q++) {
                int row = b_row + q * 16;
                uint32_t off = row * 128 + ((b_cb + ks * 32) ^ ((row & 7) << 4));
                LDSM4(bh[q], bB + off);
            }
#pragma unroll
            for (int mt = 0; mt < 4; mt++)
#pragma unroll
                for (int nt = 0; nt < NTL; nt++)
                    MMAH16816(acc[mt][nt], ah[mt], &bh[nt >> 1][(nt & 1) * 2]);
        }
        __syncthreads();
    }

    const int rbase = m0 + wm * 64;
#pragma unroll
    for (int mt = 0; mt < 4; mt++) {
#pragma unroll
        for (int nt = 0; nt < NTL; nt++) {
            int c = n0 + wn * NCOL + nt * 8 + (lane & 3) * 2;
            float bv0 = 0.f, bv1 = 0.f;
            if (flags & FBIAS) { bv0 = bias[c]; bv1 = bias[c + 1]; }
#pragma unroll
            for (int half = 0; half < 2; half++) {
                int r = rbase + mt * 16 + (lane >> 2) + half * 8;
                float v0 = acc[mt][nt][half * 2 + 0];
                float v1 = acc[mt][nt][half * 2 + 1];
                if (flags & FBIAS) { v0 += bv0; v1 += bv1; }
                if (flags & FGELU) {
                    v0 = 0.5f * v0 * (1.f + erff(v0 * 0.70710678118654752f));
                    v1 = 0.5f * v1 * (1.f + erff(v1 * 0.70710678118654752f));
                }
                long idx = (long)r * N + c;
                if (flags & FRES) { v0 += res[idx]; v1 += res[idx + 1]; }
                if (C) *(float2*)(C + idx) = make_float2(v0, v1);
                if (Ch) {
                    __half2 hv = __floats2half2_rn(v0, v1);
                    *(__half2*)(Ch + idx) = hv;
                }
            }
        }
    }
}

// ---------------------------------------------------------------------------
// Fused flash attention. QK bf16 hi/lo 3-pass; PV single-pass fp16.
// ---------------------------------------------------------------------------
#define FA_SMEM 133120
#define NEGBIG  -1e30f

__global__ void __launch_bounds__(256, 1) flash_attn(
    const __nv_bfloat16* __restrict__ Qh_, const __nv_bfloat16* __restrict__ Ql_,
    const __nv_bfloat16* __restrict__ Kh_, const __nv_bfloat16* __restrict__ Kl_,
    const __half* __restrict__ Vt_,
    const int* __restrict__ image_ids, const int* __restrict__ lengths,
    __half* __restrict__ O_)
{
    extern __shared__ char smem[];
    uint32_t uS = smem_u32(smem);
    const int tid = threadIdx.x, wid = tid >> 5, lane = tid & 31;
    const int z = blockIdx.y, b = z / 12, h = z % 12;
    const int m0 = blockIdx.x * 128;

    int* s_cmin   = (int*)(smem + 131072);
    int* s_cmax   = s_cmin + 8;
    int* s_jlist  = s_cmax + 8;
    int* s_meta   = s_jlist + 8;
    int* s_imgRow = s_meta + 8;
    int* s_imgCol = s_imgRow + 128;

    const int len = lengths[b];

    {
        int4 v = *(const int4*)(image_ids + b*1024 + wid*128 + lane*4);
        int mn = min(min(v.x, v.y), min(v.z, v.w));
        int mx = max(max(v.x, v.y), max(v.z, v.w));
#pragma unroll
        for (int o = 16; o; o >>= 1) {
            mn = min(mn, __shfl_xor_sync(0xffffffffu, mn, o));
            mx = max(mx, __shfl_xor_sync(0xffffffffu, mx, o));
        }
        if (lane == 0) { s_cmin[wid] = mn; s_cmax[wid] = mx; }
    }
    if (tid < 128) s_imgRow[tid] = image_ids[b*1024 + m0 + tid];
    __syncthreads();
    if (tid == 0) {
        int rmin = s_cmin[blockIdx.x], rmax = s_cmax[blockIdx.x];
        int nj = 0;
        for (int jb = 0; jb < 8; jb++)
            if (jb * 128 < len && s_cmax[jb] >= rmin && s_cmin[jb] <= rmax)
                s_jlist[nj++] = jb;
        s_meta[0] = nj;
    }
    __syncthreads();
    const int nj = s_meta[0];

    const size_t qoff = ((size_t)z * 1024 + m0) * 64;
    cpa_tile(uS,         Qh_ + qoff, 64, 1024, tid);
    cpa_tile(uS + 16384, Ql_ + qoff, 64, 1024, tid);

    auto prefetch = [&](int t) {
        int jb = s_jlist[t];
        int st = t & 1;
        uint32_t base = uS + 32768 + st * 49152;
        size_t koff = ((size_t)z * 1024 + jb * 128) * 64;
        cpa_tile(base,         Kh_ + koff, 64, 1024, tid);
        cpa_tile(base + 16384, Kl_ + koff, 64, 1024, tid);
        const __half* vt = Vt_ + (size_t)z * 64 * 1024 + jb * 128;
        for (int i = tid; i < 1024; i += 256) {
            int r = i >> 4, c = i & 15;
            int kc = c >> 3, cc = c & 7;
            uint32_t off = r * 128 + cc * 16;
            uint32_t sw = off ^ ((off >> 3) & 0x70);
            CPA16(base + 32768 + kc * 8192 + sw, vt + (size_t)r * 1024 + c * 8);
        }
        if (tid < 128) s_imgCol[st * 128 + tid] = image_ids[b*1024 + jb*128 + tid];
    };
    prefetch(0);
    CP_COMMIT();

    float O[8][4] = {};
    float mA = -FLT_MAX, mB = -FLT_MAX, lA = 0.f, lB = 0.f;
    uint32_t qh[4][4], ql[4][4];
    bool qloaded = false;

    const int rA = lane >> 2;
    const int imgA = s_imgRow[wid * 16 + rA];
    const int imgB = s_imgRow[wid * 16 + rA + 8];

    const int a_row = wid * 16 + (lane & 15);
    const int a_cb  = (lane >> 4) * 16;
    const int b_row_base = (lane & 7) + ((lane >> 4) << 3);
    const int b_cb  = ((lane >> 3) & 1) * 16;

    for (int t = 0; t < nj; t++) {
        if (t + 1 < nj) { prefetch(t + 1); CP_COMMIT(); CP_WAIT1(); }
        else CP_WAIT0();
        __syncthreads();

        if (!qloaded) {
            qloaded = true;
#pragma unroll
            for (int ks = 0; ks < 4; ks++) {
                uint32_t off = a_row * 128 + ((a_cb + ks * 32) ^ ((a_row & 7) << 4));
                LDSM4(qh[ks], uS + off);
                LDSM4(ql[ks], uS + 16384 + off);
            }
        }

        int st = t & 1;
        uint32_t bK  = uS + 32768 + st * 49152;
        uint32_t bKl = bK + 16384;
        uint32_t bV  = bK + 32768;
        int jb = s_jlist[t];
        int j0 = jb * 128;
        const int* imgC = s_imgCol + st * 128;

        float S[16][4] = {};
#pragma unroll
        for (int ks = 0; ks < 4; ks++) {
#pragma unroll
            for (int nb = 0; nb < 8; nb++) {
                uint32_t bh4[4], bl4[4];
                int row = nb * 16 + b_row_base;
                uint32_t off = row * 128 + ((b_cb + ks * 32) ^ ((row & 7) << 4));
                LDSM4(bh4, bK + off);
                LDSM4(bl4, bKl + off);
                MMA16816(S[2*nb],   qh[ks], bh4);
                MMA16816(S[2*nb+1], qh[ks], bh4 + 2);
                MMA16816(S[2*nb],   qh[ks], bl4);
                MMA16816(S[2*nb+1], qh[ks], bl4 + 2);
                MMA16816(S[2*nb],   ql[ks], bh4);
                MMA16816(S[2*nb+1], ql[ks], bh4 + 2);
            }
        }

#pragma unroll
        for (int nt = 0; nt < 16; nt++) {
            int c0 = nt * 8 + (lane & 3) * 2;
            int i0 = imgC[c0], i1 = imgC[c0 + 1];
            bool v0 = (j0 + c0) < len, v1 = (j0 + c0 + 1) < len;
            if (!(i0 == imgA && v0)) S[nt][0] = NEGBIG;
            if (!(i1 == imgA && v1)) S[nt][1] = NEGBIG;
            if (!(i0 == imgB && v0)) S[nt][2] = NEGBIG;
            if (!(i1 == imgB && v1)) S[nt][3] = NEGBIG;
        }
        float mnA = mA, mnB = mB;
#pragma unroll
        for (int nt = 0; nt < 16; nt++) {
            mnA = fmaxf(mnA, fmaxf(S[nt][0], S[nt][1]));
            mnB = fmaxf(mnB, fmaxf(S[nt][2], S[nt][3]));
        }
#pragma unroll
        for (int o = 1; o <= 2; o <<= 1) {
            mnA = fmaxf(mnA, __shfl_xor_sync(0xffffffffu, mnA, o));
            mnB = fmaxf(mnB, __shfl_xor_sync(0xffffffffu, mnB, o));
        }
        float scA = __expf(mA - mnA), scB = __expf(mB - mnB);
        mA = mnA; mB = mnB;
        lA *= scA; lB *= scB;
#pragma unroll
        for (int nt = 0; nt < 16; nt++) {
            float p0 = (S[nt][0] > -1e29f) ? __expf(S[nt][0] - mnA) : 0.f;
            float p1 = (S[nt][1] > -1e29f) ? __expf(S[nt][1] - mnA) : 0.f;
            float p2 = (S[nt][2] > -1e29f) ? __expf(S[nt][2] - mnB) : 0.f;
            float p3 = (S[nt][3] > -1e29f) ? __expf(S[nt][3] - mnB) : 0.f;
            lA += p0 + p1; lB += p2 + p3;
            S[nt][0] = p0; S[nt][1] = p1; S[nt][2] = p2; S[nt][3] = p3;
        }
#pragma unroll
        for (int nt = 0; nt < 8; nt++) {
            O[nt][0] *= scA; O[nt][1] *= scA; O[nt][2] *= scB; O[nt][3] *= scB;
        }

#pragma unroll
        for (int kt = 0; kt < 8; kt++) {
            uint32_t ah4[4];
            {
                __half2 p0 = __floats2half2_rn(S[2*kt][0],   S[2*kt][1]);
                __half2 p1 = __floats2half2_rn(S[2*kt][2],   S[2*kt][3]);
                __half2 p2 = __floats2half2_rn(S[2*kt+1][0], S[2*kt+1][1]);
                __half2 p3 = __floats2half2_rn(S[2*kt+1][2], S[2*kt+1][3]);
                ah4[0] = *(uint32_t*)&p0; ah4[1] = *(uint32_t*)&p1;
                ah4[2] = *(uint32_t*)&p2; ah4[3] = *(uint32_t*)&p3;
            }
            uint32_t tb = bV + (kt >> 2) * 8192;
#pragma unroll
            for (int nb = 0; nb < 4; nb++) {
                uint32_t vh4[4];
                int row = nb * 16 + b_row_base;
                uint32_t off = row * 128 + ((b_cb + (kt & 3) * 32) ^ ((row & 7) << 4));
                LDSM4(vh4, tb + off);
                MMAH16816(O[2*nb],   ah4, vh4);
                MMAH16816(O[2*nb+1], ah4, vh4 + 2);
            }
        }
        __syncthreads();
    }

#pragma unroll
    for (int o = 1; o <= 2; o <<= 1) {
        lA += __shfl_xor_sync(0xffffffffu, lA, o);
        lB += __shfl_xor_sync(0xffffffffu, lB, o);
    }
    float iA = lA > 0.f ? 1.f / lA : 0.f;
    float iB = lB > 0.f ? 1.f / lB : 0.f;
    size_t rowA = (size_t)(b * 1024 + m0 + wid * 16 + rA);
#pragma unroll
    for (int nt = 0; nt < 8; nt++) {
        int c = nt * 8 + (lane & 3) * 2;
        size_t idx = rowA * 768 + h * 64 + c;
        *(__half2*)(O_ + idx) = __floats2half2_rn(O[nt][0] * iA, O[nt][1] * iA);
        idx = (rowA + 8) * 768 + h * 64 + c;
        *(__half2*)(O_ + idx) = __floats2half2_rn(O[nt][2] * iB, O[nt][3] * iB);
    }
}

// ---------------------------------------------------------------------------
// LayerNorm over width 768, 4 rows per block.
// ---------------------------------------------------------------------------
__global__ void ln_kernel(const float* __restrict__ in, const float* __restrict__ g,
                          float* __restrict__ outf, __half* __restrict__ outh,
                          const float* __restrict__ pos_h, const float* __restrict__ pos_w,
                          const int* __restrict__ ppos, int nrows)
{
    const int r0 = blockIdx.x * 4;
    const int tid = threadIdx.x;
    const int w = tid >> 5;

    float v[4][3];
    float s[4], q[4];
#pragma unroll
    for (int j = 0; j < 4; j++) { s[j] = 0.f; q[j] = 0.f; }
#pragma unroll
    for (int j = 0; j < 4; j++) {
        int row = r0 + j;
        if (row < nrows) {
            const float* xr = in + (size_t)row * 768;
#pragma unroll
            for (int i = 0; i < 3; i++) {
                float t = xr[tid + i*256];
                v[j][i] = t; s[j] += t; q[j] += t*t;
            }
        }
    }
#pragma unroll
    for (int o = 16; o; o >>= 1) {
#pragma unroll
        for (int j = 0; j < 4; j++) {
            s[j] += __shfl_xor_sync(0xffffffffu, s[j], o);
            q[j] += __shfl_xor_sync(0xffffffffu, q[j], o);
        }
    }
    __shared__ float shs[8][4], shq[8][4], st[4][2];
    if ((tid & 31) == 0) {
#pragma unroll
        for (int j = 0; j < 4; j++) { shs[w][j] = s[j]; shq[w][j] = q[j]; }
    }
    __syncthreads();
    if (tid < 4) {
        float S = 0.f, Q = 0.f;
#pragma unroll
        for (int i = 0; i < 8; i++) { S += shs[i][tid]; Q += shq[i][tid]; }
        float mu = S * (1.f/768.f);
        st[tid][0] = mu;
        st[tid][1] = rsqrtf(Q * (1.f/768.f) - mu*mu + 1e-5f);
    }
    __syncthreads();

#pragma unroll
    for (int j = 0; j < 4; j++) {
        int row = r0 + j;
        if (row >= nrows) continue;
        float mu = st[j][0], rs = st[j][1];
        int p0 = 0, p1 = 0;
        if (ppos) { p0 = ppos[row*2]; p1 = ppos[row*2 + 1]; }
#pragma unroll
        for (int i = 0; i < 3; i++) {
            int c = tid + i*256;
            float y = (v[j][i] - mu) * rs * g[c];
            if (ppos) y += pos_h[p0*768 + c] + pos_w[p1*768 + c];
            size_t idx = (size_t)row*768 + c;
            if (outf) outf[idx] = y;
            if (outh) outh[idx] = __float2half(y);
        }
    }
}

// ---------------------------------------------------------------------------
// Fused QKV postprocess: 2 tokens per block.
// ---------------------------------------------------------------------------
__global__ void rmsT_all(const float* __restrict__ qkv,
                         const float* __restrict__ qg, const float* __restrict__ kg,
                         __nv_bfloat16* __restrict__ qh, __nv_bfloat16* __restrict__ ql,
                         __nv_bfloat16* __restrict__ kh, __nv_bfloat16* __restrict__ kl,
                         __half* __restrict__ vt)
{
    int t0 = blockIdx.x * 2;
    int b = t0 >> 10, n0 = t0 & 1023;
    int w = threadIdx.x >> 5, lane = threadIdx.x & 31;
    const float* base0 = qkv + (size_t)t0 * 2304 + w * 64;
    const float* base1 = base0 + 2304;
    __nv_bfloat16 hh, ll;

    {
        float a0 = base0[lane], a1 = base0[lane + 32];
        float b0 = base1[lane], b1 = base1[lane + 32];
        float s0 = a0*a0 + a1*a1, s1 = b0*b0 + b1*b1;
#pragma unroll
        for (int o = 16; o; o >>= 1) {
            s0 += __shfl_xor_sync(0xffffffffu, s0, o);
            s1 += __shfl_xor_sync(0xffffffffu, s1, o);
        }
        float i0 = 8.0f / fmaxf(sqrtf(s0), 1e-12f);
        float i1 = 8.0f / fmaxf(sqrtf(s1), 1e-12f);
        float g0 = qg[w*64 + lane], g1 = qg[w*64 + lane + 32];
        size_t d0 = ((size_t)(b*12 + w) * 1024 + n0) * 64;
        split2(a0 * i0 * g0, hh, ll); qh[d0 + lane] = hh;      ql[d0 + lane] = ll;
        split2(a1 * i0 * g1, hh, ll); qh[d0 + lane + 32] = hh; ql[d0 + lane + 32] = ll;
        split2(b0 * i1 * g0, hh, ll); qh[d0 + 64 + lane] = hh;      ql[d0 + 64 + lane] = ll;
        split2(b1 * i1 * g1, hh, ll); qh[d0 + 64 + lane + 32] = hh; ql[d0 + 64 + lane + 32] = ll;
    }
    {
        float a0 = base0[768 + lane], a1 = base0[768 + lane + 32];
        float b0 = base1[768 + lane], b1 = base1[768 + lane + 32];
        float s0 = a0*a0 + a1*a1, s1 = b0*b0 + b1*b1;
#pragma unroll
        for (int o = 16; o; o >>= 1) {
            s0 += __shfl_xor_sync(0xffffffffu, s0, o);
            s1 += __shfl_xor_sync(0xffffffffu, s1, o);
        }
        float i0 = 8.0f / fmaxf(sqrtf(s0), 1e-12f);
        float i1 = 8.0f / fmaxf(sqrtf(s1), 1e-12f);
        float g0 = kg[w*64 + lane], g1 = kg[w*64 + lane + 32];
        size_t d0 = ((size_t)(b*12 + w) * 1024 + n0) * 64;
        split2(a0 * i0 * g0, hh, ll); kh[d0 + lane] = hh;      kl[d0 + lane] = ll;
        split2(a1 * i0 * g1, hh, ll); kh[d0 + lane + 32] = hh; kl[d0 + lane + 32] = ll;
        split2(b0 * i1 * g0, hh, ll); kh[d0 + 64 + lane] = hh;      kl[d0 + 64 + lane] = ll;
        split2(b1 * i1 * g1, hh, ll); kh[d0 + 64 + lane + 32] = hh; kl[d0 + 64 + lane + 32] = ll;
    }
    {
        float a0 = base0[1536 + lane], a1 = base0[1536 + lane + 32];
        float b0 = base1[1536 + lane], b1 = base1[1536 + lane + 32];
        size_t vb = ((size_t)(b*12 + w) * 64) * 1024 + n0;
        *(__half2*)(vt + vb + (size_t)lane * 1024)        = __floats2half2_rn(a0, b0);
        *(__half2*)(vt + vb + (size_t)(lane + 32) * 1024) = __floats2half2_rn(a1, b1);
    }
}

// Pool-path: one launch does k-rms + v copy (fp32 outputs).
__global__ void rmsT_pool(const float* __restrict__ kv,
                          const float* __restrict__ kg,
                          float* __restrict__ kT, float* __restrict__ vT)
{
    int token = blockIdx.x;
    int b = token >> 10, n = token & 1023;
    int w = threadIdx.x >> 5, lane = threadIdx.x & 31;
    const float* base = kv + (size_t)token * 1536 + w * 64;
    {
        float v0 = base[lane], v1 = base[lane + 32];
        float ss = v0*v0 + v1*v1;
#pragma unroll
        for (int o = 16; o; o >>= 1) ss += __shfl_xor_sync(0xffffffffu, ss, o);
        float inv = 8.0f / fmaxf(sqrtf(ss), 1e-12f);
        float* dst = kT + ((size_t)(b*12 + w) * 1024 + n) * 64;
        dst[lane]      = v0 * inv * kg[w*64 + lane];
        dst[lane + 32] = v1 * inv * kg[w*64 + lane + 32];
    }
    {
        float v0 = base[768 + lane], v1 = base[768 + lane + 32];
        float* dst = vT + ((size_t)(b*12 + w) * 1024 + n) * 64;
        dst[lane] = v0; dst[lane + 32] = v1;
    }
}

// ---------------------------------------------------------------------------
// Attention pooling (192 blocks), fp32 path.
// ---------------------------------------------------------------------------
__global__ void pool_attn_kernel(const float* __restrict__ pqn, const float* __restrict__ kT,
                                 const float* __restrict__ vT, const int* __restrict__ image_ids,
                                 const int* __restrict__ lengths, float* __restrict__ out)
{
    int idx = blockIdx.x;
    int h = idx % 12, img = (idx / 12) % 4, b = idx / 48;
    int tid = threadIdx.x;
    __shared__ float q[64];
    __shared__ float p[1024];
    __shared__ float sh[8];
    __shared__ float bs[2];
    __shared__ float sred[256];
    if (tid < 64) q[tid] = pqn[h*64 + tid];
    __syncthreads();

    const float* K = kT + (size_t)(b*12 + h) * 1024 * 64;
    int len = lengths[b];
    float loc[4]; float mx = -FLT_MAX;
#pragma unroll
    for (int t = 0; t < 4; t++) {
        int j = tid + t*256;
        const float* kr = K + (size_t)j * 64;
        float dot = 0.f;
#pragma unroll
        for (int d = 0; d < 64; d++) dot += q[d] * kr[d];
        bool ok = (image_ids[b*1024 + j] == img) && (j < len);
        loc[t] = ok ? dot : -FLT_MAX;
        mx = fmaxf(mx, loc[t]);
    }
#pragma unroll
    for (int o = 16; o; o >>= 1) mx = fmaxf(mx, __shfl_xor_sync(0xffffffffu, mx, o));
    int w = tid >> 5;
    if ((tid & 31) == 0) sh[w] = mx;
    __syncthreads();
    if (tid == 0) { float mm = sh[0]; for (int i = 1; i < 8; i++) mm = fmaxf(mm, sh[i]); bs[0] = mm; }
    __syncthreads();
    mx = bs[0];
    float s = 0.f;
#pragma unroll
    for (int t = 0; t < 4; t++) {
        float e = __expf(loc[t] - mx);
        p[tid + t*256] = e;
        s += e;
    }
#pragma unroll
    for (int o = 16; o; o >>= 1) s += __shfl_xor_sync(0xffffffffu, s, o);
    if ((tid & 31) == 0) sh[w] = s;
    __syncthreads();
    if (tid == 0) { float ss = 0.f; for (int i = 0; i < 8; i++) ss += sh[i]; bs[1] = 1.f / ss; }
    __syncthreads();
    float inv = bs[1];

    const float* V = vT + (size_t)(b*12 + h) * 1024 * 64;
    int d = tid & 63, grp = tid >> 6;
    float acc = 0.f;
    for (int j = grp; j < 1024; j += 4) acc += p[j] * V[(size_t)j*64 + d];
    sred[tid] = acc;
    __syncthreads();
    if (grp == 0) {
        float r = (sred[d] + sred[d + 64]) + (sred[d + 128] + sred[d + 192]);
        out[(size_t)(b*4 + img) * 768 + h*64 + d] = r * inv;
    }
}

__global__ void rms_vec_kernel(const float* __restrict__ in, const float* __restrict__ g,
                               float* __restrict__ out)
{
    int w = threadIdx.x >> 5, lane = threadIdx.x & 31;
    float v0 = in[w*64 + lane], v1 = in[w*64 + lane + 32];
    float ss = v0*v0 + v1*v1;
#pragma unroll
    for (int o = 16; o; o >>= 1) ss += __shfl_xor_sync(0xffffffffu, ss, o);
    float inv = 8.0f / fmaxf(sqrtf(ss), 1e-12f);
    out[w*64 + lane]      = v0 * inv * g[w*64 + lane];
    out[w*64 + lane + 32] = v1 * inv * g[w*64 + lane + 32];
}

__global__ void small_gemm_kernel(const float* __restrict__ A, const float* __restrict__ W,
                                  const float* __restrict__ addvec, float* __restrict__ C,
                                  int N, int K)
{
    __shared__ float a[768];
    int row = blockIdx.y;
    for (int i = threadIdx.x; i < K; i += 256) a[i] = A[(size_t)row*K + i];
    __syncthreads();
    int n = blockIdx.x * 256 + threadIdx.x;
    if (n >= N) return;
    float acc = addvec ? addvec[n] : 0.f;
#pragma unroll 4
    for (int k = 0; k < K; k++) acc += a[k] * W[(size_t)k*N + n];
    C[(size_t)row*N + n] = acc;
}

// ---------------------------------------------------------------------------
// Host side
// ---------------------------------------------------------------------------
extern "C" void kernel_launch(void* const* d_in, const int* in_sizes, int n_in,
                              void* d_out, int out_size)
{
    (void)in_sizes; (void)n_in; (void)out_size;
    const float* patches    = (const float*)d_in[0];
    const int*   ppos       = (const int*)  d_in[1];
    const int*   image_ids  = (const int*)  d_in[2];
    const int*   lengths    = (const int*)  d_in[3];
    const float* emb_ln_g   = (const float*)d_in[4];
    const float* W_emb      = (const float*)d_in[5];
    const float* b_emb      = (const float*)d_in[6];
    const float* emb_ln2_g  = (const float*)d_in[7];
    const float* pos_h      = (const float*)d_in[8];
    const float* pos_w      = (const float*)d_in[9];
    const float* ln_attn_g  = (const float*)d_in[10];
    const float* Wq         = (const float*)d_in[11];
    const float* Wkv        = (const float*)d_in[12];
    const float* qn_g       = (const float*)d_in[13];
    const float* kn_g       = (const float*)d_in[14];
    const float* Wo         = (const float*)d_in[15];
    const float* ln_ff_g    = (const float*)d_in[16];
    const float* W1         = (const float*)d_in[17];
    const float* b1         = (const float*)d_in[18];
    const float* W2         = (const float*)d_in[19];
    const float* b2         = (const float*)d_in[20];
    const float* final_ln_g = (const float*)d_in[21];
    const float* pool_q     = (const float*)d_in[22];
    const float* pool_ln_g  = (const float*)d_in[23];
    const float* pWq        = (const float*)d_in[24];
    const float* pWkv       = (const float*)d_in[25];
    const float* p_qn_g     = (const float*)d_in[26];
    const float* p_kn_g     = (const float*)d_in[27];
    const float* pWo        = (const float*)d_in[28];
    const float* head_ln_g  = (const float*)d_in[29];
    const float* W_head     = (const float*)d_in[30];

    float *x, *qkv, *kTf, *vTf, *sm, *pattn, *pool, *pln;
    __half *xn, *tmp, *ao, *w, *vTt;
    __nv_bfloat16 *qTh, *qTl, *kTh, *kTl;
    cudaGetSymbolAddress((void**)&x,    g_x);
    cudaGetSymbolAddress((void**)&qkv,  g_qkv);
    cudaGetSymbolAddress((void**)&kTf,  g_kTf);
    cudaGetSymbolAddress((void**)&vTf,  g_vTf);
    cudaGetSymbolAddress((void**)&sm,   g_sm);
    cudaGetSymbolAddress((void**)&pattn,g_pattn);
    cudaGetSymbolAddress((void**)&pool, g_pool);
    cudaGetSymbolAddress((void**)&pln,  g_pln);
    cudaGetSymbolAddress((void**)&xn,   g_xn);
    cudaGetSymbolAddress((void**)&tmp,  g_tmp);
    cudaGetSymbolAddress((void**)&ao,   g_ao);
    cudaGetSymbolAddress((void**)&qTh,  g_qTh);
    cudaGetSymbolAddress((void**)&qTl,  g_qTl);
    cudaGetSymbolAddress((void**)&kTh,  g_kTh);
    cudaGetSymbolAddress((void**)&kTl,  g_kTl);
    cudaGetSymbolAddress((void**)&vTt,  g_vTt);
    cudaGetSymbolAddress((void**)&w,    g_w);

    constexpr int SMEM128 = 65536;
    constexpr int SMEM64  = 49152;
    cudaFuncSetAttribute(mma_gemm<128>, cudaFuncAttributeMaxDynamicSharedMemorySize, SMEM128);
    cudaFuncSetAttribute(mma_gemm<64>,  cudaFuncAttributeMaxDynamicSharedMemorySize, SMEM64);
    cudaFuncSetAttribute(flash_attn,    cudaFuncAttributeMaxDynamicSharedMemorySize, FA_SMEM);

    // ---- Fork a side stream for the weight-conversion + pool-q prologue ----
    cudaStream_t s2;
    cudaStreamCreate(&s2);
    cudaEvent_t eFork, eEmb, eAll;
    cudaEventCreateWithFlags(&eFork, cudaEventDisableTiming);
    cudaEventCreateWithFlags(&eEmb,  cudaEventDisableTiming);
    cudaEventCreateWithFlags(&eAll,  cudaEventDisableTiming);

    cudaEventRecord(eFork, 0);
    cudaStreamWaitEvent(s2, eFork, 0);

    dim3 wb(32, 8);
    // s2: W_emb first (needed earliest), then the rest + pool-q chain
    wconv_kernel<<<dim3(DIM/32,  DIM/32,  1), wb, 0, s2>>>(W_emb, w + WOFF_EMB, DIM, DIM, 0, 0);
    cudaEventRecord(eEmb, s2);
    wconv_kernel<<<dim3(DIM/32,  DIM/32,  4), wb, 0, s2>>>(Wq,  w + WOFF_Q(0),  DIM,  DIM,   (long)DIM*DIM,   (long)WPERL);
    wconv_kernel<<<dim3(2*DIM/32,DIM/32,  4), wb, 0, s2>>>(Wkv, w + WOFF_KV(0), DIM,  2*DIM, (long)DIM*2*DIM, (long)WPERL);
    wconv_kernel<<<dim3(DIM/32,  DIM/32,  4), wb, 0, s2>>>(Wo,  w + WOFF_O(0),  DIM,  DIM,   (long)DIM*DIM,   (long)WPERL);
    wconv_kernel<<<dim3(MLPD/32, DIM/32,  4), wb, 0, s2>>>(W1,  w + WOFF_W1(0), DIM,  MLPD,  (long)DIM*MLPD,  (long)WPERL);
    wconv_kernel<<<dim3(DIM/32,  MLPD/32, 4), wb, 0, s2>>>(W2,  w + WOFF_W2(0), MLPD, DIM,   (long)MLPD*DIM,  (long)WPERL);
    wconv_kernel<<<dim3(2*DIM/32,DIM/32,  1), wb, 0, s2>>>(pWkv, w + WOFF_PKV, DIM, 2*DIM, 0, 0);
    // pool-q prologue (depends only on inputs)
    ln_kernel<<<1, 256, 0, s2>>>(pool_q, pool_ln_g, sm, nullptr, nullptr, nullptr, nullptr, 1);
    small_gemm_kernel<<<dim3(3, 1), 256, 0, s2>>>(sm, pWq, nullptr, sm + 768, DIM, DIM);
    rms_vec_kernel<<<1, 384, 0, s2>>>(sm + 768, p_qn_g, sm + 1536);
    cudaEventRecord(eAll, s2);

    auto G128 = [&](const __half* a, const __half* bw,
                    const float* bias, const float* res,
                    float* C, __half* Ch, int M, int N, int K, int flags) {
        mma_gemm<128><<<dim3(N/128, M/128), 256, SMEM128>>>(a, bw, bias, res, C, Ch, M, N, K, flags);
    };
    auto G64 = [&](const __half* a, const __half* bw,
                   const float* bias, const float* res,
                   float* C, __half* Ch, int M, int N, int K, int flags) {
        mma_gemm<64><<<dim3(N/128, M/64), 256, SMEM64>>>(a, bw, bias, res, C, Ch, M, N, K, flags);
    };
    auto LN = [&](const float* in, const float* g, float* outf, __half* outh,
                  const float* ph, const float* pw, const int* pp, int nrows) {
        ln_kernel<<<(nrows + 3) / 4, 256>>>(in, g, outf, outh, ph, pw, pp, nrows);
    };

    // ---- Embedding (overlaps with s2 prologue) ----
    LN(patches, emb_ln_g, nullptr, xn, nullptr, nullptr, nullptr, TOKS);
    cudaStreamWaitEvent(0, eEmb, 0);          // W_emb ready
    G64(xn, w + WOFF_EMB, b_emb, nullptr, x, nullptr, TOKS, DIM, DIM, FBIAS);
    LN(x, emb_ln2_g, x, nullptr, pos_h, pos_w, ppos, TOKS);
    cudaStreamWaitEvent(0, eAll, 0);          // all weights + pool-q ready (join)

    // ---- Transformer layers ----
    for (int l = 0; l < 4; l++) {
        LN(x, ln_attn_g + l*DIM, nullptr, xn, nullptr, nullptr, nullptr, TOKS);
        G128(xn, w + WOFF_Q(l), nullptr, nullptr, qkv, nullptr, TOKS, 2304, DIM, 0);
        rmsT_all<<<TOKS/2, 384>>>(qkv, qn_g + l*DIM, kn_g + l*DIM, qTh, qTl, kTh, kTl, vTt);
        flash_attn<<<dim3(8, BH), 256, FA_SMEM>>>(qTh, qTl, kTh, kTl, vTt,
                                                  image_ids, lengths, ao);
        G64(ao, w + WOFF_O(l), nullptr, x, x, nullptr, TOKS, DIM, DIM, FRES);
        LN(x, ln_ff_g + l*DIM, nullptr, xn, nullptr, nullptr, nullptr, TOKS);
        G128(xn, w + WOFF_W1(l), b1 + l*MLPD, nullptr, nullptr, tmp, TOKS, MLPD, DIM, FBIAS|FGELU);
        G64(tmp, w + WOFF_W2(l), b2 + l*DIM, x, x, nullptr, TOKS, DIM, MLPD, FBIAS|FRES);
    }

    // ---- Final LN ----
    LN(x, final_ln_g, nullptr, xn, nullptr, nullptr, nullptr, TOKS);

    // ---- Attention pooling (pool-q already computed on s2, joined above) ----
    G128(xn, w + WOFF_PKV, nullptr, nullptr, qkv, nullptr, TOKS, 1536, DIM, 0);
    rmsT_pool<<<TOKS, 384>>>(qkv, p_kn_g, kTf, vTf);
    pool_attn_kernel<<<NB*IMGS*NHEAD, 256>>>(sm + 1536, kTf, vTf, image_ids, lengths, pattn);
    small_gemm_kernel<<<dim3(3, 16), 256>>>(pattn, pWo, pool_q, pool, DIM, DIM);
    LN(pool, head_ln_g, pln, nullptr, nullptr, nullptr, nullptr, 16);
    small_gemm_kernel<<<dim3(4, 16), 256>>>(pln, W_head, nullptr, (float*)d_out, NCLS, DIM);

    // NOTE: s2/events intentionally not destroyed here — destroying a forked
    // stream while capture is active would invalidate the capture. They are
    // few (one set per kernel_launch invocation) and hold no device memory.
}

// round 17
// speedup vs baseline: 1.2251x; 1.0627x over previous
#include <cuda_runtime.h>
#include <cuda_bf16.h>
#include <cuda_fp16.h>
#include <math.h>
#include <float.h>
#include <stdint.h>

// ---------------------------------------------------------------------------
// Problem constants
// ---------------------------------------------------------------------------
#define NB      4
#define NTOK    1024
#define DIM     768
#define NHEAD   12
#define DHEAD   64
#define MLPD    3072
#define IMGS    4
#define NCLS    1000
#define TOKS    (NB*NTOK)
#define BH      (NB*NHEAD)

#define FBIAS 1
#define FGELU 2
#define FRES  4

#define WOFF_EMB 0ULL
#define WPERL    7077888ULL
#define WOFF_L(l)   (589824ULL + (unsigned long long)(l)*WPERL)
#define WOFF_Q(l)   (WOFF_L(l) + 0ULL)
#define WOFF_KV(l)  (WOFF_L(l) + 589824ULL)
#define WOFF_O(l)   (WOFF_L(l) + 1769472ULL)
#define WOFF_W1(l)  (WOFF_L(l) + 2359296ULL)
#define WOFF_W2(l)  (WOFF_L(l) + 4718592ULL)
#define WOFF_PKV    (589824ULL + 4ULL*WPERL)
#define WTOTAL      30081024ULL

// ---------------------------------------------------------------------------
// Device scratch
// ---------------------------------------------------------------------------
__device__ float g_x   [TOKS*DIM];
__device__ float g_qkv [TOKS*2304];
__device__ __half g_xn  [TOKS*DIM];
__device__ __half g_tmp [TOKS*MLPD];
__device__ __half g_ao  [TOKS*DIM];
__device__ __nv_bfloat16 g_qTh[BH*NTOK*DHEAD], g_qTl[BH*NTOK*DHEAD];
__device__ __nv_bfloat16 g_kTh[BH*NTOK*DHEAD], g_kTl[BH*NTOK*DHEAD];
__device__ __half g_vTt[BH*DHEAD*NTOK];
__device__ float g_kTf[BH*NTOK*DHEAD], g_vTf[BH*NTOK*DHEAD];
__device__ float g_sm  [4096];
__device__ float g_pattn[16*DIM];
__device__ float g_pool [16*DIM];
__device__ float g_pln  [16*DIM];
__device__ __half g_w[WTOTAL];

// ---------------------------------------------------------------------------
// Helpers
// ---------------------------------------------------------------------------
__device__ __forceinline__ uint32_t smem_u32(const void* p) {
    uint32_t a;
    asm("{ .reg .u64 t; cvta.to.shared.u64 t, %1; cvt.u32.u64 %0, t; }" : "=r"(a) : "l"(p));
    return a;
}

#define LDSM4(r, addr) \
    asm volatile("ldmatrix.sync.aligned.m8n8.x4.shared.b16 {%0,%1,%2,%3}, [%4];" \
        : "=r"((r)[0]), "=r"((r)[1]), "=r"((r)[2]), "=r"((r)[3]) : "r"(addr))

#define MMA16816(d, a, b) \
    asm volatile("mma.sync.aligned.m16n8k16.row.col.f32.bf16.bf16.f32 " \
        "{%0,%1,%2,%3}, {%4,%5,%6,%7}, {%8,%9}, {%0,%1,%2,%3};" \
        : "+f"((d)[0]), "+f"((d)[1]), "+f"((d)[2]), "+f"((d)[3]) \
        : "r"((a)[0]), "r"((a)[1]), "r"((a)[2]), "r"((a)[3]), "r"((b)[0]), "r"((b)[1]))

#define MMAH16816(d, a, b) \
    asm volatile("mma.sync.aligned.m16n8k16.row.col.f32.f16.f16.f32 " \
        "{%0,%1,%2,%3}, {%4,%5,%6,%7}, {%8,%9}, {%0,%1,%2,%3};" \
        : "+f"((d)[0]), "+f"((d)[1]), "+f"((d)[2]), "+f"((d)[3]) \
        : "r"((a)[0]), "r"((a)[1]), "r"((a)[2]), "r"((a)[3]), "r"((b)[0]), "r"((b)[1]))

#define CPA16(dst, src) \
    asm volatile("cp.async.cg.shared.global [%0], [%1], 16;" :: "r"(dst), "l"(src))
#define CP_COMMIT() asm volatile("cp.async.commit_group;" ::: "memory")
#define CP_WAIT0()  asm volatile("cp.async.wait_group 0;" ::: "memory")
#define CP_WAIT1()  asm volatile("cp.async.wait_group 1;" ::: "memory")

__device__ __forceinline__ void split2(float v, __nv_bfloat16& h, __nv_bfloat16& l) {
    h = __float2bfloat16(v);
    l = __float2bfloat16(v - __bfloat162float(h));
}
__device__ __forceinline__ uint32_t bfu(__nv_bfloat16 b) { return (uint32_t)__bfloat16_as_ushort(b); }

template<typename T>
__device__ __forceinline__ void cpa_tile(uint32_t smbase, const T* __restrict__ g,
                                         int ldk, int chunks, int tid)
{
    for (int i = tid; i < chunks; i += 256) {
        int r = i >> 3, c = i & 7;
        uint32_t off = r * 128 + c * 16;
        uint32_t sw = off ^ ((off >> 3) & 0x70);
        CPA16(smbase + sw, g + (size_t)r * ldk + c * 8);
    }
}

// ---------------------------------------------------------------------------
// Weight convert+transpose, family-batched: z = layer.
// ---------------------------------------------------------------------------
__global__ void wconv_kernel(const float* __restrict__ W, __half* __restrict__ out,
                             int K, int N, long srcStride, long dstStride)
{
    __shared__ float t[32][33];
    int z = blockIdx.z;
    const float* Wz = W + (size_t)z * srcStride;
    __half* oz = out + (size_t)z * dstStride;
    int n0 = blockIdx.x * 32, k0 = blockIdx.y * 32;
    int tx = threadIdx.x, ty = threadIdx.y;
#pragma unroll
    for (int r = 0; r < 4; r++)
        t[ty + r*8][tx] = Wz[(size_t)(k0 + ty + r*8) * N + n0 + tx];
    __syncthreads();
#pragma unroll
    for (int r = 0; r < 4; r++) {
        int n = n0 + ty + r*8, k = k0 + tx;
        oz[(size_t)n * K + k] = __float2half(t[tx][ty + r*8]);
    }
}

// ---------------------------------------------------------------------------
// Pipelined mma.sync fp16 GEMM, single pass, 2-stage.
// MT=128: 8 warps 2Mx4N, 2 CTAs/SM.  MT=64: 8 warps 1Mx8N, 3 CTAs/SM.
// ---------------------------------------------------------------------------
template<int MT>
__global__ void __launch_bounds__(256, (MT == 64) ? 3 : 2) mma_gemm(
    const __half* __restrict__ A, const __half* __restrict__ B,
    const float* __restrict__ bias, const float* __restrict__ res,
    float* __restrict__ C, __half* __restrict__ Ch,
    int M, int N, int K, int flags)
{
    constexpr int WM   = MT / 64;
    constexpr int NQ   = (MT == 128) ? 2 : 1;
    constexpr int NTL  = 2 * NQ;
    constexpr int NCOL = NQ * 16;
    constexpr int A_SZ = MT * 128;
    constexpr int STG  = A_SZ + 16384;

    extern __shared__ char smem[];
    uint32_t uS = smem_u32(smem);

    const int tid = threadIdx.x;
    const int wid = tid >> 5, lane = tid & 31;
    const int m0 = blockIdx.y * MT, n0 = blockIdx.x * 128;
    const int wm = wid & (WM - 1), wn = wid / WM;

    const __half* Az = A + (size_t)m0 * K;
    const __half* Bz = B + (size_t)n0 * K;

    float acc[4][NTL][4] = {};

    const int a_row = wm * 64 + (lane & 15);
    const int a_cb  = (lane >> 4) * 16;
    const int b_row = wn * NCOL + (lane & 7) + ((lane >> 4) << 3);
    const int b_cb  = ((lane >> 3) & 1) * 16;

    const int KT = K >> 6;
    {
        cpa_tile(uS,         Az, K, MT * 8, tid);
        cpa_tile(uS + A_SZ,  Bz, K, 1024,   tid);
        CP_COMMIT();
    }

    for (int kt = 0; kt < KT; kt++) {
        if (kt + 1 < KT) {
            uint32_t base = uS + ((kt + 1) & 1) * STG;
            cpa_tile(base,        Az + (kt + 1) * 64, K, MT * 8, tid);
            cpa_tile(base + A_SZ, Bz + (kt + 1) * 64, K, 1024,   tid);
            CP_COMMIT();
            CP_WAIT1();
        } else {
            CP_WAIT0();
        }
        __syncthreads();

        uint32_t bA = uS + (kt & 1) * STG;
        uint32_t bB = bA + A_SZ;

#pragma unroll
        for (int ks = 0; ks < 4; ks++) {
            uint32_t ah[4][4], bh[NQ][4];
#pragma unroll
            for (int mt = 0; mt < 4; mt++) {
                int row = a_row + mt * 16;
                uint32_t off = row * 128 + ((a_cb + ks * 32) ^ ((row & 7) << 4));
                LDSM4(ah[mt], bA + off);
            }
#pragma unroll
            for (int q = 0; q < NQ; q++) {
                int row = b_row + q * 16;
                uint32_t off = row * 128 + ((b_cb + ks * 32) ^ ((row & 7) << 4));
                LDSM4(bh[q], bB + off);
            }
#pragma unroll
            for (int mt = 0; mt < 4; mt++)
#pragma unroll
                for (int nt = 0; nt < NTL; nt++)
                    MMAH16816(acc[mt][nt], ah[mt], &bh[nt >> 1][(nt & 1) * 2]);
        }
        __syncthreads();
    }

    const int rbase = m0 + wm * 64;
#pragma unroll
    for (int mt = 0; mt < 4; mt++) {
#pragma unroll
        for (int nt = 0; nt < NTL; nt++) {
            int c = n0 + wn * NCOL + nt * 8 + (lane & 3) * 2;
            float bv0 = 0.f, bv1 = 0.f;
            if (flags & FBIAS) { bv0 = bias[c]; bv1 = bias[c + 1]; }
#pragma unroll
            for (int half = 0; half < 2; half++) {
                int r = rbase + mt * 16 + (lane >> 2) + half * 8;
                float v0 = acc[mt][nt][half * 2 + 0];
                float v1 = acc[mt][nt][half * 2 + 1];
                if (flags & FBIAS) { v0 += bv0; v1 += bv1; }
                if (flags & FGELU) {
                    v0 = 0.5f * v0 * (1.f + erff(v0 * 0.70710678118654752f));
                    v1 = 0.5f * v1 * (1.f + erff(v1 * 0.70710678118654752f));
                }
                long idx = (long)r * N + c;
                if (flags & FRES) { v0 += res[idx]; v1 += res[idx + 1]; }
                if (C) *(float2*)(C + idx) = make_float2(v0, v1);
                if (Ch) {
                    __half2 hv = __floats2half2_rn(v0, v1);
                    *(__half2*)(Ch + idx) = hv;
                }
            }
        }
    }
}

// ---------------------------------------------------------------------------
// Fused flash attention. QK bf16 hi/lo 3-pass; PV single-pass fp16.
// ---------------------------------------------------------------------------
#define FA_SMEM 133120
#define NEGBIG  -1e30f

__global__ void __launch_bounds__(256, 1) flash_attn(
    const __nv_bfloat16* __restrict__ Qh_, const __nv_bfloat16* __restrict__ Ql_,
    const __nv_bfloat16* __restrict__ Kh_, const __nv_bfloat16* __restrict__ Kl_,
    const __half* __restrict__ Vt_,
    const int* __restrict__ image_ids, const int* __restrict__ lengths,
    __half* __restrict__ O_)
{
    extern __shared__ char smem[];
    uint32_t uS = smem_u32(smem);
    const int tid = threadIdx.x, wid = tid >> 5, lane = tid & 31;
    const int z = blockIdx.y, b = z / 12, h = z % 12;
    const int m0 = blockIdx.x * 128;

    int* s_cmin   = (int*)(smem + 131072);
    int* s_cmax   = s_cmin + 8;
    int* s_jlist  = s_cmax + 8;
    int* s_meta   = s_jlist + 8;
    int* s_imgRow = s_meta + 8;
    int* s_imgCol = s_imgRow + 128;

    const int len = lengths[b];

    {
        int4 v = *(const int4*)(image_ids + b*1024 + wid*128 + lane*4);
        int mn = min(min(v.x, v.y), min(v.z, v.w));
        int mx = max(max(v.x, v.y), max(v.z, v.w));
#pragma unroll
        for (int o = 16; o; o >>= 1) {
            mn = min(mn, __shfl_xor_sync(0xffffffffu, mn, o));
            mx = max(mx, __shfl_xor_sync(0xffffffffu, mx, o));
        }
        if (lane == 0) { s_cmin[wid] = mn; s_cmax[wid] = mx; }
    }
    if (tid < 128) s_imgRow[tid] = image_ids[b*1024 + m0 + tid];
    __syncthreads();
    if (tid == 0) {
        int rmin = s_cmin[blockIdx.x], rmax = s_cmax[blockIdx.x];
        int nj = 0;
        for (int jb = 0; jb < 8; jb++)
            if (jb * 128 < len && s_cmax[jb] >= rmin && s_cmin[jb] <= rmax)
                s_jlist[nj++] = jb;
        s_meta[0] = nj;
    }
    __syncthreads();
    const int nj = s_meta[0];

    const size_t qoff = ((size_t)z * 1024 + m0) * 64;
    cpa_tile(uS,         Qh_ + qoff, 64, 1024, tid);
    cpa_tile(uS + 16384, Ql_ + qoff, 64, 1024, tid);

    auto prefetch = [&](int t) {
        int jb = s_jlist[t];
        int st = t & 1;
        uint32_t base = uS + 32768 + st * 49152;
        size_t koff = ((size_t)z * 1024 + jb * 128) * 64;
        cpa_tile(base,         Kh_ + koff, 64, 1024, tid);
        cpa_tile(base + 16384, Kl_ + koff, 64, 1024, tid);
        const __half* vt = Vt_ + (size_t)z * 64 * 1024 + jb * 128;
        for (int i = tid; i < 1024; i += 256) {
            int r = i >> 4, c = i & 15;
            int kc = c >> 3, cc = c & 7;
            uint32_t off = r * 128 + cc * 16;
            uint32_t sw = off ^ ((off >> 3) & 0x70);
            CPA16(base + 32768 + kc * 8192 + sw, vt + (size_t)r * 1024 + c * 8);
        }
        if (tid < 128) s_imgCol[st * 128 + tid] = image_ids[b*1024 + jb*128 + tid];
    };
    prefetch(0);
    CP_COMMIT();

    float O[8][4] = {};
    float mA = -FLT_MAX, mB = -FLT_MAX, lA = 0.f, lB = 0.f;
    uint32_t qh[4][4], ql[4][4];
    bool qloaded = false;

    const int rA = lane >> 2;
    const int imgA = s_imgRow[wid * 16 + rA];
    const int imgB = s_imgRow[wid * 16 + rA + 8];

    const int a_row = wid * 16 + (lane & 15);
    const int a_cb  = (lane >> 4) * 16;
    const int b_row_base = (lane & 7) + ((lane >> 4) << 3);
    const int b_cb  = ((lane >> 3) & 1) * 16;

    for (int t = 0; t < nj; t++) {
        if (t + 1 < nj) { prefetch(t + 1); CP_COMMIT(); CP_WAIT1(); }
        else CP_WAIT0();
        __syncthreads();

        if (!qloaded) {
            qloaded = true;
#pragma unroll
            for (int ks = 0; ks < 4; ks++) {
                uint32_t off = a_row * 128 + ((a_cb + ks * 32) ^ ((a_row & 7) << 4));
                LDSM4(qh[ks], uS + off);
                LDSM4(ql[ks], uS + 16384 + off);
            }
        }

        int st = t & 1;
        uint32_t bK  = uS + 32768 + st * 49152;
        uint32_t bKl = bK + 16384;
        uint32_t bV  = bK + 32768;
        int jb = s_jlist[t];
        int j0 = jb * 128;
        const int* imgC = s_imgCol + st * 128;

        float S[16][4] = {};
#pragma unroll
        for (int ks = 0; ks < 4; ks++) {
#pragma unroll
            for (int nb = 0; nb < 8; nb++) {
                uint32_t bh4[4], bl4[4];
                int row = nb * 16 + b_row_base;
                uint32_t off = row * 128 + ((b_cb + ks * 32) ^ ((row & 7) << 4));
                LDSM4(bh4, bK + off);
                LDSM4(bl4, bKl + off);
                MMA16816(S[2*nb],   qh[ks], bh4);
                MMA16816(S[2*nb+1], qh[ks], bh4 + 2);
                MMA16816(S[2*nb],   qh[ks], bl4);
                MMA16816(S[2*nb+1], qh[ks], bl4 + 2);
                MMA16816(S[2*nb],   ql[ks], bh4);
                MMA16816(S[2*nb+1], ql[ks], bh4 + 2);
            }
        }

#pragma unroll
        for (int nt = 0; nt < 16; nt++) {
            int c0 = nt * 8 + (lane & 3) * 2;
            int i0 = imgC[c0], i1 = imgC[c0 + 1];
            bool v0 = (j0 + c0) < len, v1 = (j0 + c0 + 1) < len;
            if (!(i0 == imgA && v0)) S[nt][0] = NEGBIG;
            if (!(i1 == imgA && v1)) S[nt][1] = NEGBIG;
            if (!(i0 == imgB && v0)) S[nt][2] = NEGBIG;
            if (!(i1 == imgB && v1)) S[nt][3] = NEGBIG;
        }
        float mnA = mA, mnB = mB;
#pragma unroll
        for (int nt = 0; nt < 16; nt++) {
            mnA = fmaxf(mnA, fmaxf(S[nt][0], S[nt][1]));
            mnB = fmaxf(mnB, fmaxf(S[nt][2], S[nt][3]));
        }
#pragma unroll
        for (int o = 1; o <= 2; o <<= 1) {
            mnA = fmaxf(mnA, __shfl_xor_sync(0xffffffffu, mnA, o));
            mnB = fmaxf(mnB, __shfl_xor_sync(0xffffffffu, mnB, o));
        }
        float scA = __expf(mA - mnA), scB = __expf(mB - mnB);
        mA = mnA; mB = mnB;
        lA *= scA; lB *= scB;
#pragma unroll
        for (int nt = 0; nt < 16; nt++) {
            float p0 = (S[nt][0] > -1e29f) ? __expf(S[nt][0] - mnA) : 0.f;
            float p1 = (S[nt][1] > -1e29f) ? __expf(S[nt][1] - mnA) : 0.f;
            float p2 = (S[nt][2] > -1e29f) ? __expf(S[nt][2] - mnB) : 0.f;
            float p3 = (S[nt][3] > -1e29f) ? __expf(S[nt][3] - mnB) : 0.f;
            lA += p0 + p1; lB += p2 + p3;
            S[nt][0] = p0; S[nt][1] = p1; S[nt][2] = p2; S[nt][3] = p3;
        }
#pragma unroll
        for (int nt = 0; nt < 8; nt++) {
            O[nt][0] *= scA; O[nt][1] *= scA; O[nt][2] *= scB; O[nt][3] *= scB;
        }

#pragma unroll
        for (int kt = 0; kt < 8; kt++) {
            uint32_t ah4[4];
            {
                __half2 p0 = __floats2half2_rn(S[2*kt][0],   S[2*kt][1]);
                __half2 p1 = __floats2half2_rn(S[2*kt][2],   S[2*kt][3]);
                __half2 p2 = __floats2half2_rn(S[2*kt+1][0], S[2*kt+1][1]);
                __half2 p3 = __floats2half2_rn(S[2*kt+1][2], S[2*kt+1][3]);
                ah4[0] = *(uint32_t*)&p0; ah4[1] = *(uint32_t*)&p1;
                ah4[2] = *(uint32_t*)&p2; ah4[3] = *(uint32_t*)&p3;
            }
            uint32_t tb = bV + (kt >> 2) * 8192;
#pragma unroll
            for (int nb = 0; nb < 4; nb++) {
                uint32_t vh4[4];
                int row = nb * 16 + b_row_base;
                uint32_t off = row * 128 + ((b_cb + (kt & 3) * 32) ^ ((row & 7) << 4));
                LDSM4(vh4, tb + off);
                MMAH16816(O[2*nb],   ah4, vh4);
                MMAH16816(O[2*nb+1], ah4, vh4 + 2);
            }
        }
        __syncthreads();
    }

#pragma unroll
    for (int o = 1; o <= 2; o <<= 1) {
        lA += __shfl_xor_sync(0xffffffffu, lA, o);
        lB += __shfl_xor_sync(0xffffffffu, lB, o);
    }
    float iA = lA > 0.f ? 1.f / lA : 0.f;
    float iB = lB > 0.f ? 1.f / lB : 0.f;
    size_t rowA = (size_t)(b * 1024 + m0 + wid * 16 + rA);
#pragma unroll
    for (int nt = 0; nt < 8; nt++) {
        int c = nt * 8 + (lane & 3) * 2;
        size_t idx = rowA * 768 + h * 64 + c;
        *(__half2*)(O_ + idx) = __floats2half2_rn(O[nt][0] * iA, O[nt][1] * iA);
        idx = (rowA + 8) * 768 + h * 64 + c;
        *(__half2*)(O_ + idx) = __floats2half2_rn(O[nt][2] * iB, O[nt][3] * iB);
    }
}

// ---------------------------------------------------------------------------
// LayerNorm over width 768, 4 rows per block.
// ---------------------------------------------------------------------------
__global__ void ln_kernel(const float* __restrict__ in, const float* __restrict__ g,
                          float* __restrict__ outf, __half* __restrict__ outh,
                          const float* __restrict__ pos_h, const float* __restrict__ pos_w,
                          const int* __restrict__ ppos, int nrows)
{
    const int r0 = blockIdx.x * 4;
    const int tid = threadIdx.x;
    const int w = tid >> 5;

    float v[4][3];
    float s[4], q[4];
#pragma unroll
    for (int j = 0; j < 4; j++) { s[j] = 0.f; q[j] = 0.f; }
#pragma unroll
    for (int j = 0; j < 4; j++) {
        int row = r0 + j;
        if (row < nrows) {
            const float* xr = in + (size_t)row * 768;
#pragma unroll
            for (int i = 0; i < 3; i++) {
                float t = xr[tid + i*256];
                v[j][i] = t; s[j] += t; q[j] += t*t;
            }
        }
    }
#pragma unroll
    for (int o = 16; o; o >>= 1) {
#pragma unroll
        for (int j = 0; j < 4; j++) {
            s[j] += __shfl_xor_sync(0xffffffffu, s[j], o);
            q[j] += __shfl_xor_sync(0xffffffffu, q[j], o);
        }
    }
    __shared__ float shs[8][4], shq[8][4], st[4][2];
    if ((tid & 31) == 0) {
#pragma unroll
        for (int j = 0; j < 4; j++) { shs[w][j] = s[j]; shq[w][j] = q[j]; }
    }
    __syncthreads();
    if (tid < 4) {
        float S = 0.f, Q = 0.f;
#pragma unroll
        for (int i = 0; i < 8; i++) { S += shs[i][tid]; Q += shq[i][tid]; }
        float mu = S * (1.f/768.f);
        st[tid][0] = mu;
        st[tid][1] = rsqrtf(Q * (1.f/768.f) - mu*mu + 1e-5f);
    }
    __syncthreads();

#pragma unroll
    for (int j = 0; j < 4; j++) {
        int row = r0 + j;
        if (row >= nrows) continue;
        float mu = st[j][0], rs = st[j][1];
        int p0 = 0, p1 = 0;
        if (ppos) { p0 = ppos[row*2]; p1 = ppos[row*2 + 1]; }
#pragma unroll
        for (int i = 0; i < 3; i++) {
            int c = tid + i*256;
            float y = (v[j][i] - mu) * rs * g[c];
            if (ppos) y += pos_h[p0*768 + c] + pos_w[p1*768 + c];
            size_t idx = (size_t)row*768 + c;
            if (outf) outf[idx] = y;
            if (outh) outh[idx] = __float2half(y);
        }
    }
}

// ---------------------------------------------------------------------------
// Fused QKV postprocess: 2 tokens per block.
// ---------------------------------------------------------------------------
__global__ void rmsT_all(const float* __restrict__ qkv,
                         const float* __restrict__ qg, const float* __restrict__ kg,
                         __nv_bfloat16* __restrict__ qh, __nv_bfloat16* __restrict__ ql,
                         __nv_bfloat16* __restrict__ kh, __nv_bfloat16* __restrict__ kl,
                         __half* __restrict__ vt)
{
    int t0 = blockIdx.x * 2;
    int b = t0 >> 10, n0 = t0 & 1023;
    int w = threadIdx.x >> 5, lane = threadIdx.x & 31;
    const float* base0 = qkv + (size_t)t0 * 2304 + w * 64;
    const float* base1 = base0 + 2304;
    __nv_bfloat16 hh, ll;

    {
        float a0 = base0[lane], a1 = base0[lane + 32];
        float b0 = base1[lane], b1 = base1[lane + 32];
        float s0 = a0*a0 + a1*a1, s1 = b0*b0 + b1*b1;
#pragma unroll
        for (int o = 16; o; o >>= 1) {
            s0 += __shfl_xor_sync(0xffffffffu, s0, o);
            s1 += __shfl_xor_sync(0xffffffffu, s1, o);
        }
        float i0 = 8.0f / fmaxf(sqrtf(s0), 1e-12f);
        float i1 = 8.0f / fmaxf(sqrtf(s1), 1e-12f);
        float g0 = qg[w*64 + lane], g1 = qg[w*64 + lane + 32];
        size_t d0 = ((size_t)(b*12 + w) * 1024 + n0) * 64;
        split2(a0 * i0 * g0, hh, ll); qh[d0 + lane] = hh;      ql[d0 + lane] = ll;
        split2(a1 * i0 * g1, hh, ll); qh[d0 + lane + 32] = hh; ql[d0 + lane + 32] = ll;
        split2(b0 * i1 * g0, hh, ll); qh[d0 + 64 + lane] = hh;      ql[d0 + 64 + lane] = ll;
        split2(b1 * i1 * g1, hh, ll); qh[d0 + 64 + lane + 32] = hh; ql[d0 + 64 + lane + 32] = ll;
    }
    {
        float a0 = base0[768 + lane], a1 = base0[768 + lane + 32];
        float b0 = base1[768 + lane], b1 = base1[768 + lane + 32];
        float s0 = a0*a0 + a1*a1, s1 = b0*b0 + b1*b1;
#pragma unroll
        for (int o = 16; o; o >>= 1) {
            s0 += __shfl_xor_sync(0xffffffffu, s0, o);
            s1 += __shfl_xor_sync(0xffffffffu, s1, o);
        }
        float i0 = 8.0f / fmaxf(sqrtf(s0), 1e-12f);
        float i1 = 8.0f / fmaxf(sqrtf(s1), 1e-12f);
        float g0 = kg[w*64 + lane], g1 = kg[w*64 + lane + 32];
        size_t d0 = ((size_t)(b*12 + w) * 1024 + n0) * 64;
        split2(a0 * i0 * g0, hh, ll); kh[d0 + lane] = hh;      kl[d0 + lane] = ll;
        split2(a1 * i0 * g1, hh, ll); kh[d0 + lane + 32] = hh; kl[d0 + lane + 32] = ll;
        split2(b0 * i1 * g0, hh, ll); kh[d0 + 64 + lane] = hh;      kl[d0 + 64 + lane] = ll;
        split2(b1 * i1 * g1, hh, ll); kh[d0 + 64 + lane + 32] = hh; kl[d0 + 64 + lane + 32] = ll;
    }
    {
        float a0 = base0[1536 + lane], a1 = base0[1536 + lane + 32];
        float b0 = base1[1536 + lane], b1 = base1[1536 + lane + 32];
        size_t vb = ((size_t)(b*12 + w) * 64) * 1024 + n0;
        *(__half2*)(vt + vb + (size_t)lane * 1024)        = __floats2half2_rn(a0, b0);
        *(__half2*)(vt + vb + (size_t)(lane + 32) * 1024) = __floats2half2_rn(a1, b1);
    }
}

// Pool-path: one launch does k-rms + v copy (fp32 outputs).
__global__ void rmsT_pool(const float* __restrict__ kv,
                          const float* __restrict__ kg,
                          float* __restrict__ kT, float* __restrict__ vT)
{
    int token = blockIdx.x;
    int b = token >> 10, n = token & 1023;
    int w = threadIdx.x >> 5, lane = threadIdx.x & 31;
    const float* base = kv + (size_t)token * 1536 + w * 64;
    {
        float v0 = base[lane], v1 = base[lane + 32];
        float ss = v0*v0 + v1*v1;
#pragma unroll
        for (int o = 16; o; o >>= 1) ss += __shfl_xor_sync(0xffffffffu, ss, o);
        float inv = 8.0f / fmaxf(sqrtf(ss), 1e-12f);
        float* dst = kT + ((size_t)(b*12 + w) * 1024 + n) * 64;
        dst[lane]      = v0 * inv * kg[w*64 + lane];
        dst[lane + 32] = v1 * inv * kg[w*64 + lane + 32];
    }
    {
        float v0 = base[768 + lane], v1 = base[768 + lane + 32];
        float* dst = vT + ((size_t)(b*12 + w) * 1024 + n) * 64;
        dst[lane] = v0; dst[lane + 32] = v1;
    }
}

// ---------------------------------------------------------------------------
// Attention pooling (192 blocks), fp32 path.
// ---------------------------------------------------------------------------
__global__ void pool_attn_kernel(const float* __restrict__ pqn, const float* __restrict__ kT,
                                 const float* __restrict__ vT, const int* __restrict__ image_ids,
                                 const int* __restrict__ lengths, float* __restrict__ out)
{
    int idx = blockIdx.x;
    int h = idx % 12, img = (idx / 12) % 4, b = idx / 48;
    int tid = threadIdx.x;
    __shared__ float q[64];
    __shared__ float p[1024];
    __shared__ float sh[8];
    __shared__ float bs[2];
    __shared__ float sred[256];
    if (tid < 64) q[tid] = pqn[h*64 + tid];
    __syncthreads();

    const float* K = kT + (size_t)(b*12 + h) * 1024 * 64;
    int len = lengths[b];
    float loc[4]; float mx = -FLT_MAX;
#pragma unroll
    for (int t = 0; t < 4; t++) {
        int j = tid + t*256;
        const float* kr = K + (size_t)j * 64;
        float dot = 0.f;
#pragma unroll
        for (int d = 0; d < 64; d++) dot += q[d] * kr[d];
        bool ok = (image_ids[b*1024 + j] == img) && (j < len);
        loc[t] = ok ? dot : -FLT_MAX;
        mx = fmaxf(mx, loc[t]);
    }
#pragma unroll
    for (int o = 16; o; o >>= 1) mx = fmaxf(mx, __shfl_xor_sync(0xffffffffu, mx, o));
    int w = tid >> 5;
    if ((tid & 31) == 0) sh[w] = mx;
    __syncthreads();
    if (tid == 0) { float mm = sh[0]; for (int i = 1; i < 8; i++) mm = fmaxf(mm, sh[i]); bs[0] = mm; }
    __syncthreads();
    mx = bs[0];
    float s = 0.f;
#pragma unroll
    for (int t = 0; t < 4; t++) {
        float e = __expf(loc[t] - mx);
        p[tid + t*256] = e;
        s += e;
    }
#pragma unroll
    for (int o = 16; o; o >>= 1) s += __shfl_xor_sync(0xffffffffu, s, o);
    if ((tid & 31) == 0) sh[w] = s;
    __syncthreads();
    if (tid == 0) { float ss = 0.f; for (int i = 0; i < 8; i++) ss += sh[i]; bs[1] = 1.f / ss; }
    __syncthreads();
    float inv = bs[1];

    const float* V = vT + (size_t)(b*12 + h) * 1024 * 64;
    int d = tid & 63, grp = tid >> 6;
    float acc = 0.f;
    for (int j = grp; j < 1024; j += 4) acc += p[j] * V[(size_t)j*64 + d];
    sred[tid] = acc;
    __syncthreads();
    if (grp == 0) {
        float r = (sred[d] + sred[d + 64]) + (sred[d + 128] + sred[d + 192]);
        out[(size_t)(b*4 + img) * 768 + h*64 + d] = r * inv;
    }
}

__global__ void rms_vec_kernel(const float* __restrict__ in, const float* __restrict__ g,
                               float* __restrict__ out)
{
    int w = threadIdx.x >> 5, lane = threadIdx.x & 31;
    float v0 = in[w*64 + lane], v1 = in[w*64 + lane + 32];
    float ss = v0*v0 + v1*v1;
#pragma unroll
    for (int o = 16; o; o >>= 1) ss += __shfl_xor_sync(0xffffffffu, ss, o);
    float inv = 8.0f / fmaxf(sqrtf(ss), 1e-12f);
    out[w*64 + lane]      = v0 * inv * g[w*64 + lane];
    out[w*64 + lane + 32] = v1 * inv * g[w*64 + lane + 32];
}

__global__ void small_gemm_kernel(const float* __restrict__ A, const float* __restrict__ W,
                                  const float* __restrict__ addvec, float* __restrict__ C,
                                  int N, int K)
{
    __shared__ float a[768];
    int row = blockIdx.y;
    for (int i = threadIdx.x; i < K; i += 256) a[i] = A[(size_t)row*K + i];
    __syncthreads();
    int n = blockIdx.x * 256 + threadIdx.x;
    if (n >= N) return;
    float acc = addvec ? addvec[n] : 0.f;
#pragma unroll 4
    for (int k = 0; k < K; k++) acc += a[k] * W[(size_t)k*N + n];
    C[(size_t)row*N + n] = acc;
}

// ---------------------------------------------------------------------------
// Host side
// ---------------------------------------------------------------------------
extern "C" void kernel_launch(void* const* d_in, const int* in_sizes, int n_in,
                              void* d_out, int out_size)
{
    (void)in_sizes; (void)n_in; (void)out_size;
    const float* patches    = (const float*)d_in[0];
    const int*   ppos       = (const int*)  d_in[1];
    const int*   image_ids  = (const int*)  d_in[2];
    const int*   lengths    = (const int*)  d_in[3];
    const float* emb_ln_g   = (const float*)d_in[4];
    const float* W_emb      = (const float*)d_in[5];
    const float* b_emb      = (const float*)d_in[6];
    const float* emb_ln2_g  = (const float*)d_in[7];
    const float* pos_h      = (const float*)d_in[8];
    const float* pos_w      = (const float*)d_in[9];
    const float* ln_attn_g  = (const float*)d_in[10];
    const float* Wq         = (const float*)d_in[11];
    const float* Wkv        = (const float*)d_in[12];
    const float* qn_g       = (const float*)d_in[13];
    const float* kn_g       = (const float*)d_in[14];
    const float* Wo         = (const float*)d_in[15];
    const float* ln_ff_g    = (const float*)d_in[16];
    const float* W1         = (const float*)d_in[17];
    const float* b1         = (const float*)d_in[18];
    const float* W2         = (const float*)d_in[19];
    const float* b2         = (const float*)d_in[20];
    const float* final_ln_g = (const float*)d_in[21];
    const float* pool_q     = (const float*)d_in[22];
    const float* pool_ln_g  = (const float*)d_in[23];
    const float* pWq        = (const float*)d_in[24];
    const float* pWkv       = (const float*)d_in[25];
    const float* p_qn_g     = (const float*)d_in[26];
    const float* p_kn_g     = (const float*)d_in[27];
    const float* pWo        = (const float*)d_in[28];
    const float* head_ln_g  = (const float*)d_in[29];
    const float* W_head     = (const float*)d_in[30];

    float *x, *qkv, *kTf, *vTf, *sm, *pattn, *pool, *pln;
    __half *xn, *tmp, *ao, *w, *vTt;
    __nv_bfloat16 *qTh, *qTl, *kTh, *kTl;
    cudaGetSymbolAddress((void**)&x,    g_x);
    cudaGetSymbolAddress((void**)&qkv,  g_qkv);
    cudaGetSymbolAddress((void**)&kTf,  g_kTf);
    cudaGetSymbolAddress((void**)&vTf,  g_vTf);
    cudaGetSymbolAddress((void**)&sm,   g_sm);
    cudaGetSymbolAddress((void**)&pattn,g_pattn);
    cudaGetSymbolAddress((void**)&pool, g_pool);
    cudaGetSymbolAddress((void**)&pln,  g_pln);
    cudaGetSymbolAddress((void**)&xn,   g_xn);
    cudaGetSymbolAddress((void**)&tmp,  g_tmp);
    cudaGetSymbolAddress((void**)&ao,   g_ao);
    cudaGetSymbolAddress((void**)&qTh,  g_qTh);
    cudaGetSymbolAddress((void**)&qTl,  g_qTl);
    cudaGetSymbolAddress((void**)&kTh,  g_kTh);
    cudaGetSymbolAddress((void**)&kTl,  g_kTl);
    cudaGetSymbolAddress((void**)&vTt,  g_vTt);
    cudaGetSymbolAddress((void**)&w,    g_w);

    constexpr int SMEM128 = 65536;
    constexpr int SMEM64  = 49152;
    cudaFuncSetAttribute(mma_gemm<128>, cudaFuncAttributeMaxDynamicSharedMemorySize, SMEM128);
    cudaFuncSetAttribute(mma_gemm<64>,  cudaFuncAttributeMaxDynamicSharedMemorySize, SMEM64);
    cudaFuncSetAttribute(flash_attn,    cudaFuncAttributeMaxDynamicSharedMemorySize, FA_SMEM);

    // ---- Fork a side stream for the weight-conversion + pool-q prologue ----
    cudaStream_t s2;
    cudaStreamCreate(&s2);
    cudaEvent_t eFork, eEmb, eL0, eAll;
    cudaEventCreateWithFlags(&eFork, cudaEventDisableTiming);
    cudaEventCreateWithFlags(&eEmb,  cudaEventDisableTiming);
    cudaEventCreateWithFlags(&eL0,   cudaEventDisableTiming);
    cudaEventCreateWithFlags(&eAll,  cudaEventDisableTiming);

    cudaEventRecord(eFork, 0);
    cudaStreamWaitEvent(s2, eFork, 0);

    dim3 wb(32, 8);
    // s2 phase 1: W_emb (needed first)
    wconv_kernel<<<dim3(DIM/32,  DIM/32,  1), wb, 0, s2>>>(W_emb, w + WOFF_EMB, DIM, DIM, 0, 0);
    cudaEventRecord(eEmb, s2);
    // s2 phase 2: layer-0 weight families only
    wconv_kernel<<<dim3(DIM/32,  DIM/32,  1), wb, 0, s2>>>(Wq,  w + WOFF_Q(0),  DIM,  DIM,   0, 0);
    wconv_kernel<<<dim3(2*DIM/32,DIM/32,  1), wb, 0, s2>>>(Wkv, w + WOFF_KV(0), DIM,  2*DIM, 0, 0);
    wconv_kernel<<<dim3(DIM/32,  DIM/32,  1), wb, 0, s2>>>(Wo,  w + WOFF_O(0),  DIM,  DIM,   0, 0);
    wconv_kernel<<<dim3(MLPD/32, DIM/32,  1), wb, 0, s2>>>(W1,  w + WOFF_W1(0), DIM,  MLPD,  0, 0);
    wconv_kernel<<<dim3(DIM/32,  MLPD/32, 1), wb, 0, s2>>>(W2,  w + WOFF_W2(0), MLPD, DIM,   0, 0);
    cudaEventRecord(eL0, s2);
    // s2 phase 3: layers 1..3 families (overlap with layer-0 compute)
    wconv_kernel<<<dim3(DIM/32,  DIM/32,  3), wb, 0, s2>>>(Wq  + (size_t)DIM*DIM,    w + WOFF_Q(1),  DIM,  DIM,   (long)DIM*DIM,   (long)WPERL);
    wconv_kernel<<<dim3(2*DIM/32,DIM/32,  3), wb, 0, s2>>>(Wkv + (size_t)DIM*2*DIM,  w + WOFF_KV(1), DIM,  2*DIM, (long)DIM*2*DIM, (long)WPERL);
    wconv_kernel<<<dim3(DIM/32,  DIM/32,  3), wb, 0, s2>>>(Wo  + (size_t)DIM*DIM,    w + WOFF_O(1),  DIM,  DIM,   (long)DIM*DIM,   (long)WPERL);
    wconv_kernel<<<dim3(MLPD/32, DIM/32,  3), wb, 0, s2>>>(W1  + (size_t)DIM*MLPD,   w + WOFF_W1(1), DIM,  MLPD,  (long)DIM*MLPD,  (long)WPERL);
    wconv_kernel<<<dim3(DIM/32,  MLPD/32, 3), wb, 0, s2>>>(W2  + (size_t)MLPD*DIM,   w + WOFF_W2(1), MLPD, DIM,   (long)MLPD*DIM,  (long)WPERL);
    wconv_kernel<<<dim3(2*DIM/32,DIM/32,  1), wb, 0, s2>>>(pWkv, w + WOFF_PKV, DIM, 2*DIM, 0, 0);
    // pool-q prologue (depends only on inputs)
    ln_kernel<<<1, 256, 0, s2>>>(pool_q, pool_ln_g, sm, nullptr, nullptr, nullptr, nullptr, 1);
    small_gemm_kernel<<<dim3(3, 1), 256, 0, s2>>>(sm, pWq, nullptr, sm + 768, DIM, DIM);
    rms_vec_kernel<<<1, 384, 0, s2>>>(sm + 768, p_qn_g, sm + 1536);
    cudaEventRecord(eAll, s2);

    auto G128 = [&](const __half* a, const __half* bw,
                    const float* bias, const float* res,
                    float* C, __half* Ch, int M, int N, int K, int flags) {
        mma_gemm<128><<<dim3(N/128, M/128), 256, SMEM128>>>(a, bw, bias, res, C, Ch, M, N, K, flags);
    };
    auto G64 = [&](const __half* a, const __half* bw,
                   const float* bias, const float* res,
                   float* C, __half* Ch, int M, int N, int K, int flags) {
        mma_gemm<64><<<dim3(N/128, M/64), 256, SMEM64>>>(a, bw, bias, res, C, Ch, M, N, K, flags);
    };
    auto LN = [&](const float* in, const float* g, float* outf, __half* outh,
                  const float* ph, const float* pw, const int* pp, int nrows) {
        ln_kernel<<<(nrows + 3) / 4, 256>>>(in, g, outf, outh, ph, pw, pp, nrows);
    };

    // ---- Embedding (overlaps with s2) ----
    LN(patches, emb_ln_g, nullptr, xn, nullptr, nullptr, nullptr, TOKS);
    cudaStreamWaitEvent(0, eEmb, 0);          // W_emb ready
    G64(xn, w + WOFF_EMB, b_emb, nullptr, x, nullptr, TOKS, DIM, DIM, FBIAS);
    LN(x, emb_ln2_g, x, nullptr, pos_h, pos_w, ppos, TOKS);
    cudaStreamWaitEvent(0, eL0, 0);           // layer-0 weights ready

    // ---- Transformer layers ----
    for (int l = 0; l < 4; l++) {
        if (l == 1) cudaStreamWaitEvent(0, eAll, 0);   // all remaining weights + pool-q ready
        LN(x, ln_attn_g + l*DIM, nullptr, xn, nullptr, nullptr, nullptr, TOKS);
        G128(xn, w + WOFF_Q(l), nullptr, nullptr, qkv, nullptr, TOKS, 2304, DIM, 0);
        rmsT_all<<<TOKS/2, 384>>>(qkv, qn_g + l*DIM, kn_g + l*DIM, qTh, qTl, kTh, kTl, vTt);
        flash_attn<<<dim3(8, BH), 256, FA_SMEM>>>(qTh, qTl, kTh, kTl, vTt,
                                                  image_ids, lengths, ao);
        G64(ao, w + WOFF_O(l), nullptr, x, x, nullptr, TOKS, DIM, DIM, FRES);
        LN(x, ln_ff_g + l*DIM, nullptr, xn, nullptr, nullptr, nullptr, TOKS);
        G128(xn, w + WOFF_W1(l), b1 + l*MLPD, nullptr, nullptr, tmp, TOKS, MLPD, DIM, FBIAS|FGELU);
        G64(tmp, w + WOFF_W2(l), b2 + l*DIM, x, x, nullptr, TOKS, DIM, MLPD, FBIAS|FRES);
    }

    // ---- Final LN ----
    LN(x, final_ln_g, nullptr, xn, nullptr, nullptr, nullptr, TOKS);

    // ---- Attention pooling (pool-q already computed on s2) ----
    G128(xn, w + WOFF_PKV, nullptr, nullptr, qkv, nullptr, TOKS, 1536, DIM, 0);
    rmsT_pool<<<TOKS, 384>>>(qkv, p_kn_g, kTf, vTf);
    pool_attn_kernel<<<NB*IMGS*NHEAD, 256>>>(sm + 1536, kTf, vTf, image_ids, lengths, pattn);
    small_gemm_kernel<<<dim3(3, 16), 256>>>(pattn, pWo, pool_q, pool, DIM, DIM);
    LN(pool, head_ln_g, pln, nullptr, nullptr, nullptr, nullptr, 16);
    small_gemm_kernel<<<dim3(4, 16), 256>>>(pln, W_head, nullptr, (float*)d_out, NCLS, DIM);

    // NOTE: s2/events intentionally not destroyed (capture-safe; no device memory).
}